// round 10
// baseline (speedup 1.0000x reference)
#include <cuda_runtime.h>
#include <cuda_bf16.h>
#include <math.h>
#include <float.h>
#include <stdint.h>

// Problem dims: B=8, S=32, HN=64, TN=512, HID=EMB=512
// ---------------- scratch (device globals; no allocation) ----------------
__device__ float g_dh  [256 * 1024];            // [.,0:512)=decp  [.,512:1024)=hqd
__device__ float g_hh  [8   * 1024];            // [.,0:512)=histp [.,512:1024)=hqh
__device__ float g_headq[512  * 512];
__device__ float g_attn [8LL*2048*512];
__device__ float g_hk   [16384LL*512];
__device__ float g_hq   [256 * 512];
__device__ __nv_bfloat16 g_tq_hi [8LL*2048*512], g_tq_lo [8LL*2048*512];
__device__ __nv_bfloat16 g_tk_hi [4096LL*512],   g_tk_lo [4096LL*512];
__device__ __nv_bfloat16 g_tkT_hi[4096LL*512],   g_tkT_lo[4096LL*512];
__device__ __nv_bfloat16 g_at_hi [8LL*2048*512], g_at_lo [8LL*2048*512];
__device__ __nv_bfloat16 g_ctx_hi[8LL*2048*512], g_ctx_lo[8LL*2048*512];
__device__ __nv_bfloat16 g_gh_hi [8LL*2048*512], g_gh_lo [8LL*2048*512];
__device__ __nv_bfloat16 g_wT_hi [9LL*512*512],  g_wT_lo [9LL*512*512];
__device__ unsigned int g_mask_byte_mode;

__device__ __forceinline__ uint32_t smem_u32(const void* p) {
    uint32_t a;
    asm("{ .reg .u64 t; cvta.to.shared.u64 t, %1; cvt.u32.u64 %0, t; }" : "=r"(a) : "l"(p));
    return a;
}
__device__ __forceinline__ void cp16(uint32_t dst, const void* src) {
    asm volatile("cp.async.cg.shared.global [%0], [%1], 16;" :: "r"(dst), "l"(src));
}
__device__ __forceinline__ void mma_bf16(float* d, const uint32_t* a, const uint32_t* b) {
    asm volatile("mma.sync.aligned.m16n8k16.row.col.f32.bf16.bf16.f32 "
        "{%0,%1,%2,%3}, {%4,%5,%6,%7}, {%8,%9}, {%0,%1,%2,%3};"
        : "+f"(d[0]), "+f"(d[1]), "+f"(d[2]), "+f"(d[3])
        : "r"(a[0]), "r"(a[1]), "r"(a[2]), "r"(a[3]), "r"(b[0]), "r"(b[1]));
}
__device__ __forceinline__ void ldm_x4(uint32_t& r0, uint32_t& r1, uint32_t& r2, uint32_t& r3,
                                       uint32_t addr) {
    asm volatile("ldmatrix.sync.aligned.m8n8.x4.shared.b16 {%0,%1,%2,%3}, [%4];"
        : "=r"(r0), "=r"(r1), "=r"(r2), "=r"(r3) : "r"(addr));
}
__device__ __forceinline__ float eluf(float x) { return x > 0.f ? x : expm1f(x); }

// smem: NSTAGE buffers; each = A tile (64 rows x 144B) + B tile (128 x 144B)
// row layout: bytes [0,64) = hi 32 bf16, [64,128) = lo 32 bf16, [128,144) pad
#define ROWB   144
#define MT     64
#define ATILEB (MT * ROWB)           // 9216
#define BTILEB (128 * ROWB)          // 18432
#define BUFB   (ATILEB + BTILEB)     // 27648
#define NSTAGE 4
#define SMEM_BYTES (NSTAGE * BUFB)   // 110592 -> 2 CTAs/SM

#define LDM_SETUP \
    const int lrow = lane & 7, lsel = lane >> 3; \
    const int a_dm = (lsel & 1) << 3, a_dk = (lsel >> 1) << 3; \
    const int b_dn = (lsel >> 1) << 3, b_dk = (lsel & 1) << 3;

__device__ __forceinline__ void pipe_wait(int rem) {
    if (rem >= 3)      asm volatile("cp.async.wait_group 3;");
    else if (rem == 2) asm volatile("cp.async.wait_group 2;");
    else if (rem == 1) asm volatile("cp.async.wait_group 1;");
    else               asm volatile("cp.async.wait_group 0;");
}

// ==================================================================
// Main bf16-split GEMM (pre-split bf16 A), 4-stage pipeline, MT=64,
// fragment-hoisted mainloop (16 ldmatrix.x4 per chunk instead of 24)
// ==================================================================
template<int ACT, bool TWO, bool OUTB>
__global__ void __launch_bounds__(256, 2) gemm_mma(
    const __nv_bfloat16* __restrict__ Ahi, const __nv_bfloat16* __restrict__ Alo,
    const __nv_bfloat16* __restrict__ Bhi, const __nv_bfloat16* __restrict__ Blo,
    const __nv_bfloat16* __restrict__ A2hi, const __nv_bfloat16* __restrict__ A2lo,
    const __nv_bfloat16* __restrict__ B2hi, const __nv_bfloat16* __restrict__ B2lo,
    float* __restrict__ Cf, __nv_bfloat16* __restrict__ Chi, __nv_bfloat16* __restrict__ Clo,
    const float* __restrict__ bias,
    int M, int K, long long sA, long long sB, long long sC, int ldc)
{
    constexpr int FM = 2;
    extern __shared__ char sm[];
    const uint32_t smb = smem_u32(sm);
    const int tid = threadIdx.x, wid = tid >> 5, lane = tid & 31;
    const int wm = wid >> 2, wn = wid & 3;
    const int m0 = blockIdx.y * MT, n0 = blockIdx.x * 128, z = blockIdx.z;

    const int kc  = K >> 5;
    const int nch = TWO ? 2 * kc : kc;

    float d[FM][4][4];
    #pragma unroll
    for (int f = 0; f < FM; f++)
        #pragma unroll
        for (int g = 0; g < 4; g++)
            #pragma unroll
            for (int e = 0; e < 4; e++) d[f][g][e] = 0.f;

    auto load_chunk = [&](int c) {
        const bool sec = TWO && (c >= kc);
        const int koff = (sec ? c - kc : c) << 5;
        const int buf = c % NSTAGE;
        const uint32_t smA = smb + buf * BUFB;
        const uint32_t smB = smA + ATILEB;
        {
            const __nv_bfloat16* pH = (sec ? A2hi : Ahi) + (long long)z * sA;
            const __nv_bfloat16* pL = (sec ? A2lo : Alo) + (long long)z * sA;
            const int r = tid >> 2, s = tid & 3;
            const long long go = (long long)(m0 + r) * K + koff + s * 8;
            const uint32_t dst = smA + r * ROWB + s * 16;
            cp16(dst,      pH + go);
            cp16(dst + 64, pL + go);
        }
        {
            const __nv_bfloat16* pH = (sec ? B2hi : Bhi) + (long long)z * sB;
            const __nv_bfloat16* pL = (sec ? B2lo : Blo) + (long long)z * sB;
            #pragma unroll
            for (int i = 0; i < 2; i++) {
                const int idx = tid + 256 * i;
                const int r = idx >> 2, s = idx & 3;
                const long long go = (long long)(n0 + r) * K + koff + s * 8;
                const uint32_t dst = smB + r * ROWB + s * 16;
                cp16(dst,      pH + go);
                cp16(dst + 64, pL + go);
            }
        }
        asm volatile("cp.async.commit_group;");
    };

    #pragma unroll
    for (int p = 0; p < NSTAGE - 1; p++) if (p < nch) load_chunk(p);

    LDM_SETUP

    for (int c = 0; c < nch; ++c) {
        if (c + NSTAGE - 1 < nch) load_chunk(c + NSTAGE - 1);
        pipe_wait(nch - 1 - c);
        __syncthreads();

        const uint32_t a_base = smb + (c % NSTAGE) * BUFB;
        const uint32_t b_base = a_base + ATILEB;

        // hoisted fragments: B at kb=0,16,32,48; A two ka at a time
        uint32_t b0[4][2], b1[4][2], b2[4][2], b3[4][2];
        uint32_t aA[FM][4], aB[FM][4];

        #define LDB(bb, kb) { \
            _Pragma("unroll") \
            for (int gp = 0; gp < 2; gp++) { \
                const uint32_t addr = b_base \
                    + (uint32_t)((wn * 32 + gp * 16 + b_dn + lrow) * ROWB + ((kb) + b_dk) * 2); \
                ldm_x4(bb[2*gp][0], bb[2*gp][1], bb[2*gp+1][0], bb[2*gp+1][1], addr); \
            } }
        #define LDA(aa, ka) { \
            _Pragma("unroll") \
            for (int f = 0; f < FM; f++) { \
                const uint32_t addr = a_base \
                    + (uint32_t)((wm * 32 + f * 16 + a_dm + lrow) * ROWB + ((ka) + a_dk) * 2); \
                ldm_x4(aa[f][0], aa[f][1], aa[f][2], aa[f][3], addr); \
            } }
        #define MMAG(aa, bb) { \
            _Pragma("unroll") \
            for (int f = 0; f < FM; f++) \
                _Pragma("unroll") \
                for (int g = 0; g < 4; g++) \
                    mma_bf16(d[f][g], aa[f], bb[g]); }

        LDB(b0, 0);  LDB(b1, 16);
        LDA(aA, 0);  LDA(aB, 16);
        MMAG(aA, b0);                 // (0,0)   AhBh
        MMAG(aB, b1);                 // (16,16) AhBh
        LDB(b2, 32); LDB(b3, 48);
        MMAG(aA, b2);                 // (0,32)  AhBl
        MMAG(aB, b3);                 // (16,48) AhBl
        LDA(aA, 32); LDA(aB, 48);
        MMAG(aA, b0);                 // (32,0)  AlBh
        MMAG(aB, b1);                 // (48,16) AlBh

        #undef LDB
        #undef LDA
        #undef MMAG
        __syncthreads();
    }

    const int qr = lane >> 2, qc = 2 * (lane & 3);
    #pragma unroll
    for (int f = 0; f < FM; f++) {
        #pragma unroll
        for (int g = 0; g < 4; g++) {
            const int cc = n0 + wn * 32 + g * 8 + qc;
            float bx = 0.f, by = 0.f;
            if (bias) { bx = bias[cc]; by = bias[cc + 1]; }
            #pragma unroll
            for (int h = 0; h < 2; h++) {
                const int row = m0 + wm * 32 + f * 16 + qr + h * 8;
                if (row >= M) continue;
                float v0 = d[f][g][2 * h]     + bx;
                float v1 = d[f][g][2 * h + 1] + by;
                if (ACT == 1) { v0 = eluf(v0); v1 = eluf(v1); }
                else if (ACT == 2) { v0 = tanhf(v0); v1 = tanhf(v1); }
                const long long o = (long long)z * sC + (long long)row * ldc + cc;
                if constexpr (!OUTB) {
                    *reinterpret_cast<float2*>(Cf + o) = make_float2(v0, v1);
                } else {
                    __nv_bfloat162 hb = __floats2bfloat162_rn(v0, v1);
                    float2 hf = __bfloat1622float2(hb);
                    __nv_bfloat162 lb = __floats2bfloat162_rn(v0 - hf.x, v1 - hf.y);
                    *reinterpret_cast<__nv_bfloat162*>(Chi + o) = hb;
                    *reinterpret_cast<__nv_bfloat162*>(Clo + o) = lb;
                }
            }
        }
    }
}

// ==================================================================
// Prologue uber-GEMM (streamed-fragment loop; fp32 A with gather):
// Grid 320 CTAs: [0,32) dh, [32,64) headq, [64,320) tk
// ==================================================================
__global__ void __launch_bounds__(256, 2) gemm_pro(
    const float* __restrict__ dec_out, const float* __restrict__ emb,
    const int* __restrict__ head, const int* __restrict__ tail,
    const __nv_bfloat16* __restrict__ wT_hi, const __nv_bfloat16* __restrict__ wT_lo,
    float* __restrict__ dh, float* __restrict__ headq,
    __nv_bfloat16* __restrict__ tk_hi, __nv_bfloat16* __restrict__ tk_lo,
    const float* __restrict__ b_tk)
{
    constexpr int FM = 2;
    extern __shared__ char sm[];
    const uint32_t smb = smem_u32(sm);
    const int tid = threadIdx.x, wid = tid >> 5, lane = tid & 31;
    const int wm = wid >> 2, wn = wid & 3;

    const int bid = blockIdx.x;
    const float* Af; const int* gidx; long long boff; float* Cf; int ldc;
    int m0, n0; int outb, act; const float* bias;
    if (bid < 32) {
        Af = dec_out; gidx = nullptr; boff = 0;
        Cf = dh; ldc = 1024; outb = 0; act = 0; bias = nullptr;
        n0 = (bid & 7) * 128; m0 = (bid >> 3) * MT;
    } else if (bid < 64) {
        const int t = bid - 32;
        Af = emb; gidx = head; boff = 2LL * 512 * 512;
        Cf = headq; ldc = 512; outb = 0; act = 0; bias = nullptr;
        n0 = (t & 3) * 128; m0 = (t >> 2) * MT;
    } else {
        const int t = bid - 64;
        Af = emb; gidx = tail; boff = 3LL * 512 * 512;
        Cf = nullptr; ldc = 512; outb = 1; act = 1; bias = b_tk;
        n0 = (t & 3) * 128; m0 = (t >> 2) * MT;
    }
    const __nv_bfloat16* Bhi = wT_hi + boff;
    const __nv_bfloat16* Blo = wT_lo + boff;
    const int K = 512, nch = 16;

    float d[FM][4][4];
    #pragma unroll
    for (int f = 0; f < FM; f++)
        #pragma unroll
        for (int g = 0; g < 4; g++)
            #pragma unroll
            for (int e = 0; e < 4; e++) d[f][g][e] = 0.f;

    auto load_chunk = [&](int c) {
        const int koff = c << 5;
        const int buf = c % NSTAGE;
        const uint32_t smA = smb + buf * BUFB;
        const uint32_t smB = smA + ATILEB;
        char* smAp = sm + buf * BUFB;
        #pragma unroll
        for (int i = 0; i < 2; i++) {
            const int idx = tid + 256 * i;
            const int r = idx >> 3, s = idx & 7;
            const int gm = m0 + r;
            const long long row = gidx ? (long long)gidx[gm] : (long long)gm;
            float4 v = *reinterpret_cast<const float4*>(Af + row * K + koff + s * 4);
            __nv_bfloat162 h01 = __floats2bfloat162_rn(v.x, v.y);
            __nv_bfloat162 h23 = __floats2bfloat162_rn(v.z, v.w);
            float2 f01 = __bfloat1622float2(h01), f23 = __bfloat1622float2(h23);
            __nv_bfloat162 l01 = __floats2bfloat162_rn(v.x - f01.x, v.y - f01.y);
            __nv_bfloat162 l23 = __floats2bfloat162_rn(v.z - f23.x, v.w - f23.y);
            uint2 uh, ul;
            uh.x = *(uint32_t*)&h01; uh.y = *(uint32_t*)&h23;
            ul.x = *(uint32_t*)&l01; ul.y = *(uint32_t*)&l23;
            *reinterpret_cast<uint2*>(smAp + r * ROWB + s * 8)      = uh;
            *reinterpret_cast<uint2*>(smAp + r * ROWB + 64 + s * 8) = ul;
        }
        #pragma unroll
        for (int i = 0; i < 2; i++) {
            const int idx = tid + 256 * i;
            const int r = idx >> 2, s = idx & 3;
            const long long go = (long long)(n0 + r) * K + koff + s * 8;
            const uint32_t dst = smB + r * ROWB + s * 16;
            cp16(dst,      Bhi + go);
            cp16(dst + 64, Blo + go);
        }
        asm volatile("cp.async.commit_group;");
    };

    #pragma unroll
    for (int p = 0; p < NSTAGE - 1; p++) load_chunk(p);

    const int stepA[6] = {0, 16, 0, 16, 32, 48};
    const int stepB[6] = {0, 16, 32, 48, 0, 16};
    LDM_SETUP

    for (int c = 0; c < nch; ++c) {
        if (c + NSTAGE - 1 < nch) load_chunk(c + NSTAGE - 1);
        pipe_wait(nch - 1 - c);
        __syncthreads();

        const uint32_t a_base = smb + (c % NSTAGE) * BUFB;
        const uint32_t b_base = a_base + ATILEB;

        #pragma unroll
        for (int st = 0; st < 6; ++st) {
            const int ka = stepA[st], kb = stepB[st];
            uint32_t a[FM][4], b[4][2];
            #pragma unroll
            for (int f = 0; f < FM; f++) {
                const uint32_t addr = a_base
                    + (uint32_t)((wm * 32 + f * 16 + a_dm + lrow) * ROWB + (ka + a_dk) * 2);
                ldm_x4(a[f][0], a[f][1], a[f][2], a[f][3], addr);
            }
            #pragma unroll
            for (int gp = 0; gp < 2; gp++) {
                const uint32_t addr = b_base
                    + (uint32_t)((wn * 32 + gp * 16 + b_dn + lrow) * ROWB + (kb + b_dk) * 2);
                ldm_x4(b[2*gp][0], b[2*gp][1], b[2*gp+1][0], b[2*gp+1][1], addr);
            }
            #pragma unroll
            for (int f = 0; f < FM; f++)
                #pragma unroll
                for (int g = 0; g < 4; g++)
                    mma_bf16(d[f][g], a[f], b[g]);
        }
        __syncthreads();
    }

    const int qr = lane >> 2, qc = 2 * (lane & 3);
    #pragma unroll
    for (int f = 0; f < FM; f++) {
        #pragma unroll
        for (int g = 0; g < 4; g++) {
            const int cc = n0 + wn * 32 + g * 8 + qc;
            float bx = 0.f, by = 0.f;
            if (bias) { bx = bias[cc]; by = bias[cc + 1]; }
            #pragma unroll
            for (int h = 0; h < 2; h++) {
                const int row = m0 + wm * 32 + f * 16 + qr + h * 8;
                float v0 = d[f][g][2 * h]     + bx;
                float v1 = d[f][g][2 * h + 1] + by;
                if (act == 1) { v0 = eluf(v0); v1 = eluf(v1); }
                if (!outb) {
                    *reinterpret_cast<float2*>(Cf + (long long)row * ldc + cc) = make_float2(v0, v1);
                } else {
                    __nv_bfloat162 hb = __floats2bfloat162_rn(v0, v1);
                    float2 hf = __bfloat1622float2(hb);
                    __nv_bfloat162 lb = __floats2bfloat162_rn(v0 - hf.x, v1 - hf.y);
                    const long long o = (long long)row * 512 + cc;
                    *reinterpret_cast<__nv_bfloat162*>(tk_hi + o) = hb;
                    *reinterpret_cast<__nv_bfloat162*>(tk_lo + o) = lb;
                }
            }
        }
    }
}

// ---------------- weights: transpose 512x512 fp32 -> bf16 hi/lo ----------------
struct WPtrs { const float* s[9]; };
__global__ void prep_weights(WPtrs wp, __nv_bfloat16* __restrict__ dhi, __nv_bfloat16* __restrict__ dlo)
{
    __shared__ float t[32][33];
    const int mtx = blockIdx.z;
    const float* src = wp.s[mtx];
    __nv_bfloat16* oh = dhi + (long long)mtx * 512 * 512;
    __nv_bfloat16* ol = dlo + (long long)mtx * 512 * 512;
    const int tx = threadIdx.x, ty = threadIdx.y;
    const int bx = blockIdx.x * 32, by = blockIdx.y * 32;
    #pragma unroll
    for (int i = 0; i < 32; i += 8)
        t[ty + i][tx] = src[(long long)(by + ty + i) * 512 + bx + tx];
    __syncthreads();
    #pragma unroll
    for (int i = 0; i < 32; i += 8) {
        const float v = t[tx][ty + i];
        const __nv_bfloat16 h = __float2bfloat16(v);
        const long long o = (long long)(bx + ty + i) * 512 + by + tx;
        oh[o] = h;
        ol[o] = __float2bfloat16(v - __bfloat162float(h));
    }
}

// ---------------- history small GEMM ----------------
__global__ void hist_small(const float* __restrict__ hist,
                           const __nv_bfloat16* __restrict__ w7h, const __nv_bfloat16* __restrict__ w7l,
                           const __nv_bfloat16* __restrict__ w8h, const __nv_bfloat16* __restrict__ w8l,
                           float* __restrict__ out)
{
    const int wid = threadIdx.x >> 5, lane = threadIdx.x & 31;
    const int c = blockIdx.x * 8 + wid;
    const __nv_bfloat16* rh = (c < 512) ? w7h + (long long)c * 512 : w8h + (long long)(c - 512) * 512;
    const __nv_bfloat16* rl = (c < 512) ? w7l + (long long)c * 512 : w8l + (long long)(c - 512) * 512;
    float acc[8] = {0.f,0.f,0.f,0.f,0.f,0.f,0.f,0.f};
    #pragma unroll 4
    for (int i = 0; i < 16; i++) {
        const int k = lane + i * 32;
        const float w = __bfloat162float(rh[k]) + __bfloat162float(rl[k]);
        #pragma unroll
        for (int r = 0; r < 8; r++) acc[r] = fmaf(hist[r * 512 + k], w, acc[r]);
    }
    #pragma unroll
    for (int r = 0; r < 8; r++) {
        float v = acc[r];
        #pragma unroll
        for (int o = 16; o; o >>= 1) v += __shfl_xor_sync(0xffffffffu, v, o);
        if (lane == 0) out[r * 1024 + c] = v;
    }
}

// ---------------- tk transpose per batch (bf16 hi/lo) ----------------
__global__ void transpose_tk(const __nv_bfloat16* __restrict__ shi, const __nv_bfloat16* __restrict__ slo,
                             __nv_bfloat16* __restrict__ dhi, __nv_bfloat16* __restrict__ dlo)
{
    __shared__ __nv_bfloat16 th[32][33], tl[32][33];
    const long long zb = (long long)blockIdx.z * 512 * 512;
    const int tx = threadIdx.x, ty = threadIdx.y;
    const int bx = blockIdx.x * 32, by = blockIdx.y * 32;
    #pragma unroll
    for (int i = 0; i < 32; i += 8) {
        const long long o = zb + (long long)(by + ty + i) * 512 + bx + tx;
        th[ty + i][tx] = shi[o];
        tl[ty + i][tx] = slo[o];
    }
    __syncthreads();
    #pragma unroll
    for (int i = 0; i < 32; i += 8) {
        const long long o = zb + (long long)(bx + ty + i) * 512 + by + tx;
        dhi[o] = th[tx][ty + i];
        dlo[o] = tl[tx][ty + i];
    }
}

// ---------------- mask dtype detector ----------------
__global__ void detect_mask_kernel(const unsigned int* __restrict__ adj, int nwords)
{
    __shared__ unsigned int s;
    if (threadIdx.x == 0) s = 0u;
    __syncthreads();
    unsigned int local = 0u;
    for (int i = threadIdx.x; i < nwords; i += blockDim.x)
        local |= (adj[i] > 1u) ? 1u : 0u;
    if (local) atomicOr(&s, 1u);
    __syncthreads();
    if (threadIdx.x == 0) g_mask_byte_mode = s;
}

// ---------------- tq = elu(decp + histp + headq + b_tq) -> bf16 hi/lo ----------------
__global__ void build_tq(const float4* __restrict__ dh, const float4* __restrict__ hh,
                         const float4* __restrict__ headq, const float4* __restrict__ btq,
                         __nv_bfloat162* __restrict__ thi, __nv_bfloat162* __restrict__ tlo)
{
    const int i = blockIdx.x * 256 + threadIdx.x;
    const int d  = i & 127;
    const int h  = (i >> 7) & 63;
    const int bs = i >> 13;
    const int b  = bs >> 5;
    float4 a = dh[bs * 256 + d];
    float4 c = hh[b * 256 + d];
    float4 e = headq[(b * 64 + h) * 128 + d];
    float4 g = btq[d];
    float4 r;
    r.x = eluf(a.x + c.x + e.x + g.x);
    r.y = eluf(a.y + c.y + e.y + g.y);
    r.z = eluf(a.z + c.z + e.z + g.z);
    r.w = eluf(a.w + c.w + e.w + g.w);
    __nv_bfloat162 h0 = __floats2bfloat162_rn(r.x, r.y);
    __nv_bfloat162 h1 = __floats2bfloat162_rn(r.z, r.w);
    float2 f0 = __bfloat1622float2(h0), f1 = __bfloat1622float2(h1);
    __nv_bfloat162 l0 = __floats2bfloat162_rn(r.x - f0.x, r.y - f0.y);
    __nv_bfloat162 l1 = __floats2bfloat162_rn(r.z - f1.x, r.w - f1.y);
    thi[2 * i] = h0; thi[2 * i + 1] = h1;
    tlo[2 * i] = l0; tlo[2 * i + 1] = l1;
}

// ---------------- hq = elu(hqd + hqh + b_hq) (cols 512:1024) ----------------
__global__ void build_hq(const float4* __restrict__ dh, const float4* __restrict__ hh,
                         const float4* __restrict__ bhq, float4* __restrict__ hq)
{
    const int i = blockIdx.x * 256 + threadIdx.x;
    const int d  = i & 127;
    const int bs = i >> 7;
    const int b  = bs >> 5;
    float4 a = dh[bs * 256 + 128 + d];
    float4 c = hh[b * 256 + 128 + d];
    float4 g = bhq[d];
    float4 r;
    r.x = eluf(a.x + c.x + g.x);
    r.y = eluf(a.y + c.y + g.y);
    r.z = eluf(a.z + c.z + g.z);
    r.w = eluf(a.w + c.w + g.w);
    hq[i] = r;
}

// ---------------- masked softmax (bf16 hi/lo out only) ----------------
__global__ void masked_softmax(const float* __restrict__ attn,
                               __nv_bfloat16* __restrict__ ahi, __nv_bfloat16* __restrict__ alo,
                               const void* __restrict__ adj, const void* __restrict__ dup)
{
    const int q = blockIdx.x;
    const int b = blockIdx.y;
    const int s = q >> 6, h = q & 63;
    const long long ro = ((long long)(b * 2048 + q)) * 512;
    const float* row = attn + ro;
    const long long aoff = ((long long)(b * 64 + h)) * 512;
    const long long doff = ((long long)(b * 32 + s)) * 512;

    const unsigned int byte_mode = g_mask_byte_mode;
    const unsigned char* am8 = (const unsigned char*)adj + aoff;
    const unsigned char* dm8 = (const unsigned char*)dup + doff;
    const int* am32 = (const int*)adj + aoff;
    const int* dm32 = (const int*)dup + doff;

    const int tid = threadIdx.x;
    float v[2]; int mk[2];
    float lmax = -FLT_MAX;
    #pragma unroll
    for (int j = 0; j < 2; j++) {
        const int t = tid + j * 256;
        if (byte_mode) mk[j] = am8[t]  && !dm8[t];
        else           mk[j] = am32[t] && !dm32[t];
        v[j] = row[t];
        if (mk[j]) lmax = fmaxf(lmax, v[j]);
    }
    __shared__ float smax[8], ssum[8];
    #pragma unroll
    for (int o = 16; o; o >>= 1) lmax = fmaxf(lmax, __shfl_xor_sync(0xffffffffu, lmax, o));
    if ((tid & 31) == 0) smax[tid >> 5] = lmax;
    __syncthreads();
    float bmax = -FLT_MAX;
    #pragma unroll
    for (int w = 0; w < 8; w++) bmax = fmaxf(bmax, smax[w]);

    float e[2], lsum = 0.f;
    #pragma unroll
    for (int j = 0; j < 2; j++) { e[j] = mk[j] ? expf(v[j] - bmax) : 0.f; lsum += e[j]; }
    #pragma unroll
    for (int o = 16; o; o >>= 1) lsum += __shfl_xor_sync(0xffffffffu, lsum, o);
    if ((tid & 31) == 0) ssum[tid >> 5] = lsum;
    __syncthreads();
    float bsum = 0.f;
    #pragma unroll
    for (int w = 0; w < 8; w++) bsum += ssum[w];

    const float inv = 1.f / bsum;
    #pragma unroll
    for (int j = 0; j < 2; j++) {
        const int t = tid + j * 256;
        const float p = e[j] * inv;
        const __nv_bfloat16 hb = __float2bfloat16(p);
        ahi[ro + t] = hb;
        alo[ro + t] = __float2bfloat16(p - __bfloat162float(hb));
    }
}

// ---------------- final: head attention + prob + log (attn from bf16 hi/lo) ----------------
__global__ void final_kernel(const float* __restrict__ hq, const float* __restrict__ hk,
                             const __nv_bfloat16* __restrict__ athi,
                             const __nv_bfloat16* __restrict__ atlo,
                             const int* __restrict__ head, float* __restrict__ out)
{
    const int n = blockIdx.x;
    const int b = n >> 5;
    const int tid = threadIdx.x;

    __shared__ float shq[512];
    __shared__ float sc[64];
    __shared__ float sw[64];
    __shared__ int   s_len;

    if (tid == 0) s_len = 0;
    shq[tid]       = hq[(long long)n * 512 + tid];
    shq[tid + 256] = hq[(long long)n * 512 + 256 + tid];
    __syncthreads();
    if (tid < 64) { if (head[b * 64 + tid] != 0) atomicAdd(&s_len, 1); }
    __syncthreads();

    const int w = tid >> 5, lane = tid & 31;
    for (int k = w; k < 64; k += 8) {
        const float* hkr = hk + ((long long)n * 64 + k) * 512;
        float sacc = 0.f;
        for (int d = lane; d < 512; d += 32) sacc = fmaf(shq[d], hkr[d], sacc);
        #pragma unroll
        for (int o = 16; o; o >>= 1) sacc += __shfl_xor_sync(0xffffffffu, sacc, o);
        if (lane == 0) sc[k] = sacc;
    }
    __syncthreads();

    if (tid == 0) {
        const int len = s_len;
        float mx = -FLT_MAX;
        for (int k = 0; k < len; k++) mx = fmaxf(mx, sc[k]);
        float sum = 0.f;
        for (int k = 0; k < 64; k++) {
            float e = (k < len) ? expf(sc[k] - mx) : 0.f;
            sw[k] = e; sum += e;
        }
        float inv = 1.f / sum;
        for (int k = 0; k < 64; k++) sw[k] *= inv;
    }
    __syncthreads();

    const long long base = (long long)n * 64 * 512;
    for (int t = tid; t < 512; t += 256) {
        float p = 0.f;
        #pragma unroll 8
        for (int k = 0; k < 64; k++) {
            const long long o = base + k * 512 + t;
            const float a = __bfloat162float(athi[o]) + __bfloat162float(atlo[o]);
            p = fmaf(sw[k], a, p);
        }
        out[(long long)n * 512 + t] = logf(p + 1e-20f);
    }
}

// ---------------- launch ----------------
extern "C" void kernel_launch(void* const* d_in, const int* in_sizes, int n_in,
                              void* d_out, int out_size)
{
    const float* dec_out = (const float*)d_in[0];
    const float* history = (const float*)d_in[1];
    const int*   head    = (const int*)  d_in[2];
    const int*   tail    = (const int*)  d_in[3];
    const void*  adj     = d_in[4];
    const void*  dup     = d_in[5];
    const float* emb     = (const float*)d_in[6];
    const float* W_tq    = (const float*)d_in[7];
    const float* b_tq    = (const float*)d_in[8];
    const float* W_tk    = (const float*)d_in[9];
    const float* b_tk    = (const float*)d_in[10];
    const float* W_tout  = (const float*)d_in[11];
    const float* W_hq    = (const float*)d_in[12];
    const float* b_hq    = (const float*)d_in[13];
    const float* W_hk    = (const float*)d_in[14];
    const float* b_hk    = (const float*)d_in[15];

    float *dh, *hh, *headq, *attn, *hk, *hq;
    __nv_bfloat16 *tq_hi, *tq_lo, *tk_hi, *tk_lo, *tkT_hi, *tkT_lo;
    __nv_bfloat16 *at_hi, *at_lo, *ctx_hi, *ctx_lo, *gh_hi, *gh_lo, *wT_hi, *wT_lo;
    cudaGetSymbolAddress((void**)&dh,     g_dh);
    cudaGetSymbolAddress((void**)&hh,     g_hh);
    cudaGetSymbolAddress((void**)&headq,  g_headq);
    cudaGetSymbolAddress((void**)&attn,   g_attn);
    cudaGetSymbolAddress((void**)&hk,     g_hk);
    cudaGetSymbolAddress((void**)&hq,     g_hq);
    cudaGetSymbolAddress((void**)&tq_hi,  g_tq_hi);  cudaGetSymbolAddress((void**)&tq_lo,  g_tq_lo);
    cudaGetSymbolAddress((void**)&tk_hi,  g_tk_hi);  cudaGetSymbolAddress((void**)&tk_lo,  g_tk_lo);
    cudaGetSymbolAddress((void**)&tkT_hi, g_tkT_hi); cudaGetSymbolAddress((void**)&tkT_lo, g_tkT_lo);
    cudaGetSymbolAddress((void**)&at_hi,  g_at_hi);  cudaGetSymbolAddress((void**)&at_lo,  g_at_lo);
    cudaGetSymbolAddress((void**)&ctx_hi, g_ctx_hi); cudaGetSymbolAddress((void**)&ctx_lo, g_ctx_lo);
    cudaGetSymbolAddress((void**)&gh_hi,  g_gh_hi);  cudaGetSymbolAddress((void**)&gh_lo,  g_gh_lo);
    cudaGetSymbolAddress((void**)&wT_hi,  g_wT_hi);  cudaGetSymbolAddress((void**)&wT_lo,  g_wT_lo);

    cudaFuncSetAttribute(gemm_pro,                cudaFuncAttributeMaxDynamicSharedMemorySize, SMEM_BYTES);
    cudaFuncSetAttribute(gemm_mma<0,false,false>, cudaFuncAttributeMaxDynamicSharedMemorySize, SMEM_BYTES);
    cudaFuncSetAttribute(gemm_mma<0,false,true >, cudaFuncAttributeMaxDynamicSharedMemorySize, SMEM_BYTES);
    cudaFuncSetAttribute(gemm_mma<2,true ,true >, cudaFuncAttributeMaxDynamicSharedMemorySize, SMEM_BYTES);
    cudaFuncSetAttribute(gemm_mma<1,false,false>, cudaFuncAttributeMaxDynamicSharedMemorySize, SMEM_BYTES);

    WPtrs wp;
    wp.s[0] = W_tq;               wp.s[1] = W_hq;               wp.s[2] = W_tq + 1024LL*512;
    wp.s[3] = W_tk;               wp.s[4] = W_tout;             wp.s[5] = W_tout + 512LL*512;
    wp.s[6] = W_hk;               wp.s[7] = W_tq + 512LL*512;   wp.s[8] = W_hq + 512LL*512;
    #define WTH(i) (wT_hi + (long long)(i)*512*512)
    #define WTL(i) (wT_lo + (long long)(i)*512*512)

    detect_mask_kernel<<<1, 256>>>((const unsigned int*)adj, 65536);
    prep_weights<<<dim3(16,16,9), dim3(32,8)>>>(wp, wT_hi, wT_lo);

    const __nv_bfloat16* nb = nullptr;

    hist_small<<<128, 256>>>(history, WTH(7), WTL(7), WTH(8), WTL(8), hh);
    gemm_pro<<<320, 256, SMEM_BYTES>>>(dec_out, emb, head, tail, wT_hi, wT_lo,
                                       dh, headq, tk_hi, tk_lo, b_tk);
    transpose_tk<<<dim3(16,16,8), dim3(32,8)>>>(tk_hi, tk_lo, tkT_hi, tkT_lo);
    build_tq<<<8192, 256>>>((const float4*)dh, (const float4*)hh,
                            (const float4*)headq, (const float4*)b_tq,
                            (__nv_bfloat162*)tq_hi, (__nv_bfloat162*)tq_lo);
    gemm_mma<0,false,false><<<dim3(4,32,8), 256, SMEM_BYTES>>>(
        tq_hi, tq_lo, tk_hi, tk_lo, nb, nb, nb, nb,
        attn, nullptr, nullptr, nullptr, 2048, 512,
        2048LL*512, 512LL*512, 2048LL*512, 512);
    masked_softmax<<<dim3(2048,8), 256>>>(attn, at_hi, at_lo, adj, dup);
    gemm_mma<0,false,true><<<dim3(4,32,8), 256, SMEM_BYTES>>>(
        at_hi, at_lo, tkT_hi, tkT_lo, nb, nb, nb, nb,
        nullptr, ctx_hi, ctx_lo, nullptr, 2048, 512,
        2048LL*512, 512LL*512, 2048LL*512, 512);
    gemm_mma<2,true,true><<<dim3(4,256,1), 256, SMEM_BYTES>>>(
        ctx_hi, ctx_lo, WTH(4), WTL(4),
        tq_hi, tq_lo, WTH(5), WTL(5),
        nullptr, gh_hi, gh_lo, nullptr, 16384, 512, 0, 0, 0, 512);
    gemm_mma<1,false,false><<<dim3(4,256,1), 256, SMEM_BYTES>>>(
        gh_hi, gh_lo, WTH(6), WTL(6), nb, nb, nb, nb,
        hk, nullptr, nullptr, b_hk, 16384, 512, 0, 0, 0, 512);
    build_hq<<<128, 256>>>((const float4*)dh, (const float4*)hh,
                           (const float4*)b_hq, (float4*)hq);
    final_kernel<<<256, 256>>>(hq, hk, at_hi, at_lo, head, (float*)d_out);
}

// round 11
// speedup vs baseline: 1.0375x; 1.0375x over previous
#include <cuda_runtime.h>
#include <cuda_bf16.h>
#include <math.h>
#include <float.h>
#include <stdint.h>

// Problem dims: B=8, S=32, HN=64, TN=512, HID=EMB=512
// ---------------- scratch (device globals; no allocation) ----------------
__device__ float g_dh  [256 * 1024];            // [.,0:512)=decp  [.,512:1024)=hqd
__device__ float g_hh  [8   * 1024];            // [.,0:512)=histp [.,512:1024)=hqh
__device__ float g_headq[512  * 512];
__device__ float g_attn [8LL*2048*512];
__device__ float g_hk   [16384LL*512];
__device__ float g_hq   [256 * 512];
__device__ __nv_bfloat16 g_tq_hi [8LL*2048*512], g_tq_lo [8LL*2048*512];
__device__ __nv_bfloat16 g_tk_hi [4096LL*512],   g_tk_lo [4096LL*512];
__device__ __nv_bfloat16 g_tkT_hi[4096LL*512],   g_tkT_lo[4096LL*512];
__device__ __nv_bfloat16 g_at_hi [8LL*2048*512], g_at_lo [8LL*2048*512];
__device__ __nv_bfloat16 g_ctx_hi[8LL*2048*512], g_ctx_lo[8LL*2048*512];
__device__ __nv_bfloat16 g_gh_hi [8LL*2048*512], g_gh_lo [8LL*2048*512];
__device__ __nv_bfloat16 g_wT_hi [9LL*512*512],  g_wT_lo [9LL*512*512];
__device__ unsigned int g_mask_byte_mode;

__device__ __forceinline__ uint32_t smem_u32(const void* p) {
    uint32_t a;
    asm("{ .reg .u64 t; cvta.to.shared.u64 t, %1; cvt.u32.u64 %0, t; }" : "=r"(a) : "l"(p));
    return a;
}
__device__ __forceinline__ void cp16(uint32_t dst, const void* src) {
    asm volatile("cp.async.cg.shared.global [%0], [%1], 16;" :: "r"(dst), "l"(src));
}
__device__ __forceinline__ void mma_bf16(float* d, const uint32_t* a, const uint32_t* b) {
    asm volatile("mma.sync.aligned.m16n8k16.row.col.f32.bf16.bf16.f32 "
        "{%0,%1,%2,%3}, {%4,%5,%6,%7}, {%8,%9}, {%0,%1,%2,%3};"
        : "+f"(d[0]), "+f"(d[1]), "+f"(d[2]), "+f"(d[3])
        : "r"(a[0]), "r"(a[1]), "r"(a[2]), "r"(a[3]), "r"(b[0]), "r"(b[1]));
}
__device__ __forceinline__ void ldm_x4(uint32_t& r0, uint32_t& r1, uint32_t& r2, uint32_t& r3,
                                       uint32_t addr) {
    asm volatile("ldmatrix.sync.aligned.m8n8.x4.shared.b16 {%0,%1,%2,%3}, [%4];"
        : "=r"(r0), "=r"(r1), "=r"(r2), "=r"(r3) : "r"(addr));
}
__device__ __forceinline__ float eluf(float x) { return x > 0.f ? x : expm1f(x); }

// smem: 4 buffers (2 pairs); each = A tile (64 rows x 144B) + B tile (128 x 144B)
// row layout: bytes [0,64) = hi 32 bf16, [64,128) = lo 32 bf16, [128,144) pad
#define ROWB   144
#define MT     64
#define ATILEB (MT * ROWB)           // 9216
#define BTILEB (128 * ROWB)          // 18432
#define BUFB   (ATILEB + BTILEB)     // 27648
#define NSTAGE 4
#define SMEM_BYTES (NSTAGE * BUFB)   // 110592 -> 2 CTAs/SM

#define LDM_SETUP \
    const int lrow = lane & 7, lsel = lane >> 3; \
    const int a_dm = (lsel & 1) << 3, a_dk = (lsel >> 1) << 3; \
    const int b_dn = (lsel >> 1) << 3, b_dk = (lsel & 1) << 3;

// ==================================================================
// Main bf16-split GEMM (pre-split bf16 A), pair-loop with ONE barrier
// per K=64 (2 chunks). 4 smem stages = 2 buffer pairs.
// ==================================================================
template<int ACT, bool TWO, bool OUTB>
__global__ void __launch_bounds__(256, 2) gemm_mma(
    const __nv_bfloat16* __restrict__ Ahi, const __nv_bfloat16* __restrict__ Alo,
    const __nv_bfloat16* __restrict__ Bhi, const __nv_bfloat16* __restrict__ Blo,
    const __nv_bfloat16* __restrict__ A2hi, const __nv_bfloat16* __restrict__ A2lo,
    const __nv_bfloat16* __restrict__ B2hi, const __nv_bfloat16* __restrict__ B2lo,
    float* __restrict__ Cf, __nv_bfloat16* __restrict__ Chi, __nv_bfloat16* __restrict__ Clo,
    const float* __restrict__ bias,
    int M, int K, long long sA, long long sB, long long sC, int ldc)
{
    constexpr int FM = 2;
    extern __shared__ char sm[];
    const uint32_t smb = smem_u32(sm);
    const int tid = threadIdx.x, wid = tid >> 5, lane = tid & 31;
    const int wm = wid >> 2, wn = wid & 3;
    const int m0 = blockIdx.y * MT, n0 = blockIdx.x * 128, z = blockIdx.z;

    const int kc  = K >> 5;
    const int nch = TWO ? 2 * kc : kc;
    const int np  = nch >> 1;                       // pairs of chunks

    float d[FM][4][4];
    #pragma unroll
    for (int f = 0; f < FM; f++)
        #pragma unroll
        for (int g = 0; g < 4; g++)
            #pragma unroll
            for (int e = 0; e < 4; e++) d[f][g][e] = 0.f;

    auto load_chunk = [&](int c) {
        const bool sec = TWO && (c >= kc);
        const int koff = (sec ? c - kc : c) << 5;
        const int buf = c & 3;
        const uint32_t smA = smb + buf * BUFB;
        const uint32_t smB = smA + ATILEB;
        {
            const __nv_bfloat16* pH = (sec ? A2hi : Ahi) + (long long)z * sA;
            const __nv_bfloat16* pL = (sec ? A2lo : Alo) + (long long)z * sA;
            const int r = tid >> 2, s = tid & 3;
            const long long go = (long long)(m0 + r) * K + koff + s * 8;
            const uint32_t dst = smA + r * ROWB + s * 16;
            cp16(dst,      pH + go);
            cp16(dst + 64, pL + go);
        }
        {
            const __nv_bfloat16* pH = (sec ? B2hi : Bhi) + (long long)z * sB;
            const __nv_bfloat16* pL = (sec ? B2lo : Blo) + (long long)z * sB;
            #pragma unroll
            for (int i = 0; i < 2; i++) {
                const int idx = tid + 256 * i;
                const int r = idx >> 2, s = idx & 3;
                const long long go = (long long)(n0 + r) * K + koff + s * 8;
                const uint32_t dst = smB + r * ROWB + s * 16;
                cp16(dst,      pH + go);
                cp16(dst + 64, pL + go);
            }
        }
    };
    auto load_pair = [&](int p) {
        load_chunk(2 * p);
        load_chunk(2 * p + 1);
        asm volatile("cp.async.commit_group;");
    };

    LDM_SETUP

    auto compute_chunk = [&](int c) {
        const uint32_t a_base = smb + (c & 3) * BUFB;
        const uint32_t b_base = a_base + ATILEB;
        uint32_t b0[4][2], b1[4][2], b2[4][2], b3[4][2];
        uint32_t aA[FM][4], aB[FM][4];
        #define LDB(bb, kb) { \
            _Pragma("unroll") \
            for (int gp = 0; gp < 2; gp++) { \
                const uint32_t addr = b_base \
                    + (uint32_t)((wn * 32 + gp * 16 + b_dn + lrow) * ROWB + ((kb) + b_dk) * 2); \
                ldm_x4(bb[2*gp][0], bb[2*gp][1], bb[2*gp+1][0], bb[2*gp+1][1], addr); \
            } }
        #define LDA(aa, ka) { \
            _Pragma("unroll") \
            for (int f = 0; f < FM; f++) { \
                const uint32_t addr = a_base \
                    + (uint32_t)((wm * 32 + f * 16 + a_dm + lrow) * ROWB + ((ka) + a_dk) * 2); \
                ldm_x4(aa[f][0], aa[f][1], aa[f][2], aa[f][3], addr); \
            } }
        #define MMAG(aa, bb) { \
            _Pragma("unroll") \
            for (int f = 0; f < FM; f++) \
                _Pragma("unroll") \
                for (int g = 0; g < 4; g++) \
                    mma_bf16(d[f][g], aa[f], bb[g]); }
        LDB(b0, 0);  LDB(b1, 16);
        LDA(aA, 0);  LDA(aB, 16);
        MMAG(aA, b0);
        MMAG(aB, b1);
        LDB(b2, 32); LDB(b3, 48);
        MMAG(aA, b2);
        MMAG(aB, b3);
        LDA(aA, 32); LDA(aB, 48);
        MMAG(aA, b0);
        MMAG(aB, b1);
        #undef LDB
        #undef LDA
        #undef MMAG
    };

    load_pair(0);
    for (int p = 0; p < np; ++p) {
        asm volatile("cp.async.wait_group 0;");
        __syncthreads();
        if (p + 1 < np) load_pair(p + 1);
        compute_chunk(2 * p);
        compute_chunk(2 * p + 1);
    }

    const int qr = lane >> 2, qc = 2 * (lane & 3);
    #pragma unroll
    for (int f = 0; f < FM; f++) {
        #pragma unroll
        for (int g = 0; g < 4; g++) {
            const int cc = n0 + wn * 32 + g * 8 + qc;
            float bx = 0.f, by = 0.f;
            if (bias) { bx = bias[cc]; by = bias[cc + 1]; }
            #pragma unroll
            for (int h = 0; h < 2; h++) {
                const int row = m0 + wm * 32 + f * 16 + qr + h * 8;
                if (row >= M) continue;
                float v0 = d[f][g][2 * h]     + bx;
                float v1 = d[f][g][2 * h + 1] + by;
                if (ACT == 1) { v0 = eluf(v0); v1 = eluf(v1); }
                else if (ACT == 2) { v0 = tanhf(v0); v1 = tanhf(v1); }
                const long long o = (long long)z * sC + (long long)row * ldc + cc;
                if constexpr (!OUTB) {
                    *reinterpret_cast<float2*>(Cf + o) = make_float2(v0, v1);
                } else {
                    __nv_bfloat162 hb = __floats2bfloat162_rn(v0, v1);
                    float2 hf = __bfloat1622float2(hb);
                    __nv_bfloat162 lb = __floats2bfloat162_rn(v0 - hf.x, v1 - hf.y);
                    *reinterpret_cast<__nv_bfloat162*>(Chi + o) = hb;
                    *reinterpret_cast<__nv_bfloat162*>(Clo + o) = lb;
                }
            }
        }
    }
}

// ==================================================================
// Prologue uber-GEMM (fp32 A with gather), pair-loop single barrier:
// Grid 320 CTAs: [0,32) dh, [32,64) headq, [64,320) tk
// ==================================================================
__global__ void __launch_bounds__(256, 2) gemm_pro(
    const float* __restrict__ dec_out, const float* __restrict__ emb,
    const int* __restrict__ head, const int* __restrict__ tail,
    const __nv_bfloat16* __restrict__ wT_hi, const __nv_bfloat16* __restrict__ wT_lo,
    float* __restrict__ dh, float* __restrict__ headq,
    __nv_bfloat16* __restrict__ tk_hi, __nv_bfloat16* __restrict__ tk_lo,
    const float* __restrict__ b_tk)
{
    constexpr int FM = 2;
    extern __shared__ char sm[];
    const uint32_t smb = smem_u32(sm);
    const int tid = threadIdx.x, wid = tid >> 5, lane = tid & 31;
    const int wm = wid >> 2, wn = wid & 3;

    const int bid = blockIdx.x;
    const float* Af; const int* gidx; long long boff; float* Cf; int ldc;
    int m0, n0; int outb, act; const float* bias;
    if (bid < 32) {
        Af = dec_out; gidx = nullptr; boff = 0;
        Cf = dh; ldc = 1024; outb = 0; act = 0; bias = nullptr;
        n0 = (bid & 7) * 128; m0 = (bid >> 3) * MT;
    } else if (bid < 64) {
        const int t = bid - 32;
        Af = emb; gidx = head; boff = 2LL * 512 * 512;
        Cf = headq; ldc = 512; outb = 0; act = 0; bias = nullptr;
        n0 = (t & 3) * 128; m0 = (t >> 2) * MT;
    } else {
        const int t = bid - 64;
        Af = emb; gidx = tail; boff = 3LL * 512 * 512;
        Cf = nullptr; ldc = 512; outb = 1; act = 1; bias = b_tk;
        n0 = (t & 3) * 128; m0 = (t >> 2) * MT;
    }
    const __nv_bfloat16* Bhi = wT_hi + boff;
    const __nv_bfloat16* Blo = wT_lo + boff;
    const int K = 512, nch = 16, np = 8;

    float d[FM][4][4];
    #pragma unroll
    for (int f = 0; f < FM; f++)
        #pragma unroll
        for (int g = 0; g < 4; g++)
            #pragma unroll
            for (int e = 0; e < 4; e++) d[f][g][e] = 0.f;

    auto load_chunk = [&](int c) {
        const int koff = c << 5;
        const int buf = c & 3;
        const uint32_t smA = smb + buf * BUFB;
        const uint32_t smB = smA + ATILEB;
        char* smAp = sm + buf * BUFB;
        #pragma unroll
        for (int i = 0; i < 2; i++) {
            const int idx = tid + 256 * i;
            const int r = idx >> 3, s = idx & 7;
            const int gm = m0 + r;
            const long long row = gidx ? (long long)gidx[gm] : (long long)gm;
            float4 v = *reinterpret_cast<const float4*>(Af + row * K + koff + s * 4);
            __nv_bfloat162 h01 = __floats2bfloat162_rn(v.x, v.y);
            __nv_bfloat162 h23 = __floats2bfloat162_rn(v.z, v.w);
            float2 f01 = __bfloat1622float2(h01), f23 = __bfloat1622float2(h23);
            __nv_bfloat162 l01 = __floats2bfloat162_rn(v.x - f01.x, v.y - f01.y);
            __nv_bfloat162 l23 = __floats2bfloat162_rn(v.z - f23.x, v.w - f23.y);
            uint2 uh, ul;
            uh.x = *(uint32_t*)&h01; uh.y = *(uint32_t*)&h23;
            ul.x = *(uint32_t*)&l01; ul.y = *(uint32_t*)&l23;
            *reinterpret_cast<uint2*>(smAp + r * ROWB + s * 8)      = uh;
            *reinterpret_cast<uint2*>(smAp + r * ROWB + 64 + s * 8) = ul;
        }
        #pragma unroll
        for (int i = 0; i < 2; i++) {
            const int idx = tid + 256 * i;
            const int r = idx >> 2, s = idx & 3;
            const long long go = (long long)(n0 + r) * K + koff + s * 8;
            const uint32_t dst = smB + r * ROWB + s * 16;
            cp16(dst,      Bhi + go);
            cp16(dst + 64, Blo + go);
        }
    };
    auto load_pair = [&](int p) {
        load_chunk(2 * p);
        load_chunk(2 * p + 1);
        asm volatile("cp.async.commit_group;");
    };

    const int stepA[6] = {0, 16, 0, 16, 32, 48};
    const int stepB[6] = {0, 16, 32, 48, 0, 16};
    LDM_SETUP

    auto compute_chunk = [&](int c) {
        const uint32_t a_base = smb + (c & 3) * BUFB;
        const uint32_t b_base = a_base + ATILEB;
        #pragma unroll
        for (int st = 0; st < 6; ++st) {
            const int ka = stepA[st], kb = stepB[st];
            uint32_t a[FM][4], b[4][2];
            #pragma unroll
            for (int f = 0; f < FM; f++) {
                const uint32_t addr = a_base
                    + (uint32_t)((wm * 32 + f * 16 + a_dm + lrow) * ROWB + (ka + a_dk) * 2);
                ldm_x4(a[f][0], a[f][1], a[f][2], a[f][3], addr);
            }
            #pragma unroll
            for (int gp = 0; gp < 2; gp++) {
                const uint32_t addr = b_base
                    + (uint32_t)((wn * 32 + gp * 16 + b_dn + lrow) * ROWB + (kb + b_dk) * 2);
                ldm_x4(b[2*gp][0], b[2*gp][1], b[2*gp+1][0], b[2*gp+1][1], addr);
            }
            #pragma unroll
            for (int f = 0; f < FM; f++)
                #pragma unroll
                for (int g = 0; g < 4; g++)
                    mma_bf16(d[f][g], a[f], b[g]);
        }
    };

    load_pair(0);
    for (int p = 0; p < np; ++p) {
        asm volatile("cp.async.wait_group 0;");
        __syncthreads();
        if (p + 1 < np) load_pair(p + 1);
        compute_chunk(2 * p);
        compute_chunk(2 * p + 1);
    }

    const int qr = lane >> 2, qc = 2 * (lane & 3);
    #pragma unroll
    for (int f = 0; f < FM; f++) {
        #pragma unroll
        for (int g = 0; g < 4; g++) {
            const int cc = n0 + wn * 32 + g * 8 + qc;
            float bx = 0.f, by = 0.f;
            if (bias) { bx = bias[cc]; by = bias[cc + 1]; }
            #pragma unroll
            for (int h = 0; h < 2; h++) {
                const int row = m0 + wm * 32 + f * 16 + qr + h * 8;
                float v0 = d[f][g][2 * h]     + bx;
                float v1 = d[f][g][2 * h + 1] + by;
                if (act == 1) { v0 = eluf(v0); v1 = eluf(v1); }
                if (!outb) {
                    *reinterpret_cast<float2*>(Cf + (long long)row * ldc + cc) = make_float2(v0, v1);
                } else {
                    __nv_bfloat162 hb = __floats2bfloat162_rn(v0, v1);
                    float2 hf = __bfloat1622float2(hb);
                    __nv_bfloat162 lb = __floats2bfloat162_rn(v0 - hf.x, v1 - hf.y);
                    const long long o = (long long)row * 512 + cc;
                    *reinterpret_cast<__nv_bfloat162*>(tk_hi + o) = hb;
                    *reinterpret_cast<__nv_bfloat162*>(tk_lo + o) = lb;
                }
            }
        }
    }
}

// ---------------- weights: transpose 512x512 fp32 -> bf16 hi/lo ----------------
struct WPtrs { const float* s[9]; };
__global__ void prep_weights(WPtrs wp, __nv_bfloat16* __restrict__ dhi, __nv_bfloat16* __restrict__ dlo)
{
    __shared__ float t[32][33];
    const int mtx = blockIdx.z;
    const float* src = wp.s[mtx];
    __nv_bfloat16* oh = dhi + (long long)mtx * 512 * 512;
    __nv_bfloat16* ol = dlo + (long long)mtx * 512 * 512;
    const int tx = threadIdx.x, ty = threadIdx.y;
    const int bx = blockIdx.x * 32, by = blockIdx.y * 32;
    #pragma unroll
    for (int i = 0; i < 32; i += 8)
        t[ty + i][tx] = src[(long long)(by + ty + i) * 512 + bx + tx];
    __syncthreads();
    #pragma unroll
    for (int i = 0; i < 32; i += 8) {
        const float v = t[tx][ty + i];
        const __nv_bfloat16 h = __float2bfloat16(v);
        const long long o = (long long)(bx + ty + i) * 512 + by + tx;
        oh[o] = h;
        ol[o] = __float2bfloat16(v - __bfloat162float(h));
    }
}

// ---------------- history small GEMM ----------------
__global__ void hist_small(const float* __restrict__ hist,
                           const __nv_bfloat16* __restrict__ w7h, const __nv_bfloat16* __restrict__ w7l,
                           const __nv_bfloat16* __restrict__ w8h, const __nv_bfloat16* __restrict__ w8l,
                           float* __restrict__ out)
{
    const int wid = threadIdx.x >> 5, lane = threadIdx.x & 31;
    const int c = blockIdx.x * 8 + wid;
    const __nv_bfloat16* rh = (c < 512) ? w7h + (long long)c * 512 : w8h + (long long)(c - 512) * 512;
    const __nv_bfloat16* rl = (c < 512) ? w7l + (long long)c * 512 : w8l + (long long)(c - 512) * 512;
    float acc[8] = {0.f,0.f,0.f,0.f,0.f,0.f,0.f,0.f};
    #pragma unroll 4
    for (int i = 0; i < 16; i++) {
        const int k = lane + i * 32;
        const float w = __bfloat162float(rh[k]) + __bfloat162float(rl[k]);
        #pragma unroll
        for (int r = 0; r < 8; r++) acc[r] = fmaf(hist[r * 512 + k], w, acc[r]);
    }
    #pragma unroll
    for (int r = 0; r < 8; r++) {
        float v = acc[r];
        #pragma unroll
        for (int o = 16; o; o >>= 1) v += __shfl_xor_sync(0xffffffffu, v, o);
        if (lane == 0) out[r * 1024 + c] = v;
    }
}

// ---------------- tk transpose per batch (bf16 hi/lo) ----------------
__global__ void transpose_tk(const __nv_bfloat16* __restrict__ shi, const __nv_bfloat16* __restrict__ slo,
                             __nv_bfloat16* __restrict__ dhi, __nv_bfloat16* __restrict__ dlo)
{
    __shared__ __nv_bfloat16 th[32][33], tl[32][33];
    const long long zb = (long long)blockIdx.z * 512 * 512;
    const int tx = threadIdx.x, ty = threadIdx.y;
    const int bx = blockIdx.x * 32, by = blockIdx.y * 32;
    #pragma unroll
    for (int i = 0; i < 32; i += 8) {
        const long long o = zb + (long long)(by + ty + i) * 512 + bx + tx;
        th[ty + i][tx] = shi[o];
        tl[ty + i][tx] = slo[o];
    }
    __syncthreads();
    #pragma unroll
    for (int i = 0; i < 32; i += 8) {
        const long long o = zb + (long long)(bx + ty + i) * 512 + by + tx;
        dhi[o] = th[tx][ty + i];
        dlo[o] = tl[tx][ty + i];
    }
}

// ---------------- mask dtype detector ----------------
__global__ void detect_mask_kernel(const unsigned int* __restrict__ adj, int nwords)
{
    __shared__ unsigned int s;
    if (threadIdx.x == 0) s = 0u;
    __syncthreads();
    unsigned int local = 0u;
    for (int i = threadIdx.x; i < nwords; i += blockDim.x)
        local |= (adj[i] > 1u) ? 1u : 0u;
    if (local) atomicOr(&s, 1u);
    __syncthreads();
    if (threadIdx.x == 0) g_mask_byte_mode = s;
}

// ---------------- tq = elu(decp + histp + headq + b_tq) -> bf16 hi/lo ----------------
__global__ void build_tq(const float4* __restrict__ dh, const float4* __restrict__ hh,
                         const float4* __restrict__ headq, const float4* __restrict__ btq,
                         __nv_bfloat162* __restrict__ thi, __nv_bfloat162* __restrict__ tlo)
{
    const int i = blockIdx.x * 256 + threadIdx.x;
    const int d  = i & 127;
    const int h  = (i >> 7) & 63;
    const int bs = i >> 13;
    const int b  = bs >> 5;
    float4 a = dh[bs * 256 + d];
    float4 c = hh[b * 256 + d];
    float4 e = headq[(b * 64 + h) * 128 + d];
    float4 g = btq[d];
    float4 r;
    r.x = eluf(a.x + c.x + e.x + g.x);
    r.y = eluf(a.y + c.y + e.y + g.y);
    r.z = eluf(a.z + c.z + e.z + g.z);
    r.w = eluf(a.w + c.w + e.w + g.w);
    __nv_bfloat162 h0 = __floats2bfloat162_rn(r.x, r.y);
    __nv_bfloat162 h1 = __floats2bfloat162_rn(r.z, r.w);
    float2 f0 = __bfloat1622float2(h0), f1 = __bfloat1622float2(h1);
    __nv_bfloat162 l0 = __floats2bfloat162_rn(r.x - f0.x, r.y - f0.y);
    __nv_bfloat162 l1 = __floats2bfloat162_rn(r.z - f1.x, r.w - f1.y);
    thi[2 * i] = h0; thi[2 * i + 1] = h1;
    tlo[2 * i] = l0; tlo[2 * i + 1] = l1;
}

// ---------------- hq = elu(hqd + hqh + b_hq) (cols 512:1024) ----------------
__global__ void build_hq(const float4* __restrict__ dh, const float4* __restrict__ hh,
                         const float4* __restrict__ bhq, float4* __restrict__ hq)
{
    const int i = blockIdx.x * 256 + threadIdx.x;
    const int d  = i & 127;
    const int bs = i >> 7;
    const int b  = bs >> 5;
    float4 a = dh[bs * 256 + 128 + d];
    float4 c = hh[b * 256 + 128 + d];
    float4 g = bhq[d];
    float4 r;
    r.x = eluf(a.x + c.x + g.x);
    r.y = eluf(a.y + c.y + g.y);
    r.z = eluf(a.z + c.z + g.z);
    r.w = eluf(a.w + c.w + g.w);
    hq[i] = r;
}

// ---------------- masked softmax (bf16 hi/lo out only) ----------------
__global__ void masked_softmax(const float* __restrict__ attn,
                               __nv_bfloat16* __restrict__ ahi, __nv_bfloat16* __restrict__ alo,
                               const void* __restrict__ adj, const void* __restrict__ dup)
{
    const int q = blockIdx.x;
    const int b = blockIdx.y;
    const int s = q >> 6, h = q & 63;
    const long long ro = ((long long)(b * 2048 + q)) * 512;
    const float* row = attn + ro;
    const long long aoff = ((long long)(b * 64 + h)) * 512;
    const long long doff = ((long long)(b * 32 + s)) * 512;

    const unsigned int byte_mode = g_mask_byte_mode;
    const unsigned char* am8 = (const unsigned char*)adj + aoff;
    const unsigned char* dm8 = (const unsigned char*)dup + doff;
    const int* am32 = (const int*)adj + aoff;
    const int* dm32 = (const int*)dup + doff;

    const int tid = threadIdx.x;
    float v[2]; int mk[2];
    float lmax = -FLT_MAX;
    #pragma unroll
    for (int j = 0; j < 2; j++) {
        const int t = tid + j * 256;
        if (byte_mode) mk[j] = am8[t]  && !dm8[t];
        else           mk[j] = am32[t] && !dm32[t];
        v[j] = row[t];
        if (mk[j]) lmax = fmaxf(lmax, v[j]);
    }
    __shared__ float smax[8], ssum[8];
    #pragma unroll
    for (int o = 16; o; o >>= 1) lmax = fmaxf(lmax, __shfl_xor_sync(0xffffffffu, lmax, o));
    if ((tid & 31) == 0) smax[tid >> 5] = lmax;
    __syncthreads();
    float bmax = -FLT_MAX;
    #pragma unroll
    for (int w = 0; w < 8; w++) bmax = fmaxf(bmax, smax[w]);

    float e[2], lsum = 0.f;
    #pragma unroll
    for (int j = 0; j < 2; j++) { e[j] = mk[j] ? expf(v[j] - bmax) : 0.f; lsum += e[j]; }
    #pragma unroll
    for (int o = 16; o; o >>= 1) lsum += __shfl_xor_sync(0xffffffffu, lsum, o);
    if ((tid & 31) == 0) ssum[tid >> 5] = lsum;
    __syncthreads();
    float bsum = 0.f;
    #pragma unroll
    for (int w = 0; w < 8; w++) bsum += ssum[w];

    const float inv = 1.f / bsum;
    #pragma unroll
    for (int j = 0; j < 2; j++) {
        const int t = tid + j * 256;
        const float p = e[j] * inv;
        const __nv_bfloat16 hb = __float2bfloat16(p);
        ahi[ro + t] = hb;
        alo[ro + t] = __float2bfloat16(p - __bfloat162float(hb));
    }
}

// ---------------- final: head attention + prob + log (attn from bf16 hi/lo) ----------------
__global__ void final_kernel(const float* __restrict__ hq, const float* __restrict__ hk,
                             const __nv_bfloat16* __restrict__ athi,
                             const __nv_bfloat16* __restrict__ atlo,
                             const int* __restrict__ head, float* __restrict__ out)
{
    const int n = blockIdx.x;
    const int b = n >> 5;
    const int tid = threadIdx.x;

    __shared__ float shq[512];
    __shared__ float sc[64];
    __shared__ float sw[64];
    __shared__ int   s_len;

    if (tid == 0) s_len = 0;
    shq[tid]       = hq[(long long)n * 512 + tid];
    shq[tid + 256] = hq[(long long)n * 512 + 256 + tid];
    __syncthreads();
    if (tid < 64) { if (head[b * 64 + tid] != 0) atomicAdd(&s_len, 1); }
    __syncthreads();

    const int w = tid >> 5, lane = tid & 31;
    for (int k = w; k < 64; k += 8) {
        const float* hkr = hk + ((long long)n * 64 + k) * 512;
        float sacc = 0.f;
        for (int d = lane; d < 512; d += 32) sacc = fmaf(shq[d], hkr[d], sacc);
        #pragma unroll
        for (int o = 16; o; o >>= 1) sacc += __shfl_xor_sync(0xffffffffu, sacc, o);
        if (lane == 0) sc[k] = sacc;
    }
    __syncthreads();

    if (tid == 0) {
        const int len = s_len;
        float mx = -FLT_MAX;
        for (int k = 0; k < len; k++) mx = fmaxf(mx, sc[k]);
        float sum = 0.f;
        for (int k = 0; k < 64; k++) {
            float e = (k < len) ? expf(sc[k] - mx) : 0.f;
            sw[k] = e; sum += e;
        }
        float inv = 1.f / sum;
        for (int k = 0; k < 64; k++) sw[k] *= inv;
    }
    __syncthreads();

    const long long base = (long long)n * 64 * 512;
    for (int t = tid; t < 512; t += 256) {
        float p = 0.f;
        #pragma unroll 8
        for (int k = 0; k < 64; k++) {
            const long long o = base + k * 512 + t;
            const float a = __bfloat162float(athi[o]) + __bfloat162float(atlo[o]);
            p = fmaf(sw[k], a, p);
        }
        out[(long long)n * 512 + t] = logf(p + 1e-20f);
    }
}

// ---------------- launch ----------------
extern "C" void kernel_launch(void* const* d_in, const int* in_sizes, int n_in,
                              void* d_out, int out_size)
{
    const float* dec_out = (const float*)d_in[0];
    const float* history = (const float*)d_in[1];
    const int*   head    = (const int*)  d_in[2];
    const int*   tail    = (const int*)  d_in[3];
    const void*  adj     = d_in[4];
    const void*  dup     = d_in[5];
    const float* emb     = (const float*)d_in[6];
    const float* W_tq    = (const float*)d_in[7];
    const float* b_tq    = (const float*)d_in[8];
    const float* W_tk    = (const float*)d_in[9];
    const float* b_tk    = (const float*)d_in[10];
    const float* W_tout  = (const float*)d_in[11];
    const float* W_hq    = (const float*)d_in[12];
    const float* b_hq    = (const float*)d_in[13];
    const float* W_hk    = (const float*)d_in[14];
    const float* b_hk    = (const float*)d_in[15];

    float *dh, *hh, *headq, *attn, *hk, *hq;
    __nv_bfloat16 *tq_hi, *tq_lo, *tk_hi, *tk_lo, *tkT_hi, *tkT_lo;
    __nv_bfloat16 *at_hi, *at_lo, *ctx_hi, *ctx_lo, *gh_hi, *gh_lo, *wT_hi, *wT_lo;
    cudaGetSymbolAddress((void**)&dh,     g_dh);
    cudaGetSymbolAddress((void**)&hh,     g_hh);
    cudaGetSymbolAddress((void**)&headq,  g_headq);
    cudaGetSymbolAddress((void**)&attn,   g_attn);
    cudaGetSymbolAddress((void**)&hk,     g_hk);
    cudaGetSymbolAddress((void**)&hq,     g_hq);
    cudaGetSymbolAddress((void**)&tq_hi,  g_tq_hi);  cudaGetSymbolAddress((void**)&tq_lo,  g_tq_lo);
    cudaGetSymbolAddress((void**)&tk_hi,  g_tk_hi);  cudaGetSymbolAddress((void**)&tk_lo,  g_tk_lo);
    cudaGetSymbolAddress((void**)&tkT_hi, g_tkT_hi); cudaGetSymbolAddress((void**)&tkT_lo, g_tkT_lo);
    cudaGetSymbolAddress((void**)&at_hi,  g_at_hi);  cudaGetSymbolAddress((void**)&at_lo,  g_at_lo);
    cudaGetSymbolAddress((void**)&ctx_hi, g_ctx_hi); cudaGetSymbolAddress((void**)&ctx_lo, g_ctx_lo);
    cudaGetSymbolAddress((void**)&gh_hi,  g_gh_hi);  cudaGetSymbolAddress((void**)&gh_lo,  g_gh_lo);
    cudaGetSymbolAddress((void**)&wT_hi,  g_wT_hi);  cudaGetSymbolAddress((void**)&wT_lo,  g_wT_lo);

    cudaFuncSetAttribute(gemm_pro,                cudaFuncAttributeMaxDynamicSharedMemorySize, SMEM_BYTES);
    cudaFuncSetAttribute(gemm_mma<0,false,false>, cudaFuncAttributeMaxDynamicSharedMemorySize, SMEM_BYTES);
    cudaFuncSetAttribute(gemm_mma<0,false,true >, cudaFuncAttributeMaxDynamicSharedMemorySize, SMEM_BYTES);
    cudaFuncSetAttribute(gemm_mma<2,true ,true >, cudaFuncAttributeMaxDynamicSharedMemorySize, SMEM_BYTES);
    cudaFuncSetAttribute(gemm_mma<1,false,false>, cudaFuncAttributeMaxDynamicSharedMemorySize, SMEM_BYTES);

    WPtrs wp;
    wp.s[0] = W_tq;               wp.s[1] = W_hq;               wp.s[2] = W_tq + 1024LL*512;
    wp.s[3] = W_tk;               wp.s[4] = W_tout;             wp.s[5] = W_tout + 512LL*512;
    wp.s[6] = W_hk;               wp.s[7] = W_tq + 512LL*512;   wp.s[8] = W_hq + 512LL*512;
    #define WTH(i) (wT_hi + (long long)(i)*512*512)
    #define WTL(i) (wT_lo + (long long)(i)*512*512)

    detect_mask_kernel<<<1, 256>>>((const unsigned int*)adj, 65536);
    prep_weights<<<dim3(16,16,9), dim3(32,8)>>>(wp, wT_hi, wT_lo);

    const __nv_bfloat16* nb = nullptr;

    hist_small<<<128, 256>>>(history, WTH(7), WTL(7), WTH(8), WTL(8), hh);
    gemm_pro<<<320, 256, SMEM_BYTES>>>(dec_out, emb, head, tail, wT_hi, wT_lo,
                                       dh, headq, tk_hi, tk_lo, b_tk);
    transpose_tk<<<dim3(16,16,8), dim3(32,8)>>>(tk_hi, tk_lo, tkT_hi, tkT_lo);
    build_tq<<<8192, 256>>>((const float4*)dh, (const float4*)hh,
                            (const float4*)headq, (const float4*)b_tq,
                            (__nv_bfloat162*)tq_hi, (__nv_bfloat162*)tq_lo);
    gemm_mma<0,false,false><<<dim3(4,32,8), 256, SMEM_BYTES>>>(
        tq_hi, tq_lo, tk_hi, tk_lo, nb, nb, nb, nb,
        attn, nullptr, nullptr, nullptr, 2048, 512,
        2048LL*512, 512LL*512, 2048LL*512, 512);
    masked_softmax<<<dim3(2048,8), 256>>>(attn, at_hi, at_lo, adj, dup);
    gemm_mma<0,false,true><<<dim3(4,32,8), 256, SMEM_BYTES>>>(
        at_hi, at_lo, tkT_hi, tkT_lo, nb, nb, nb, nb,
        nullptr, ctx_hi, ctx_lo, nullptr, 2048, 512,
        2048LL*512, 512LL*512, 2048LL*512, 512);
    gemm_mma<2,true,true><<<dim3(4,256,1), 256, SMEM_BYTES>>>(
        ctx_hi, ctx_lo, WTH(4), WTL(4),
        tq_hi, tq_lo, WTH(5), WTL(5),
        nullptr, gh_hi, gh_lo, nullptr, 16384, 512, 0, 0, 0, 512);
    gemm_mma<1,false,false><<<dim3(4,256,1), 256, SMEM_BYTES>>>(
        gh_hi, gh_lo, WTH(6), WTL(6), nb, nb, nb, nb,
        hk, nullptr, nullptr, b_hk, 16384, 512, 0, 0, 0, 512);
    build_hq<<<128, 256>>>((const float4*)dh, (const float4*)hh,
                           (const float4*)b_hq, (float4*)hq);
    final_kernel<<<256, 256>>>(hq, hk, at_hi, at_lo, head, (float*)d_out);
}

// round 12
// speedup vs baseline: 1.7371x; 1.6743x over previous
#include <cuda_runtime.h>
#include <cuda_bf16.h>
#include <math.h>
#include <float.h>
#include <stdint.h>

// Problem dims: B=8, S=32, HN=64, TN=512, HID=EMB=512
// ---------------- scratch (device globals; no allocation) ----------------
__device__ float g_dh  [256 * 1024];            // [.,0:512)=decp  [.,512:1024)=hqd
__device__ float g_hh  [8   * 1024];            // [.,0:512)=histp [.,512:1024)=hqh
__device__ float g_headq[512  * 512];
__device__ float g_attn [8LL*2048*512];
__device__ float g_hk   [16384LL*512];
__device__ float g_hq   [256 * 512];
__device__ __nv_bfloat16 g_tq_hi [8LL*2048*512];
__device__ __nv_bfloat16 g_tk_hi [4096LL*512];
__device__ __nv_bfloat16 g_tkT_hi[4096LL*512];
__device__ __nv_bfloat16 g_at_hi [8LL*2048*512], g_at_lo [8LL*2048*512];
__device__ __nv_bfloat16 g_ctx_hi[8LL*2048*512];
__device__ __nv_bfloat16 g_gh_hi [8LL*2048*512];
__device__ __nv_bfloat16 g_wT_hi [9LL*512*512];
__device__ unsigned int g_mask_byte_mode;

__device__ __forceinline__ uint32_t smem_u32(const void* p) {
    uint32_t a;
    asm("{ .reg .u64 t; cvta.to.shared.u64 t, %1; cvt.u32.u64 %0, t; }" : "=r"(a) : "l"(p));
    return a;
}
__device__ __forceinline__ void cp16(uint32_t dst, const void* src) {
    asm volatile("cp.async.cg.shared.global [%0], [%1], 16;" :: "r"(dst), "l"(src));
}
__device__ __forceinline__ void mma_bf16(float* d, const uint32_t* a, const uint32_t* b) {
    asm volatile("mma.sync.aligned.m16n8k16.row.col.f32.bf16.bf16.f32 "
        "{%0,%1,%2,%3}, {%4,%5,%6,%7}, {%8,%9}, {%0,%1,%2,%3};"
        : "+f"(d[0]), "+f"(d[1]), "+f"(d[2]), "+f"(d[3])
        : "r"(a[0]), "r"(a[1]), "r"(a[2]), "r"(a[3]), "r"(b[0]), "r"(b[1]));
}
__device__ __forceinline__ void ldm_x4(uint32_t& r0, uint32_t& r1, uint32_t& r2, uint32_t& r3,
                                       uint32_t addr) {
    asm volatile("ldmatrix.sync.aligned.m8n8.x4.shared.b16 {%0,%1,%2,%3}, [%4];"
        : "=r"(r0), "=r"(r1), "=r"(r2), "=r"(r3) : "r"(addr));
}
__device__ __forceinline__ float eluf(float x) { return x > 0.f ? x : expm1f(x); }

// smem: 4 buffers (2 pairs); each = A tile (64 rows x 144B) + B tile (128 x 144B)
// row layout: 64 bf16 (one K=64 chunk) in bytes [0,128), pad [128,144)
#define ROWB   144
#define MT     64
#define ATILEB (MT * ROWB)           // 9216
#define BTILEB (128 * ROWB)          // 18432
#define BUFB   (ATILEB + BTILEB)     // 27648
#define NSTAGE 4
#define SMEM_BYTES (NSTAGE * BUFB)   // 110592 -> 2 CTAs/SM

#define LDM_SETUP \
    const int lrow = lane & 7, lsel = lane >> 3; \
    const int a_dm = (lsel & 1) << 3, a_dk = (lsel >> 1) << 3; \
    const int b_dn = (lsel >> 1) << 3, b_dk = (lsel & 1) << 3;

// ==================================================================
// Single-bf16 GEMM via mma.sync + ldmatrix; K-chunk = 64; pair-loop
// with ONE barrier per 128 K. fp32 accumulate.
// ==================================================================
template<int ACT, bool TWO, bool OUTB>
__global__ void __launch_bounds__(256, 2) gemm_mma(
    const __nv_bfloat16* __restrict__ Ahi,
    const __nv_bfloat16* __restrict__ Bhi,
    const __nv_bfloat16* __restrict__ A2hi,
    const __nv_bfloat16* __restrict__ B2hi,
    float* __restrict__ Cf, __nv_bfloat16* __restrict__ Chi,
    const float* __restrict__ bias,
    int M, int K, long long sA, long long sB, long long sC, int ldc)
{
    constexpr int FM = 2;
    extern __shared__ char sm[];
    const uint32_t smb = smem_u32(sm);
    const int tid = threadIdx.x, wid = tid >> 5, lane = tid & 31;
    const int wm = wid >> 2, wn = wid & 3;
    const int m0 = blockIdx.y * MT, n0 = blockIdx.x * 128, z = blockIdx.z;

    const int kc  = K >> 6;                         // chunks of 64 k
    const int nch = TWO ? 2 * kc : kc;
    const int np  = nch >> 1;

    float d[FM][4][4];
    #pragma unroll
    for (int f = 0; f < FM; f++)
        #pragma unroll
        for (int g = 0; g < 4; g++)
            #pragma unroll
            for (int e = 0; e < 4; e++) d[f][g][e] = 0.f;

    auto load_chunk = [&](int c) {
        const bool sec = TWO && (c >= kc);
        const int koff = (sec ? c - kc : c) << 6;
        const int buf = c & 3;
        const uint32_t smA = smb + buf * BUFB;
        const uint32_t smB = smA + ATILEB;
        {   // A: 64 rows x 8 segs of 16B
            const __nv_bfloat16* pH = (sec ? A2hi : Ahi) + (long long)z * sA;
            #pragma unroll
            for (int i = 0; i < 2; i++) {
                const int idx = tid + 256 * i;
                const int r = idx >> 3, s = idx & 7;
                cp16(smA + r * ROWB + s * 16,
                     pH + (long long)(m0 + r) * K + koff + s * 8);
            }
        }
        {   // B: 128 rows x 8 segs
            const __nv_bfloat16* pH = (sec ? B2hi : Bhi) + (long long)z * sB;
            #pragma unroll
            for (int i = 0; i < 4; i++) {
                const int idx = tid + 256 * i;
                const int r = idx >> 3, s = idx & 7;
                cp16(smB + r * ROWB + s * 16,
                     pH + (long long)(n0 + r) * K + koff + s * 8);
            }
        }
    };
    auto load_pair = [&](int p) {
        load_chunk(2 * p);
        load_chunk(2 * p + 1);
        asm volatile("cp.async.commit_group;");
    };

    LDM_SETUP

    auto compute_chunk = [&](int c) {
        const uint32_t a_base = smb + (c & 3) * BUFB;
        const uint32_t b_base = a_base + ATILEB;
        #pragma unroll
        for (int st = 0; st < 4; ++st) {
            const int k = st * 16;
            uint32_t a[FM][4], b[4][2];
            #pragma unroll
            for (int f = 0; f < FM; f++) {
                const uint32_t addr = a_base
                    + (uint32_t)((wm * 32 + f * 16 + a_dm + lrow) * ROWB + (k + a_dk) * 2);
                ldm_x4(a[f][0], a[f][1], a[f][2], a[f][3], addr);
            }
            #pragma unroll
            for (int gp = 0; gp < 2; gp++) {
                const uint32_t addr = b_base
                    + (uint32_t)((wn * 32 + gp * 16 + b_dn + lrow) * ROWB + (k + b_dk) * 2);
                ldm_x4(b[2*gp][0], b[2*gp][1], b[2*gp+1][0], b[2*gp+1][1], addr);
            }
            #pragma unroll
            for (int f = 0; f < FM; f++)
                #pragma unroll
                for (int g = 0; g < 4; g++)
                    mma_bf16(d[f][g], a[f], b[g]);
        }
    };

    load_pair(0);
    for (int p = 0; p < np; ++p) {
        asm volatile("cp.async.wait_group 0;");
        __syncthreads();
        if (p + 1 < np) load_pair(p + 1);
        compute_chunk(2 * p);
        compute_chunk(2 * p + 1);
    }

    const int qr = lane >> 2, qc = 2 * (lane & 3);
    #pragma unroll
    for (int f = 0; f < FM; f++) {
        #pragma unroll
        for (int g = 0; g < 4; g++) {
            const int cc = n0 + wn * 32 + g * 8 + qc;
            float bx = 0.f, by = 0.f;
            if (bias) { bx = bias[cc]; by = bias[cc + 1]; }
            #pragma unroll
            for (int h = 0; h < 2; h++) {
                const int row = m0 + wm * 32 + f * 16 + qr + h * 8;
                if (row >= M) continue;
                float v0 = d[f][g][2 * h]     + bx;
                float v1 = d[f][g][2 * h + 1] + by;
                if (ACT == 1) { v0 = eluf(v0); v1 = eluf(v1); }
                else if (ACT == 2) { v0 = tanhf(v0); v1 = tanhf(v1); }
                const long long o = (long long)z * sC + (long long)row * ldc + cc;
                if constexpr (!OUTB) {
                    *reinterpret_cast<float2*>(Cf + o) = make_float2(v0, v1);
                } else {
                    *reinterpret_cast<__nv_bfloat162*>(Chi + o) = __floats2bfloat162_rn(v0, v1);
                }
            }
        }
    }
}

// ==================================================================
// Prologue uber-GEMM (fp32 A with gather -> bf16): K-chunk 64, pair loop.
// Grid 320 CTAs: [0,32) dh, [32,64) headq, [64,320) tk
// ==================================================================
__global__ void __launch_bounds__(256, 2) gemm_pro(
    const float* __restrict__ dec_out, const float* __restrict__ emb,
    const int* __restrict__ head, const int* __restrict__ tail,
    const __nv_bfloat16* __restrict__ wT_hi,
    float* __restrict__ dh, float* __restrict__ headq,
    __nv_bfloat16* __restrict__ tk_hi,
    const float* __restrict__ b_tk)
{
    constexpr int FM = 2;
    extern __shared__ char sm[];
    const uint32_t smb = smem_u32(sm);
    const int tid = threadIdx.x, wid = tid >> 5, lane = tid & 31;
    const int wm = wid >> 2, wn = wid & 3;

    const int bid = blockIdx.x;
    const float* Af; const int* gidx; long long boff; float* Cf; int ldc;
    int m0, n0; int outb, act; const float* bias;
    if (bid < 32) {
        Af = dec_out; gidx = nullptr; boff = 0;
        Cf = dh; ldc = 1024; outb = 0; act = 0; bias = nullptr;
        n0 = (bid & 7) * 128; m0 = (bid >> 3) * MT;
    } else if (bid < 64) {
        const int t = bid - 32;
        Af = emb; gidx = head; boff = 2LL * 512 * 512;
        Cf = headq; ldc = 512; outb = 0; act = 0; bias = nullptr;
        n0 = (t & 3) * 128; m0 = (t >> 2) * MT;
    } else {
        const int t = bid - 64;
        Af = emb; gidx = tail; boff = 3LL * 512 * 512;
        Cf = nullptr; ldc = 512; outb = 1; act = 1; bias = b_tk;
        n0 = (t & 3) * 128; m0 = (t >> 2) * MT;
    }
    const __nv_bfloat16* Bhi = wT_hi + boff;
    const int K = 512, np = 4;

    float d[FM][4][4];
    #pragma unroll
    for (int f = 0; f < FM; f++)
        #pragma unroll
        for (int g = 0; g < 4; g++)
            #pragma unroll
            for (int e = 0; e < 4; e++) d[f][g][e] = 0.f;

    auto load_chunk = [&](int c) {
        const int koff = c << 6;
        const int buf = c & 3;
        const uint32_t smA = smb + buf * BUFB;
        const uint32_t smB = smA + ATILEB;
        char* smAp = sm + buf * BUFB;
        // A: 64 rows x 16 float4 -> bf16
        #pragma unroll
        for (int i = 0; i < 4; i++) {
            const int idx = tid + 256 * i;          // 0..1023
            const int r = idx >> 4, s = idx & 15;
            const int gm = m0 + r;
            const long long row = gidx ? (long long)gidx[gm] : (long long)gm;
            float4 v = *reinterpret_cast<const float4*>(Af + row * K + koff + s * 4);
            uint2 uh;
            __nv_bfloat162 h01 = __floats2bfloat162_rn(v.x, v.y);
            __nv_bfloat162 h23 = __floats2bfloat162_rn(v.z, v.w);
            uh.x = *(uint32_t*)&h01; uh.y = *(uint32_t*)&h23;
            *reinterpret_cast<uint2*>(smAp + r * ROWB + s * 8) = uh;
        }
        // B: 128 rows x 8 segs
        #pragma unroll
        for (int i = 0; i < 4; i++) {
            const int idx = tid + 256 * i;
            const int r = idx >> 3, s = idx & 7;
            cp16(smB + r * ROWB + s * 16,
                 Bhi + (long long)(n0 + r) * K + koff + s * 8);
        }
    };
    auto load_pair = [&](int p) {
        load_chunk(2 * p);
        load_chunk(2 * p + 1);
        asm volatile("cp.async.commit_group;");
    };

    LDM_SETUP

    auto compute_chunk = [&](int c) {
        const uint32_t a_base = smb + (c & 3) * BUFB;
        const uint32_t b_base = a_base + ATILEB;
        #pragma unroll
        for (int st = 0; st < 4; ++st) {
            const int k = st * 16;
            uint32_t a[FM][4], b[4][2];
            #pragma unroll
            for (int f = 0; f < FM; f++) {
                const uint32_t addr = a_base
                    + (uint32_t)((wm * 32 + f * 16 + a_dm + lrow) * ROWB + (k + a_dk) * 2);
                ldm_x4(a[f][0], a[f][1], a[f][2], a[f][3], addr);
            }
            #pragma unroll
            for (int gp = 0; gp < 2; gp++) {
                const uint32_t addr = b_base
                    + (uint32_t)((wn * 32 + gp * 16 + b_dn + lrow) * ROWB + (k + b_dk) * 2);
                ldm_x4(b[2*gp][0], b[2*gp][1], b[2*gp+1][0], b[2*gp+1][1], addr);
            }
            #pragma unroll
            for (int f = 0; f < FM; f++)
                #pragma unroll
                for (int g = 0; g < 4; g++)
                    mma_bf16(d[f][g], a[f], b[g]);
        }
    };

    load_pair(0);
    for (int p = 0; p < np; ++p) {
        asm volatile("cp.async.wait_group 0;");
        __syncthreads();
        if (p + 1 < np) load_pair(p + 1);
        compute_chunk(2 * p);
        compute_chunk(2 * p + 1);
    }

    const int qr = lane >> 2, qc = 2 * (lane & 3);
    #pragma unroll
    for (int f = 0; f < FM; f++) {
        #pragma unroll
        for (int g = 0; g < 4; g++) {
            const int cc = n0 + wn * 32 + g * 8 + qc;
            float bx = 0.f, by = 0.f;
            if (bias) { bx = bias[cc]; by = bias[cc + 1]; }
            #pragma unroll
            for (int h = 0; h < 2; h++) {
                const int row = m0 + wm * 32 + f * 16 + qr + h * 8;
                float v0 = d[f][g][2 * h]     + bx;
                float v1 = d[f][g][2 * h + 1] + by;
                if (act == 1) { v0 = eluf(v0); v1 = eluf(v1); }
                if (!outb) {
                    *reinterpret_cast<float2*>(Cf + (long long)row * ldc + cc) = make_float2(v0, v1);
                } else {
                    *reinterpret_cast<__nv_bfloat162*>(tk_hi + (long long)row * 512 + cc) =
                        __floats2bfloat162_rn(v0, v1);
                }
            }
        }
    }
}

// ---------------- weights: transpose 512x512 fp32 -> bf16 ----------------
struct WPtrs { const float* s[9]; };
__global__ void prep_weights(WPtrs wp, __nv_bfloat16* __restrict__ dhi)
{
    __shared__ float t[32][33];
    const int mtx = blockIdx.z;
    const float* src = wp.s[mtx];
    __nv_bfloat16* oh = dhi + (long long)mtx * 512 * 512;
    const int tx = threadIdx.x, ty = threadIdx.y;
    const int bx = blockIdx.x * 32, by = blockIdx.y * 32;
    #pragma unroll
    for (int i = 0; i < 32; i += 8)
        t[ty + i][tx] = src[(long long)(by + ty + i) * 512 + bx + tx];
    __syncthreads();
    #pragma unroll
    for (int i = 0; i < 32; i += 8)
        oh[(long long)(bx + ty + i) * 512 + by + tx] = __float2bfloat16(t[tx][ty + i]);
}

// ---------------- history small GEMM ----------------
__global__ void hist_small(const float* __restrict__ hist,
                           const __nv_bfloat16* __restrict__ w7h,
                           const __nv_bfloat16* __restrict__ w8h,
                           float* __restrict__ out)
{
    const int wid = threadIdx.x >> 5, lane = threadIdx.x & 31;
    const int c = blockIdx.x * 8 + wid;
    const __nv_bfloat16* rh = (c < 512) ? w7h + (long long)c * 512 : w8h + (long long)(c - 512) * 512;
    float acc[8] = {0.f,0.f,0.f,0.f,0.f,0.f,0.f,0.f};
    #pragma unroll 4
    for (int i = 0; i < 16; i++) {
        const int k = lane + i * 32;
        const float w = __bfloat162float(rh[k]);
        #pragma unroll
        for (int r = 0; r < 8; r++) acc[r] = fmaf(hist[r * 512 + k], w, acc[r]);
    }
    #pragma unroll
    for (int r = 0; r < 8; r++) {
        float v = acc[r];
        #pragma unroll
        for (int o = 16; o; o >>= 1) v += __shfl_xor_sync(0xffffffffu, v, o);
        if (lane == 0) out[r * 1024 + c] = v;
    }
}

// ---------------- tk transpose per batch (bf16) ----------------
__global__ void transpose_tk(const __nv_bfloat16* __restrict__ shi,
                             __nv_bfloat16* __restrict__ dhi)
{
    __shared__ __nv_bfloat16 th[32][33];
    const long long zb = (long long)blockIdx.z * 512 * 512;
    const int tx = threadIdx.x, ty = threadIdx.y;
    const int bx = blockIdx.x * 32, by = blockIdx.y * 32;
    #pragma unroll
    for (int i = 0; i < 32; i += 8)
        th[ty + i][tx] = shi[zb + (long long)(by + ty + i) * 512 + bx + tx];
    __syncthreads();
    #pragma unroll
    for (int i = 0; i < 32; i += 8)
        dhi[zb + (long long)(bx + ty + i) * 512 + by + tx] = th[tx][ty + i];
}

// ---------------- mask dtype detector ----------------
__global__ void detect_mask_kernel(const unsigned int* __restrict__ adj, int nwords)
{
    __shared__ unsigned int s;
    if (threadIdx.x == 0) s = 0u;
    __syncthreads();
    unsigned int local = 0u;
    for (int i = threadIdx.x; i < nwords; i += blockDim.x)
        local |= (adj[i] > 1u) ? 1u : 0u;
    if (local) atomicOr(&s, 1u);
    __syncthreads();
    if (threadIdx.x == 0) g_mask_byte_mode = s;
}

// ---------------- tq = elu(decp + histp + headq + b_tq) -> bf16 ----------------
__global__ void build_tq(const float4* __restrict__ dh, const float4* __restrict__ hh,
                         const float4* __restrict__ headq, const float4* __restrict__ btq,
                         __nv_bfloat162* __restrict__ thi)
{
    const int i = blockIdx.x * 256 + threadIdx.x;
    const int d  = i & 127;
    const int h  = (i >> 7) & 63;
    const int bs = i >> 13;
    const int b  = bs >> 5;
    float4 a = dh[bs * 256 + d];
    float4 c = hh[b * 256 + d];
    float4 e = headq[(b * 64 + h) * 128 + d];
    float4 g = btq[d];
    float4 r;
    r.x = eluf(a.x + c.x + e.x + g.x);
    r.y = eluf(a.y + c.y + e.y + g.y);
    r.z = eluf(a.z + c.z + e.z + g.z);
    r.w = eluf(a.w + c.w + e.w + g.w);
    thi[2 * i]     = __floats2bfloat162_rn(r.x, r.y);
    thi[2 * i + 1] = __floats2bfloat162_rn(r.z, r.w);
}

// ---------------- hq = elu(hqd + hqh + b_hq) (cols 512:1024) ----------------
__global__ void build_hq(const float4* __restrict__ dh, const float4* __restrict__ hh,
                         const float4* __restrict__ bhq, float4* __restrict__ hq)
{
    const int i = blockIdx.x * 256 + threadIdx.x;
    const int d  = i & 127;
    const int bs = i >> 7;
    const int b  = bs >> 5;
    float4 a = dh[bs * 256 + 128 + d];
    float4 c = hh[b * 256 + 128 + d];
    float4 g = bhq[d];
    float4 r;
    r.x = eluf(a.x + c.x + g.x);
    r.y = eluf(a.y + c.y + g.y);
    r.z = eluf(a.z + c.z + g.z);
    r.w = eluf(a.w + c.w + g.w);
    hq[i] = r;
}

// ---------------- masked softmax (bf16 hi/lo out) ----------------
__global__ void masked_softmax(const float* __restrict__ attn,
                               __nv_bfloat16* __restrict__ ahi, __nv_bfloat16* __restrict__ alo,
                               const void* __restrict__ adj, const void* __restrict__ dup)
{
    const int q = blockIdx.x;
    const int b = blockIdx.y;
    const int s = q >> 6, h = q & 63;
    const long long ro = ((long long)(b * 2048 + q)) * 512;
    const float* row = attn + ro;
    const long long aoff = ((long long)(b * 64 + h)) * 512;
    const long long doff = ((long long)(b * 32 + s)) * 512;

    const unsigned int byte_mode = g_mask_byte_mode;
    const unsigned char* am8 = (const unsigned char*)adj + aoff;
    const unsigned char* dm8 = (const unsigned char*)dup + doff;
    const int* am32 = (const int*)adj + aoff;
    const int* dm32 = (const int*)dup + doff;

    const int tid = threadIdx.x;
    float v[2]; int mk[2];
    float lmax = -FLT_MAX;
    #pragma unroll
    for (int j = 0; j < 2; j++) {
        const int t = tid + j * 256;
        if (byte_mode) mk[j] = am8[t]  && !dm8[t];
        else           mk[j] = am32[t] && !dm32[t];
        v[j] = row[t];
        if (mk[j]) lmax = fmaxf(lmax, v[j]);
    }
    __shared__ float smax[8], ssum[8];
    #pragma unroll
    for (int o = 16; o; o >>= 1) lmax = fmaxf(lmax, __shfl_xor_sync(0xffffffffu, lmax, o));
    if ((tid & 31) == 0) smax[tid >> 5] = lmax;
    __syncthreads();
    float bmax = -FLT_MAX;
    #pragma unroll
    for (int w = 0; w < 8; w++) bmax = fmaxf(bmax, smax[w]);

    float e[2], lsum = 0.f;
    #pragma unroll
    for (int j = 0; j < 2; j++) { e[j] = mk[j] ? expf(v[j] - bmax) : 0.f; lsum += e[j]; }
    #pragma unroll
    for (int o = 16; o; o >>= 1) lsum += __shfl_xor_sync(0xffffffffu, lsum, o);
    if ((tid & 31) == 0) ssum[tid >> 5] = lsum;
    __syncthreads();
    float bsum = 0.f;
    #pragma unroll
    for (int w = 0; w < 8; w++) bsum += ssum[w];

    const float inv = 1.f / bsum;
    #pragma unroll
    for (int j = 0; j < 2; j++) {
        const int t = tid + j * 256;
        const float p = e[j] * inv;
        const __nv_bfloat16 hb = __float2bfloat16(p);
        ahi[ro + t] = hb;
        alo[ro + t] = __float2bfloat16(p - __bfloat162float(hb));
    }
}

// ---------------- final: head attention + prob + log (attn from bf16 hi/lo) ----------------
__global__ void final_kernel(const float* __restrict__ hq, const float* __restrict__ hk,
                             const __nv_bfloat16* __restrict__ athi,
                             const __nv_bfloat16* __restrict__ atlo,
                             const int* __restrict__ head, float* __restrict__ out)
{
    const int n = blockIdx.x;
    const int b = n >> 5;
    const int tid = threadIdx.x;

    __shared__ float shq[512];
    __shared__ float sc[64];
    __shared__ float sw[64];
    __shared__ int   s_len;

    if (tid == 0) s_len = 0;
    shq[tid]       = hq[(long long)n * 512 + tid];
    shq[tid + 256] = hq[(long long)n * 512 + 256 + tid];
    __syncthreads();
    if (tid < 64) { if (head[b * 64 + tid] != 0) atomicAdd(&s_len, 1); }
    __syncthreads();

    const int w = tid >> 5, lane = tid & 31;
    for (int k = w; k < 64; k += 8) {
        const float* hkr = hk + ((long long)n * 64 + k) * 512;
        float sacc = 0.f;
        for (int d = lane; d < 512; d += 32) sacc = fmaf(shq[d], hkr[d], sacc);
        #pragma unroll
        for (int o = 16; o; o >>= 1) sacc += __shfl_xor_sync(0xffffffffu, sacc, o);
        if (lane == 0) sc[k] = sacc;
    }
    __syncthreads();

    if (tid == 0) {
        const int len = s_len;
        float mx = -FLT_MAX;
        for (int k = 0; k < len; k++) mx = fmaxf(mx, sc[k]);
        float sum = 0.f;
        for (int k = 0; k < 64; k++) {
            float e = (k < len) ? expf(sc[k] - mx) : 0.f;
            sw[k] = e; sum += e;
        }
        float inv = 1.f / sum;
        for (int k = 0; k < 64; k++) sw[k] *= inv;
    }
    __syncthreads();

    const long long base = (long long)n * 64 * 512;
    for (int t = tid; t < 512; t += 256) {
        float p = 0.f;
        #pragma unroll 8
        for (int k = 0; k < 64; k++) {
            const long long o = base + k * 512 + t;
            const float a = __bfloat162float(athi[o]) + __bfloat162float(atlo[o]);
            p = fmaf(sw[k], a, p);
        }
        out[(long long)n * 512 + t] = logf(p + 1e-20f);
    }
}

// ---------------- launch ----------------
extern "C" void kernel_launch(void* const* d_in, const int* in_sizes, int n_in,
                              void* d_out, int out_size)
{
    const float* dec_out = (const float*)d_in[0];
    const float* history = (const float*)d_in[1];
    const int*   head    = (const int*)  d_in[2];
    const int*   tail    = (const int*)  d_in[3];
    const void*  adj     = d_in[4];
    const void*  dup     = d_in[5];
    const float* emb     = (const float*)d_in[6];
    const float* W_tq    = (const float*)d_in[7];
    const float* b_tq    = (const float*)d_in[8];
    const float* W_tk    = (const float*)d_in[9];
    const float* b_tk    = (const float*)d_in[10];
    const float* W_tout  = (const float*)d_in[11];
    const float* W_hq    = (const float*)d_in[12];
    const float* b_hq    = (const float*)d_in[13];
    const float* W_hk    = (const float*)d_in[14];
    const float* b_hk    = (const float*)d_in[15];

    float *dh, *hh, *headq, *attn, *hk, *hq;
    __nv_bfloat16 *tq_hi, *tk_hi, *tkT_hi, *at_hi, *at_lo, *ctx_hi, *gh_hi, *wT_hi;
    cudaGetSymbolAddress((void**)&dh,     g_dh);
    cudaGetSymbolAddress((void**)&hh,     g_hh);
    cudaGetSymbolAddress((void**)&headq,  g_headq);
    cudaGetSymbolAddress((void**)&attn,   g_attn);
    cudaGetSymbolAddress((void**)&hk,     g_hk);
    cudaGetSymbolAddress((void**)&hq,     g_hq);
    cudaGetSymbolAddress((void**)&tq_hi,  g_tq_hi);
    cudaGetSymbolAddress((void**)&tk_hi,  g_tk_hi);
    cudaGetSymbolAddress((void**)&tkT_hi, g_tkT_hi);
    cudaGetSymbolAddress((void**)&at_hi,  g_at_hi);
    cudaGetSymbolAddress((void**)&at_lo,  g_at_lo);
    cudaGetSymbolAddress((void**)&ctx_hi, g_ctx_hi);
    cudaGetSymbolAddress((void**)&gh_hi,  g_gh_hi);
    cudaGetSymbolAddress((void**)&wT_hi,  g_wT_hi);

    cudaFuncSetAttribute(gemm_pro,                cudaFuncAttributeMaxDynamicSharedMemorySize, SMEM_BYTES);
    cudaFuncSetAttribute(gemm_mma<0,false,false>, cudaFuncAttributeMaxDynamicSharedMemorySize, SMEM_BYTES);
    cudaFuncSetAttribute(gemm_mma<0,false,true >, cudaFuncAttributeMaxDynamicSharedMemorySize, SMEM_BYTES);
    cudaFuncSetAttribute(gemm_mma<2,true ,true >, cudaFuncAttributeMaxDynamicSharedMemorySize, SMEM_BYTES);
    cudaFuncSetAttribute(gemm_mma<1,false,false>, cudaFuncAttributeMaxDynamicSharedMemorySize, SMEM_BYTES);

    // weight slots: 0 Wd, 1 Whq0 (merged N=1024), 2 We, 3 Wtk, 4 Wtout0, 5 Wtout1,
    //               6 Whk, 7 Wh, 8 Whq1
    WPtrs wp;
    wp.s[0] = W_tq;               wp.s[1] = W_hq;               wp.s[2] = W_tq + 1024LL*512;
    wp.s[3] = W_tk;               wp.s[4] = W_tout;             wp.s[5] = W_tout + 512LL*512;
    wp.s[6] = W_hk;               wp.s[7] = W_tq + 512LL*512;   wp.s[8] = W_hq + 512LL*512;
    #define WTH(i) (wT_hi + (long long)(i)*512*512)

    detect_mask_kernel<<<1, 256>>>((const unsigned int*)adj, 65536);
    prep_weights<<<dim3(16,16,9), dim3(32,8)>>>(wp, wT_hi);

    hist_small<<<128, 256>>>(history, WTH(7), WTH(8), hh);
    gemm_pro<<<320, 256, SMEM_BYTES>>>(dec_out, emb, head, tail, wT_hi,
                                       dh, headq, tk_hi, b_tk);
    transpose_tk<<<dim3(16,16,8), dim3(32,8)>>>(tk_hi, tkT_hi);
    build_tq<<<8192, 256>>>((const float4*)dh, (const float4*)hh,
                            (const float4*)headq, (const float4*)b_tq,
                            (__nv_bfloat162*)tq_hi);
    // scores[b] = tq[b] @ tk[b]^T
    gemm_mma<0,false,false><<<dim3(4,32,8), 256, SMEM_BYTES>>>(
        tq_hi, tk_hi, nullptr, nullptr,
        attn, nullptr, nullptr, 2048, 512,
        2048LL*512, 512LL*512, 2048LL*512, 512);
    masked_softmax<<<dim3(2048,8), 256>>>(attn, at_hi, at_lo, adj, dup);
    // ctx[b] = attn[b] @ tk[b]
    gemm_mma<0,false,true><<<dim3(4,32,8), 256, SMEM_BYTES>>>(
        at_hi, tkT_hi, nullptr, nullptr,
        nullptr, ctx_hi, nullptr, 2048, 512,
        2048LL*512, 512LL*512, 2048LL*512, 512);
    // ghid = tanh(ctx @ Wtout0 + tq @ Wtout1)
    gemm_mma<2,true,true><<<dim3(4,256,1), 256, SMEM_BYTES>>>(
        ctx_hi, WTH(4), tq_hi, WTH(5),
        nullptr, gh_hi, nullptr, 16384, 512, 0, 0, 0, 512);
    // hk = elu(ghid @ Whk + b_hk)
    gemm_mma<1,false,false><<<dim3(4,256,1), 256, SMEM_BYTES>>>(
        gh_hi, WTH(6), nullptr, nullptr,
        hk, nullptr, b_hk, 16384, 512, 0, 0, 0, 512);
    build_hq<<<128, 256>>>((const float4*)dh, (const float4*)hh,
                           (const float4*)b_hq, (float4*)hq);
    final_kernel<<<256, 256>>>(hq, hk, at_hi, at_lo, head, (float*)d_out);
}

// round 13
// speedup vs baseline: 1.7477x; 1.0061x over previous
#include <cuda_runtime.h>
#include <cuda_bf16.h>
#include <math.h>
#include <float.h>
#include <stdint.h>

// Problem dims: B=8, S=32, HN=64, TN=512, HID=EMB=512
// ---------------- scratch (device globals; no allocation) ----------------
__device__ float g_dh  [256 * 1024];            // [.,0:512)=decp  [.,512:1024)=hqd
__device__ float g_hh  [8   * 1024];            // [.,0:512)=histp [.,512:1024)=hqh
__device__ float g_headq[512  * 512];
__device__ float g_attn [8LL*2048*512];
__device__ float g_hk   [16384LL*512];
__device__ float g_hq   [256 * 512];
__device__ __nv_bfloat16 g_tq_hi [8LL*2048*512];
__device__ __nv_bfloat16 g_tk_hi [4096LL*512];
__device__ __nv_bfloat16 g_tkT_hi[4096LL*512];
__device__ __nv_bfloat16 g_at_hi [8LL*2048*512], g_at_lo [8LL*2048*512];
__device__ __nv_bfloat16 g_ctx_hi[8LL*2048*512];
__device__ __nv_bfloat16 g_gh_hi [8LL*2048*512];
__device__ __nv_bfloat16 g_wT_hi [9LL*512*512];
__device__ unsigned int g_mask_byte_mode;

__device__ __forceinline__ uint32_t smem_u32(const void* p) {
    uint32_t a;
    asm("{ .reg .u64 t; cvta.to.shared.u64 t, %1; cvt.u32.u64 %0, t; }" : "=r"(a) : "l"(p));
    return a;
}
__device__ __forceinline__ void cp16(uint32_t dst, const void* src) {
    asm volatile("cp.async.cg.shared.global [%0], [%1], 16;" :: "r"(dst), "l"(src));
}
__device__ __forceinline__ void mma_bf16(float* d, const uint32_t* a, const uint32_t* b) {
    asm volatile("mma.sync.aligned.m16n8k16.row.col.f32.bf16.bf16.f32 "
        "{%0,%1,%2,%3}, {%4,%5,%6,%7}, {%8,%9}, {%0,%1,%2,%3};"
        : "+f"(d[0]), "+f"(d[1]), "+f"(d[2]), "+f"(d[3])
        : "r"(a[0]), "r"(a[1]), "r"(a[2]), "r"(a[3]), "r"(b[0]), "r"(b[1]));
}
__device__ __forceinline__ void ldm_x4(uint32_t& r0, uint32_t& r1, uint32_t& r2, uint32_t& r3,
                                       uint32_t addr) {
    asm volatile("ldmatrix.sync.aligned.m8n8.x4.shared.b16 {%0,%1,%2,%3}, [%4];"
        : "=r"(r0), "=r"(r1), "=r"(r2), "=r"(r3) : "r"(addr));
}
__device__ __forceinline__ float eluf(float x) { return x > 0.f ? x : expm1f(x); }

// smem: 3 buffers; each = A tile (128 rows x 144B) + B tile (128 x 144B)
// row layout: 64 bf16 (one K=64 chunk) in bytes [0,128), pad [128,144)
#define ROWB   144
#define MT     128
#define ATILEB (MT * ROWB)           // 18432
#define BTILEB (128 * ROWB)          // 18432
#define BUFB   (ATILEB + BTILEB)     // 36864
#define NSTAGE 3
#define SMEM_BYTES (NSTAGE * BUFB)   // 110592 -> 2 CTAs/SM

#define LDM_SETUP \
    const int lrow = lane & 7, lsel = lane >> 3; \
    const int a_dm = (lsel & 1) << 3, a_dk = (lsel >> 1) << 3; \
    const int b_dn = (lsel >> 1) << 3, b_dk = (lsel & 1) << 3;

// ==================================================================
// Single-bf16 GEMM via mma.sync + ldmatrix; MT=128; K-chunk = 64;
// 3-stage chunk loop (wait_group 1). fp32 accumulate.
// ==================================================================
template<int ACT, bool TWO, bool OUTB>
__global__ void __launch_bounds__(256, 2) gemm_mma(
    const __nv_bfloat16* __restrict__ Ahi,
    const __nv_bfloat16* __restrict__ Bhi,
    const __nv_bfloat16* __restrict__ A2hi,
    const __nv_bfloat16* __restrict__ B2hi,
    float* __restrict__ Cf, __nv_bfloat16* __restrict__ Chi,
    const float* __restrict__ bias,
    int M, int K, long long sA, long long sB, long long sC, int ldc)
{
    constexpr int FM = 4;
    extern __shared__ char sm[];
    const uint32_t smb = smem_u32(sm);
    const int tid = threadIdx.x, wid = tid >> 5, lane = tid & 31;
    const int wm = wid >> 2, wn = wid & 3;
    const int m0 = blockIdx.y * MT, n0 = blockIdx.x * 128, z = blockIdx.z;

    const int kc  = K >> 6;                         // chunks of 64 k
    const int nch = TWO ? 2 * kc : kc;

    float d[FM][4][4];
    #pragma unroll
    for (int f = 0; f < FM; f++)
        #pragma unroll
        for (int g = 0; g < 4; g++)
            #pragma unroll
            for (int e = 0; e < 4; e++) d[f][g][e] = 0.f;

    auto load_chunk = [&](int c) {
        const bool sec = TWO && (c >= kc);
        const int koff = (sec ? c - kc : c) << 6;
        const int buf = c % NSTAGE;
        const uint32_t smA = smb + buf * BUFB;
        const uint32_t smB = smA + ATILEB;
        {   // A: 128 rows x 8 segs of 16B
            const __nv_bfloat16* pH = (sec ? A2hi : Ahi) + (long long)z * sA;
            #pragma unroll
            for (int i = 0; i < 4; i++) {
                const int idx = tid + 256 * i;
                const int r = idx >> 3, s = idx & 7;
                cp16(smA + r * ROWB + s * 16,
                     pH + (long long)(m0 + r) * K + koff + s * 8);
            }
        }
        {   // B: 128 rows x 8 segs
            const __nv_bfloat16* pH = (sec ? B2hi : Bhi) + (long long)z * sB;
            #pragma unroll
            for (int i = 0; i < 4; i++) {
                const int idx = tid + 256 * i;
                const int r = idx >> 3, s = idx & 7;
                cp16(smB + r * ROWB + s * 16,
                     pH + (long long)(n0 + r) * K + koff + s * 8);
            }
        }
        asm volatile("cp.async.commit_group;");
    };

    LDM_SETUP

    auto compute_chunk = [&](int c) {
        const uint32_t a_base = smb + (c % NSTAGE) * BUFB;
        const uint32_t b_base = a_base + ATILEB;
        #pragma unroll
        for (int st = 0; st < 4; ++st) {
            const int k = st * 16;
            uint32_t a[FM][4], b[4][2];
            #pragma unroll
            for (int f = 0; f < FM; f++) {
                const uint32_t addr = a_base
                    + (uint32_t)((wm * 64 + f * 16 + a_dm + lrow) * ROWB + (k + a_dk) * 2);
                ldm_x4(a[f][0], a[f][1], a[f][2], a[f][3], addr);
            }
            #pragma unroll
            for (int gp = 0; gp < 2; gp++) {
                const uint32_t addr = b_base
                    + (uint32_t)((wn * 32 + gp * 16 + b_dn + lrow) * ROWB + (k + b_dk) * 2);
                ldm_x4(b[2*gp][0], b[2*gp][1], b[2*gp+1][0], b[2*gp+1][1], addr);
            }
            #pragma unroll
            for (int f = 0; f < FM; f++)
                #pragma unroll
                for (int g = 0; g < 4; g++)
                    mma_bf16(d[f][g], a[f], b[g]);
        }
    };

    load_chunk(0);
    if (nch > 1) load_chunk(1);
    for (int c = 0; c < nch; ++c) {
        if (c + 1 < nch) asm volatile("cp.async.wait_group 1;");
        else             asm volatile("cp.async.wait_group 0;");
        __syncthreads();
        if (c + 2 < nch) load_chunk(c + 2);
        compute_chunk(c);
    }

    const int qr = lane >> 2, qc = 2 * (lane & 3);
    #pragma unroll
    for (int f = 0; f < FM; f++) {
        #pragma unroll
        for (int g = 0; g < 4; g++) {
            const int cc = n0 + wn * 32 + g * 8 + qc;
            float bx = 0.f, by = 0.f;
            if (bias) { bx = bias[cc]; by = bias[cc + 1]; }
            #pragma unroll
            for (int h = 0; h < 2; h++) {
                const int row = m0 + wm * 64 + f * 16 + qr + h * 8;
                if (row >= M) continue;
                float v0 = d[f][g][2 * h]     + bx;
                float v1 = d[f][g][2 * h + 1] + by;
                if (ACT == 1) { v0 = eluf(v0); v1 = eluf(v1); }
                else if (ACT == 2) { v0 = tanhf(v0); v1 = tanhf(v1); }
                const long long o = (long long)z * sC + (long long)row * ldc + cc;
                if constexpr (!OUTB) {
                    *reinterpret_cast<float2*>(Cf + o) = make_float2(v0, v1);
                } else {
                    *reinterpret_cast<__nv_bfloat162*>(Chi + o) = __floats2bfloat162_rn(v0, v1);
                }
            }
        }
    }
}

// ==================================================================
// Prologue uber-GEMM (fp32 A with gather -> bf16), MT=128:
// Grid 160 CTAs: [0,16) dh, [16,32) headq, [32,160) tk
// ==================================================================
__global__ void __launch_bounds__(256, 2) gemm_pro(
    const float* __restrict__ dec_out, const float* __restrict__ emb,
    const int* __restrict__ head, const int* __restrict__ tail,
    const __nv_bfloat16* __restrict__ wT_hi,
    float* __restrict__ dh, float* __restrict__ headq,
    __nv_bfloat16* __restrict__ tk_hi,
    const float* __restrict__ b_tk)
{
    constexpr int FM = 4;
    extern __shared__ char sm[];
    const uint32_t smb = smem_u32(sm);
    const int tid = threadIdx.x, wid = tid >> 5, lane = tid & 31;
    const int wm = wid >> 2, wn = wid & 3;

    const int bid = blockIdx.x;
    const float* Af; const int* gidx; long long boff; float* Cf; int ldc;
    int m0, n0; int outb, act; const float* bias;
    if (bid < 16) {            // dh: 8 n x 2 m
        Af = dec_out; gidx = nullptr; boff = 0;
        Cf = dh; ldc = 1024; outb = 0; act = 0; bias = nullptr;
        n0 = (bid & 7) * 128; m0 = (bid >> 3) * MT;
    } else if (bid < 32) {     // headq: 4 n x 4 m
        const int t = bid - 16;
        Af = emb; gidx = head; boff = 2LL * 512 * 512;
        Cf = headq; ldc = 512; outb = 0; act = 0; bias = nullptr;
        n0 = (t & 3) * 128; m0 = (t >> 2) * MT;
    } else {                   // tk: 4 n x 32 m
        const int t = bid - 32;
        Af = emb; gidx = tail; boff = 3LL * 512 * 512;
        Cf = nullptr; ldc = 512; outb = 1; act = 1; bias = b_tk;
        n0 = (t & 3) * 128; m0 = (t >> 2) * MT;
    }
    const __nv_bfloat16* Bhi = wT_hi + boff;
    const int K = 512, nch = 8;

    float d[FM][4][4];
    #pragma unroll
    for (int f = 0; f < FM; f++)
        #pragma unroll
        for (int g = 0; g < 4; g++)
            #pragma unroll
            for (int e = 0; e < 4; e++) d[f][g][e] = 0.f;

    auto load_chunk = [&](int c) {
        const int koff = c << 6;
        const int buf = c % NSTAGE;
        const uint32_t smA = smb + buf * BUFB;
        const uint32_t smB = smA + ATILEB;
        char* smAp = sm + buf * BUFB;
        // A: 128 rows x 16 float4 -> bf16
        #pragma unroll
        for (int i = 0; i < 8; i++) {
            const int idx = tid + 256 * i;          // 0..2047
            const int r = idx >> 4, s = idx & 15;
            const int gm = m0 + r;
            const long long row = gidx ? (long long)gidx[gm] : (long long)gm;
            float4 v = *reinterpret_cast<const float4*>(Af + row * K + koff + s * 4);
            uint2 uh;
            __nv_bfloat162 h01 = __floats2bfloat162_rn(v.x, v.y);
            __nv_bfloat162 h23 = __floats2bfloat162_rn(v.z, v.w);
            uh.x = *(uint32_t*)&h01; uh.y = *(uint32_t*)&h23;
            *reinterpret_cast<uint2*>(smAp + r * ROWB + s * 8) = uh;
        }
        // B: 128 rows x 8 segs
        #pragma unroll
        for (int i = 0; i < 4; i++) {
            const int idx = tid + 256 * i;
            const int r = idx >> 3, s = idx & 7;
            cp16(smB + r * ROWB + s * 16,
                 Bhi + (long long)(n0 + r) * K + koff + s * 8);
        }
        asm volatile("cp.async.commit_group;");
    };

    LDM_SETUP

    auto compute_chunk = [&](int c) {
        const uint32_t a_base = smb + (c % NSTAGE) * BUFB;
        const uint32_t b_base = a_base + ATILEB;
        #pragma unroll
        for (int st = 0; st < 4; ++st) {
            const int k = st * 16;
            uint32_t a[FM][4], b[4][2];
            #pragma unroll
            for (int f = 0; f < FM; f++) {
                const uint32_t addr = a_base
                    + (uint32_t)((wm * 64 + f * 16 + a_dm + lrow) * ROWB + (k + a_dk) * 2);
                ldm_x4(a[f][0], a[f][1], a[f][2], a[f][3], addr);
            }
            #pragma unroll
            for (int gp = 0; gp < 2; gp++) {
                const uint32_t addr = b_base
                    + (uint32_t)((wn * 32 + gp * 16 + b_dn + lrow) * ROWB + (k + b_dk) * 2);
                ldm_x4(b[2*gp][0], b[2*gp][1], b[2*gp+1][0], b[2*gp+1][1], addr);
            }
            #pragma unroll
            for (int f = 0; f < FM; f++)
                #pragma unroll
                for (int g = 0; g < 4; g++)
                    mma_bf16(d[f][g], a[f], b[g]);
        }
    };

    load_chunk(0);
    load_chunk(1);
    for (int c = 0; c < nch; ++c) {
        if (c + 1 < nch) asm volatile("cp.async.wait_group 1;");
        else             asm volatile("cp.async.wait_group 0;");
        __syncthreads();
        if (c + 2 < nch) load_chunk(c + 2);
        compute_chunk(c);
    }

    const int qr = lane >> 2, qc = 2 * (lane & 3);
    #pragma unroll
    for (int f = 0; f < FM; f++) {
        #pragma unroll
        for (int g = 0; g < 4; g++) {
            const int cc = n0 + wn * 32 + g * 8 + qc;
            float bx = 0.f, by = 0.f;
            if (bias) { bx = bias[cc]; by = bias[cc + 1]; }
            #pragma unroll
            for (int h = 0; h < 2; h++) {
                const int row = m0 + wm * 64 + f * 16 + qr + h * 8;
                float v0 = d[f][g][2 * h]     + bx;
                float v1 = d[f][g][2 * h + 1] + by;
                if (act == 1) { v0 = eluf(v0); v1 = eluf(v1); }
                if (!outb) {
                    *reinterpret_cast<float2*>(Cf + (long long)row * ldc + cc) = make_float2(v0, v1);
                } else {
                    *reinterpret_cast<__nv_bfloat162*>(tk_hi + (long long)row * 512 + cc) =
                        __floats2bfloat162_rn(v0, v1);
                }
            }
        }
    }
}

// ---------------- weights: transpose 512x512 fp32 -> bf16 ----------------
struct WPtrs { const float* s[9]; };
__global__ void prep_weights(WPtrs wp, __nv_bfloat16* __restrict__ dhi)
{
    __shared__ float t[32][33];
    const int mtx = blockIdx.z;
    const float* src = wp.s[mtx];
    __nv_bfloat16* oh = dhi + (long long)mtx * 512 * 512;
    const int tx = threadIdx.x, ty = threadIdx.y;
    const int bx = blockIdx.x * 32, by = blockIdx.y * 32;
    #pragma unroll
    for (int i = 0; i < 32; i += 8)
        t[ty + i][tx] = src[(long long)(by + ty + i) * 512 + bx + tx];
    __syncthreads();
    #pragma unroll
    for (int i = 0; i < 32; i += 8)
        oh[(long long)(bx + ty + i) * 512 + by + tx] = __float2bfloat16(t[tx][ty + i]);
}

// ---------------- history small GEMM ----------------
__global__ void hist_small(const float* __restrict__ hist,
                           const __nv_bfloat16* __restrict__ w7h,
                           const __nv_bfloat16* __restrict__ w8h,
                           float* __restrict__ out)
{
    const int wid = threadIdx.x >> 5, lane = threadIdx.x & 31;
    const int c = blockIdx.x * 8 + wid;
    const __nv_bfloat16* rh = (c < 512) ? w7h + (long long)c * 512 : w8h + (long long)(c - 512) * 512;
    float acc[8] = {0.f,0.f,0.f,0.f,0.f,0.f,0.f,0.f};
    #pragma unroll 4
    for (int i = 0; i < 16; i++) {
        const int k = lane + i * 32;
        const float w = __bfloat162float(rh[k]);
        #pragma unroll
        for (int r = 0; r < 8; r++) acc[r] = fmaf(hist[r * 512 + k], w, acc[r]);
    }
    #pragma unroll
    for (int r = 0; r < 8; r++) {
        float v = acc[r];
        #pragma unroll
        for (int o = 16; o; o >>= 1) v += __shfl_xor_sync(0xffffffffu, v, o);
        if (lane == 0) out[r * 1024 + c] = v;
    }
}

// ---------------- tk transpose per batch (bf16) ----------------
__global__ void transpose_tk(const __nv_bfloat16* __restrict__ shi,
                             __nv_bfloat16* __restrict__ dhi)
{
    __shared__ __nv_bfloat16 th[32][33];
    const long long zb = (long long)blockIdx.z * 512 * 512;
    const int tx = threadIdx.x, ty = threadIdx.y;
    const int bx = blockIdx.x * 32, by = blockIdx.y * 32;
    #pragma unroll
    for (int i = 0; i < 32; i += 8)
        th[ty + i][tx] = shi[zb + (long long)(by + ty + i) * 512 + bx + tx];
    __syncthreads();
    #pragma unroll
    for (int i = 0; i < 32; i += 8)
        dhi[zb + (long long)(bx + ty + i) * 512 + by + tx] = th[tx][ty + i];
}

// ---------------- mask dtype detector ----------------
__global__ void detect_mask_kernel(const unsigned int* __restrict__ adj, int nwords)
{
    __shared__ unsigned int s;
    if (threadIdx.x == 0) s = 0u;
    __syncthreads();
    unsigned int local = 0u;
    for (int i = threadIdx.x; i < nwords; i += blockDim.x)
        local |= (adj[i] > 1u) ? 1u : 0u;
    if (local) atomicOr(&s, 1u);
    __syncthreads();
    if (threadIdx.x == 0) g_mask_byte_mode = s;
}

// ---------------- tq = elu(decp + histp + headq + b_tq) -> bf16 ----------------
__global__ void build_tq(const float4* __restrict__ dh, const float4* __restrict__ hh,
                         const float4* __restrict__ headq, const float4* __restrict__ btq,
                         __nv_bfloat162* __restrict__ thi)
{
    const int i = blockIdx.x * 256 + threadIdx.x;
    const int d  = i & 127;
    const int h  = (i >> 7) & 63;
    const int bs = i >> 13;
    const int b  = bs >> 5;
    float4 a = dh[bs * 256 + d];
    float4 c = hh[b * 256 + d];
    float4 e = headq[(b * 64 + h) * 128 + d];
    float4 g = btq[d];
    float4 r;
    r.x = eluf(a.x + c.x + e.x + g.x);
    r.y = eluf(a.y + c.y + e.y + g.y);
    r.z = eluf(a.z + c.z + e.z + g.z);
    r.w = eluf(a.w + c.w + e.w + g.w);
    thi[2 * i]     = __floats2bfloat162_rn(r.x, r.y);
    thi[2 * i + 1] = __floats2bfloat162_rn(r.z, r.w);
}

// ---------------- hq = elu(hqd + hqh + b_hq) (cols 512:1024) ----------------
__global__ void build_hq(const float4* __restrict__ dh, const float4* __restrict__ hh,
                         const float4* __restrict__ bhq, float4* __restrict__ hq)
{
    const int i = blockIdx.x * 256 + threadIdx.x;
    const int d  = i & 127;
    const int bs = i >> 7;
    const int b  = bs >> 5;
    float4 a = dh[bs * 256 + 128 + d];
    float4 c = hh[b * 256 + 128 + d];
    float4 g = bhq[d];
    float4 r;
    r.x = eluf(a.x + c.x + g.x);
    r.y = eluf(a.y + c.y + g.y);
    r.z = eluf(a.z + c.z + g.z);
    r.w = eluf(a.w + c.w + g.w);
    hq[i] = r;
}

// ---------------- masked softmax (bf16 hi/lo out) ----------------
__global__ void masked_softmax(const float* __restrict__ attn,
                               __nv_bfloat16* __restrict__ ahi, __nv_bfloat16* __restrict__ alo,
                               const void* __restrict__ adj, const void* __restrict__ dup)
{
    const int q = blockIdx.x;
    const int b = blockIdx.y;
    const int s = q >> 6, h = q & 63;
    const long long ro = ((long long)(b * 2048 + q)) * 512;
    const float* row = attn + ro;
    const long long aoff = ((long long)(b * 64 + h)) * 512;
    const long long doff = ((long long)(b * 32 + s)) * 512;

    const unsigned int byte_mode = g_mask_byte_mode;
    const unsigned char* am8 = (const unsigned char*)adj + aoff;
    const unsigned char* dm8 = (const unsigned char*)dup + doff;
    const int* am32 = (const int*)adj + aoff;
    const int* dm32 = (const int*)dup + doff;

    const int tid = threadIdx.x;
    float v[2]; int mk[2];
    float lmax = -FLT_MAX;
    #pragma unroll
    for (int j = 0; j < 2; j++) {
        const int t = tid + j * 256;
        if (byte_mode) mk[j] = am8[t]  && !dm8[t];
        else           mk[j] = am32[t] && !dm32[t];
        v[j] = row[t];
        if (mk[j]) lmax = fmaxf(lmax, v[j]);
    }
    __shared__ float smax[8], ssum[8];
    #pragma unroll
    for (int o = 16; o; o >>= 1) lmax = fmaxf(lmax, __shfl_xor_sync(0xffffffffu, lmax, o));
    if ((tid & 31) == 0) smax[tid >> 5] = lmax;
    __syncthreads();
    float bmax = -FLT_MAX;
    #pragma unroll
    for (int w = 0; w < 8; w++) bmax = fmaxf(bmax, smax[w]);

    float e[2], lsum = 0.f;
    #pragma unroll
    for (int j = 0; j < 2; j++) { e[j] = mk[j] ? expf(v[j] - bmax) : 0.f; lsum += e[j]; }
    #pragma unroll
    for (int o = 16; o; o >>= 1) lsum += __shfl_xor_sync(0xffffffffu, lsum, o);
    if ((tid & 31) == 0) ssum[tid >> 5] = lsum;
    __syncthreads();
    float bsum = 0.f;
    #pragma unroll
    for (int w = 0; w < 8; w++) bsum += ssum[w];

    const float inv = 1.f / bsum;
    #pragma unroll
    for (int j = 0; j < 2; j++) {
        const int t = tid + j * 256;
        const float p = e[j] * inv;
        const __nv_bfloat16 hb = __float2bfloat16(p);
        ahi[ro + t] = hb;
        alo[ro + t] = __float2bfloat16(p - __bfloat162float(hb));
    }
}

// ---------------- final: head attention + prob + log (attn from bf16 hi/lo) ----------------
__global__ void final_kernel(const float* __restrict__ hq, const float* __restrict__ hk,
                             const __nv_bfloat16* __restrict__ athi,
                             const __nv_bfloat16* __restrict__ atlo,
                             const int* __restrict__ head, float* __restrict__ out)
{
    const int n = blockIdx.x;
    const int b = n >> 5;
    const int tid = threadIdx.x;

    __shared__ float shq[512];
    __shared__ float sc[64];
    __shared__ float sw[64];
    __shared__ int   s_len;

    if (tid == 0) s_len = 0;
    shq[tid]       = hq[(long long)n * 512 + tid];
    shq[tid + 256] = hq[(long long)n * 512 + 256 + tid];
    __syncthreads();
    if (tid < 64) { if (head[b * 64 + tid] != 0) atomicAdd(&s_len, 1); }
    __syncthreads();

    const int w = tid >> 5, lane = tid & 31;
    for (int k = w; k < 64; k += 8) {
        const float* hkr = hk + ((long long)n * 64 + k) * 512;
        float sacc = 0.f;
        for (int d = lane; d < 512; d += 32) sacc = fmaf(shq[d], hkr[d], sacc);
        #pragma unroll
        for (int o = 16; o; o >>= 1) sacc += __shfl_xor_sync(0xffffffffu, sacc, o);
        if (lane == 0) sc[k] = sacc;
    }
    __syncthreads();

    if (tid == 0) {
        const int len = s_len;
        float mx = -FLT_MAX;
        for (int k = 0; k < len; k++) mx = fmaxf(mx, sc[k]);
        float sum = 0.f;
        for (int k = 0; k < 64; k++) {
            float e = (k < len) ? expf(sc[k] - mx) : 0.f;
            sw[k] = e; sum += e;
        }
        float inv = 1.f / sum;
        for (int k = 0; k < 64; k++) sw[k] *= inv;
    }
    __syncthreads();

    const long long base = (long long)n * 64 * 512;
    for (int t = tid; t < 512; t += 256) {
        float p = 0.f;
        #pragma unroll 8
        for (int k = 0; k < 64; k++) {
            const long long o = base + k * 512 + t;
            const float a = __bfloat162float(athi[o]) + __bfloat162float(atlo[o]);
            p = fmaf(sw[k], a, p);
        }
        out[(long long)n * 512 + t] = logf(p + 1e-20f);
    }
}

// ---------------- launch ----------------
extern "C" void kernel_launch(void* const* d_in, const int* in_sizes, int n_in,
                              void* d_out, int out_size)
{
    const float* dec_out = (const float*)d_in[0];
    const float* history = (const float*)d_in[1];
    const int*   head    = (const int*)  d_in[2];
    const int*   tail    = (const int*)  d_in[3];
    const void*  adj     = d_in[4];
    const void*  dup     = d_in[5];
    const float* emb     = (const float*)d_in[6];
    const float* W_tq    = (const float*)d_in[7];
    const float* b_tq    = (const float*)d_in[8];
    const float* W_tk    = (const float*)d_in[9];
    const float* b_tk    = (const float*)d_in[10];
    const float* W_tout  = (const float*)d_in[11];
    const float* W_hq    = (const float*)d_in[12];
    const float* b_hq    = (const float*)d_in[13];
    const float* W_hk    = (const float*)d_in[14];
    const float* b_hk    = (const float*)d_in[15];

    float *dh, *hh, *headq, *attn, *hk, *hq;
    __nv_bfloat16 *tq_hi, *tk_hi, *tkT_hi, *at_hi, *at_lo, *ctx_hi, *gh_hi, *wT_hi;
    cudaGetSymbolAddress((void**)&dh,     g_dh);
    cudaGetSymbolAddress((void**)&hh,     g_hh);
    cudaGetSymbolAddress((void**)&headq,  g_headq);
    cudaGetSymbolAddress((void**)&attn,   g_attn);
    cudaGetSymbolAddress((void**)&hk,     g_hk);
    cudaGetSymbolAddress((void**)&hq,     g_hq);
    cudaGetSymbolAddress((void**)&tq_hi,  g_tq_hi);
    cudaGetSymbolAddress((void**)&tk_hi,  g_tk_hi);
    cudaGetSymbolAddress((void**)&tkT_hi, g_tkT_hi);
    cudaGetSymbolAddress((void**)&at_hi,  g_at_hi);
    cudaGetSymbolAddress((void**)&at_lo,  g_at_lo);
    cudaGetSymbolAddress((void**)&ctx_hi, g_ctx_hi);
    cudaGetSymbolAddress((void**)&gh_hi,  g_gh_hi);
    cudaGetSymbolAddress((void**)&wT_hi,  g_wT_hi);

    cudaFuncSetAttribute(gemm_pro,                cudaFuncAttributeMaxDynamicSharedMemorySize, SMEM_BYTES);
    cudaFuncSetAttribute(gemm_mma<0,false,false>, cudaFuncAttributeMaxDynamicSharedMemorySize, SMEM_BYTES);
    cudaFuncSetAttribute(gemm_mma<0,false,true >, cudaFuncAttributeMaxDynamicSharedMemorySize, SMEM_BYTES);
    cudaFuncSetAttribute(gemm_mma<2,true ,true >, cudaFuncAttributeMaxDynamicSharedMemorySize, SMEM_BYTES);
    cudaFuncSetAttribute(gemm_mma<1,false,false>, cudaFuncAttributeMaxDynamicSharedMemorySize, SMEM_BYTES);

    // weight slots: 0 Wd, 1 Whq0 (merged N=1024), 2 We, 3 Wtk, 4 Wtout0, 5 Wtout1,
    //               6 Whk, 7 Wh, 8 Whq1
    WPtrs wp;
    wp.s[0] = W_tq;               wp.s[1] = W_hq;               wp.s[2] = W_tq + 1024LL*512;
    wp.s[3] = W_tk;               wp.s[4] = W_tout;             wp.s[5] = W_tout + 512LL*512;
    wp.s[6] = W_hk;               wp.s[7] = W_tq + 512LL*512;   wp.s[8] = W_hq + 512LL*512;
    #define WTH(i) (wT_hi + (long long)(i)*512*512)

    detect_mask_kernel<<<1, 256>>>((const unsigned int*)adj, 65536);
    prep_weights<<<dim3(16,16,9), dim3(32,8)>>>(wp, wT_hi);

    hist_small<<<128, 256>>>(history, WTH(7), WTH(8), hh);
    gemm_pro<<<160, 256, SMEM_BYTES>>>(dec_out, emb, head, tail, wT_hi,
                                       dh, headq, tk_hi, b_tk);
    transpose_tk<<<dim3(16,16,8), dim3(32,8)>>>(tk_hi, tkT_hi);
    build_tq<<<8192, 256>>>((const float4*)dh, (const float4*)hh,
                            (const float4*)headq, (const float4*)b_tq,
                            (__nv_bfloat162*)tq_hi);
    // scores[b] = tq[b] @ tk[b]^T
    gemm_mma<0,false,false><<<dim3(4,16,8), 256, SMEM_BYTES>>>(
        tq_hi, tk_hi, nullptr, nullptr,
        attn, nullptr, nullptr, 2048, 512,
        2048LL*512, 512LL*512, 2048LL*512, 512);
    masked_softmax<<<dim3(2048,8), 256>>>(attn, at_hi, at_lo, adj, dup);
    // ctx[b] = attn[b] @ tk[b]
    gemm_mma<0,false,true><<<dim3(4,16,8), 256, SMEM_BYTES>>>(
        at_hi, tkT_hi, nullptr, nullptr,
        nullptr, ctx_hi, nullptr, 2048, 512,
        2048LL*512, 512LL*512, 2048LL*512, 512);
    // ghid = tanh(ctx @ Wtout0 + tq @ Wtout1)
    gemm_mma<2,true,true><<<dim3(4,128,1), 256, SMEM_BYTES>>>(
        ctx_hi, WTH(4), tq_hi, WTH(5),
        nullptr, gh_hi, nullptr, 16384, 512, 0, 0, 0, 512);
    // hk = elu(ghid @ Whk + b_hk)
    gemm_mma<1,false,false><<<dim3(4,128,1), 256, SMEM_BYTES>>>(
        gh_hi, WTH(6), nullptr, nullptr,
        hk, nullptr, b_hk, 16384, 512, 0, 0, 0, 512);
    build_hq<<<128, 256>>>((const float4*)dh, (const float4*)hh,
                           (const float4*)b_hq, (float4*)hq);
    final_kernel<<<256, 256>>>(hq, hk, at_hi, at_lo, head, (float*)d_out);
}

// round 14
// speedup vs baseline: 1.7657x; 1.0103x over previous
#include <cuda_runtime.h>
#include <cuda_bf16.h>
#include <math.h>
#include <float.h>
#include <stdint.h>

// Problem dims: B=8, S=32, HN=64, TN=512, HID=EMB=512
// ---------------- scratch (device globals; no allocation) ----------------
__device__ float g_dh  [256 * 1024];            // [.,0:512)=decp  [.,512:1024)=hqd
__device__ float g_hh  [8   * 1024];            // [.,0:512)=histp [.,512:1024)=hqh
__device__ float g_headq[512  * 512];
__device__ float g_hk   [16384LL*512];          // scores_lo (bf16) early, hk (bf16) late
__device__ float g_hq   [256 * 512];
__device__ __nv_bfloat16 g_tq_hi [8LL*2048*512];
__device__ __nv_bfloat16 g_tk_hi [4096LL*512];
__device__ __nv_bfloat16 g_tkT_hi[4096LL*512];
__device__ __nv_bfloat16 g_at_hi [8LL*2048*512], g_at_lo [8LL*2048*512];
__device__ __nv_bfloat16 g_ctx_hi[8LL*2048*512];
__device__ __nv_bfloat16 g_gh_hi [8LL*2048*512];   // scores_hi early, ghid late
__device__ __nv_bfloat16 g_wT_hi [9LL*512*512];
__device__ unsigned int g_mask_byte_mode;

__device__ __forceinline__ uint32_t smem_u32(const void* p) {
    uint32_t a;
    asm("{ .reg .u64 t; cvta.to.shared.u64 t, %1; cvt.u32.u64 %0, t; }" : "=r"(a) : "l"(p));
    return a;
}
__device__ __forceinline__ void cp16(uint32_t dst, const void* src) {
    asm volatile("cp.async.cg.shared.global [%0], [%1], 16;" :: "r"(dst), "l"(src));
}
__device__ __forceinline__ void mma_bf16(float* d, const uint32_t* a, const uint32_t* b) {
    asm volatile("mma.sync.aligned.m16n8k16.row.col.f32.bf16.bf16.f32 "
        "{%0,%1,%2,%3}, {%4,%5,%6,%7}, {%8,%9}, {%0,%1,%2,%3};"
        : "+f"(d[0]), "+f"(d[1]), "+f"(d[2]), "+f"(d[3])
        : "r"(a[0]), "r"(a[1]), "r"(a[2]), "r"(a[3]), "r"(b[0]), "r"(b[1]));
}
__device__ __forceinline__ void ldm_x4(uint32_t& r0, uint32_t& r1, uint32_t& r2, uint32_t& r3,
                                       uint32_t addr) {
    asm volatile("ldmatrix.sync.aligned.m8n8.x4.shared.b16 {%0,%1,%2,%3}, [%4];"
        : "=r"(r0), "=r"(r1), "=r"(r2), "=r"(r3) : "r"(addr));
}
__device__ __forceinline__ float eluf(float x) { return x > 0.f ? x : expm1f(x); }

// ---- big-GEMM smem: 3 buffers; each = A(128x144B)+B(128x144B) ----
#define ROWB   144
#define ATILEB (128 * ROWB)          // 18432
#define BTILEB (128 * ROWB)          // 18432
#define BUFB   (ATILEB + BTILEB)     // 36864
#define NSTAGE 3
#define SMEM_BYTES (NSTAGE * BUFB)   // 110592 -> 2 CTAs/SM
// ---- pro smem: 4 buffers; each = A(64x144B)+B(128x144B) ----
#define PATILEB (64 * ROWB)          // 9216
#define PBUFB   (PATILEB + BTILEB)   // 27648  (4 * 27648 = 110592)

#define LDM_SETUP \
    const int lrow = lane & 7, lsel = lane >> 3; \
    const int a_dm = (lsel & 1) << 3, a_dk = (lsel >> 1) << 3; \
    const int b_dn = (lsel >> 1) << 3, b_dk = (lsel & 1) << 3;

// ==================================================================
// Single-bf16 GEMM; MT=128; K-chunk 64; 3-stage loop.
// OUTB: 0 = fp32 out, 1 = bf16 out, 2 = bf16 hi + residual lo out
// ==================================================================
template<int ACT, bool TWO, int OUTB>
__global__ void __launch_bounds__(256, 2) gemm_mma(
    const __nv_bfloat16* __restrict__ Ahi,
    const __nv_bfloat16* __restrict__ Bhi,
    const __nv_bfloat16* __restrict__ A2hi,
    const __nv_bfloat16* __restrict__ B2hi,
    float* __restrict__ Cf, __nv_bfloat16* __restrict__ Chi, __nv_bfloat16* __restrict__ Clo,
    const float* __restrict__ bias,
    int M, int K, long long sA, long long sB, long long sC, int ldc)
{
    constexpr int FM = 4;
    extern __shared__ char sm[];
    const uint32_t smb = smem_u32(sm);
    const int tid = threadIdx.x, wid = tid >> 5, lane = tid & 31;
    const int wm = wid >> 2, wn = wid & 3;
    const int m0 = blockIdx.y * 128, n0 = blockIdx.x * 128, z = blockIdx.z;

    const int kc  = K >> 6;
    const int nch = TWO ? 2 * kc : kc;

    float d[FM][4][4];
    #pragma unroll
    for (int f = 0; f < FM; f++)
        #pragma unroll
        for (int g = 0; g < 4; g++)
            #pragma unroll
            for (int e = 0; e < 4; e++) d[f][g][e] = 0.f;

    auto load_chunk = [&](int c) {
        const bool sec = TWO && (c >= kc);
        const int koff = (sec ? c - kc : c) << 6;
        const int buf = c % NSTAGE;
        const uint32_t smA = smb + buf * BUFB;
        const uint32_t smB = smA + ATILEB;
        {
            const __nv_bfloat16* pH = (sec ? A2hi : Ahi) + (long long)z * sA;
            #pragma unroll
            for (int i = 0; i < 4; i++) {
                const int idx = tid + 256 * i;
                const int r = idx >> 3, s = idx & 7;
                cp16(smA + r * ROWB + s * 16,
                     pH + (long long)(m0 + r) * K + koff + s * 8);
            }
        }
        {
            const __nv_bfloat16* pH = (sec ? B2hi : Bhi) + (long long)z * sB;
            #pragma unroll
            for (int i = 0; i < 4; i++) {
                const int idx = tid + 256 * i;
                const int r = idx >> 3, s = idx & 7;
                cp16(smB + r * ROWB + s * 16,
                     pH + (long long)(n0 + r) * K + koff + s * 8);
            }
        }
        asm volatile("cp.async.commit_group;");
    };

    LDM_SETUP

    auto compute_chunk = [&](int c) {
        const uint32_t a_base = smb + (c % NSTAGE) * BUFB;
        const uint32_t b_base = a_base + ATILEB;
        #pragma unroll
        for (int st = 0; st < 4; ++st) {
            const int k = st * 16;
            uint32_t a[FM][4], b[4][2];
            #pragma unroll
            for (int f = 0; f < FM; f++) {
                const uint32_t addr = a_base
                    + (uint32_t)((wm * 64 + f * 16 + a_dm + lrow) * ROWB + (k + a_dk) * 2);
                ldm_x4(a[f][0], a[f][1], a[f][2], a[f][3], addr);
            }
            #pragma unroll
            for (int gp = 0; gp < 2; gp++) {
                const uint32_t addr = b_base
                    + (uint32_t)((wn * 32 + gp * 16 + b_dn + lrow) * ROWB + (k + b_dk) * 2);
                ldm_x4(b[2*gp][0], b[2*gp][1], b[2*gp+1][0], b[2*gp+1][1], addr);
            }
            #pragma unroll
            for (int f = 0; f < FM; f++)
                #pragma unroll
                for (int g = 0; g < 4; g++)
                    mma_bf16(d[f][g], a[f], b[g]);
        }
    };

    load_chunk(0);
    if (nch > 1) load_chunk(1);
    for (int c = 0; c < nch; ++c) {
        if (c + 1 < nch) asm volatile("cp.async.wait_group 1;");
        else             asm volatile("cp.async.wait_group 0;");
        __syncthreads();
        if (c + 2 < nch) load_chunk(c + 2);
        compute_chunk(c);
    }

    const int qr = lane >> 2, qc = 2 * (lane & 3);
    #pragma unroll
    for (int f = 0; f < FM; f++) {
        #pragma unroll
        for (int g = 0; g < 4; g++) {
            const int cc = n0 + wn * 32 + g * 8 + qc;
            float bx = 0.f, by = 0.f;
            if (bias) { bx = bias[cc]; by = bias[cc + 1]; }
            #pragma unroll
            for (int h = 0; h < 2; h++) {
                const int row = m0 + wm * 64 + f * 16 + qr + h * 8;
                if (row >= M) continue;
                float v0 = d[f][g][2 * h]     + bx;
                float v1 = d[f][g][2 * h + 1] + by;
                if (ACT == 1) { v0 = eluf(v0); v1 = eluf(v1); }
                else if (ACT == 2) { v0 = tanhf(v0); v1 = tanhf(v1); }
                const long long o = (long long)z * sC + (long long)row * ldc + cc;
                if constexpr (OUTB == 0) {
                    *reinterpret_cast<float2*>(Cf + o) = make_float2(v0, v1);
                } else if constexpr (OUTB == 1) {
                    *reinterpret_cast<__nv_bfloat162*>(Chi + o) = __floats2bfloat162_rn(v0, v1);
                } else {
                    __nv_bfloat162 hb = __floats2bfloat162_rn(v0, v1);
                    float2 hf = __bfloat1622float2(hb);
                    __nv_bfloat162 lb = __floats2bfloat162_rn(v0 - hf.x, v1 - hf.y);
                    *reinterpret_cast<__nv_bfloat162*>(Chi + o) = hb;
                    *reinterpret_cast<__nv_bfloat162*>(Clo + o) = lb;
                }
            }
        }
    }
}

// ==================================================================
// Prologue uber-GEMM (fp32 A with gather -> bf16), MT=64, pair-loop:
// Grid 320 CTAs: [0,32) dh, [32,64) headq, [64,320) tk
// ==================================================================
__global__ void __launch_bounds__(256, 2) gemm_pro(
    const float* __restrict__ dec_out, const float* __restrict__ emb,
    const int* __restrict__ head, const int* __restrict__ tail,
    const __nv_bfloat16* __restrict__ wT_hi,
    float* __restrict__ dh, float* __restrict__ headq,
    __nv_bfloat16* __restrict__ tk_hi,
    const float* __restrict__ b_tk)
{
    constexpr int FM = 2;
    extern __shared__ char sm[];
    const uint32_t smb = smem_u32(sm);
    const int tid = threadIdx.x, wid = tid >> 5, lane = tid & 31;
    const int wm = wid >> 2, wn = wid & 3;

    const int bid = blockIdx.x;
    const float* Af; const int* gidx; long long boff; float* Cf; int ldc;
    int m0, n0; int outb, act; const float* bias;
    if (bid < 32) {
        Af = dec_out; gidx = nullptr; boff = 0;
        Cf = dh; ldc = 1024; outb = 0; act = 0; bias = nullptr;
        n0 = (bid & 7) * 128; m0 = (bid >> 3) * 64;
    } else if (bid < 64) {
        const int t = bid - 32;
        Af = emb; gidx = head; boff = 2LL * 512 * 512;
        Cf = headq; ldc = 512; outb = 0; act = 0; bias = nullptr;
        n0 = (t & 3) * 128; m0 = (t >> 2) * 64;
    } else {
        const int t = bid - 64;
        Af = emb; gidx = tail; boff = 3LL * 512 * 512;
        Cf = nullptr; ldc = 512; outb = 1; act = 1; bias = b_tk;
        n0 = (t & 3) * 128; m0 = (t >> 2) * 64;
    }
    const __nv_bfloat16* Bhi = wT_hi + boff;
    const int K = 512, np = 4;

    float d[FM][4][4];
    #pragma unroll
    for (int f = 0; f < FM; f++)
        #pragma unroll
        for (int g = 0; g < 4; g++)
            #pragma unroll
            for (int e = 0; e < 4; e++) d[f][g][e] = 0.f;

    auto load_chunk = [&](int c) {
        const int koff = c << 6;
        const int buf = c & 3;
        const uint32_t smA = smb + buf * PBUFB;
        const uint32_t smB = smA + PATILEB;
        char* smAp = sm + buf * PBUFB;
        #pragma unroll
        for (int i = 0; i < 4; i++) {
            const int idx = tid + 256 * i;          // 0..1023
            const int r = idx >> 4, s = idx & 15;
            const int gm = m0 + r;
            const long long row = gidx ? (long long)gidx[gm] : (long long)gm;
            float4 v = *reinterpret_cast<const float4*>(Af + row * K + koff + s * 4);
            uint2 uh;
            __nv_bfloat162 h01 = __floats2bfloat162_rn(v.x, v.y);
            __nv_bfloat162 h23 = __floats2bfloat162_rn(v.z, v.w);
            uh.x = *(uint32_t*)&h01; uh.y = *(uint32_t*)&h23;
            *reinterpret_cast<uint2*>(smAp + r * ROWB + s * 8) = uh;
        }
        #pragma unroll
        for (int i = 0; i < 4; i++) {
            const int idx = tid + 256 * i;
            const int r = idx >> 3, s = idx & 7;
            cp16(smB + r * ROWB + s * 16,
                 Bhi + (long long)(n0 + r) * K + koff + s * 8);
        }
    };
    auto load_pair = [&](int p) {
        load_chunk(2 * p);
        load_chunk(2 * p + 1);
        asm volatile("cp.async.commit_group;");
    };

    LDM_SETUP

    auto compute_chunk = [&](int c) {
        const uint32_t a_base = smb + (c & 3) * PBUFB;
        const uint32_t b_base = a_base + PATILEB;
        #pragma unroll
        for (int st = 0; st < 4; ++st) {
            const int k = st * 16;
            uint32_t a[FM][4], b[4][2];
            #pragma unroll
            for (int f = 0; f < FM; f++) {
                const uint32_t addr = a_base
                    + (uint32_t)((wm * 32 + f * 16 + a_dm + lrow) * ROWB + (k + a_dk) * 2);
                ldm_x4(a[f][0], a[f][1], a[f][2], a[f][3], addr);
            }
            #pragma unroll
            for (int gp = 0; gp < 2; gp++) {
                const uint32_t addr = b_base
                    + (uint32_t)((wn * 32 + gp * 16 + b_dn + lrow) * ROWB + (k + b_dk) * 2);
                ldm_x4(b[2*gp][0], b[2*gp][1], b[2*gp+1][0], b[2*gp+1][1], addr);
            }
            #pragma unroll
            for (int f = 0; f < FM; f++)
                #pragma unroll
                for (int g = 0; g < 4; g++)
                    mma_bf16(d[f][g], a[f], b[g]);
        }
    };

    load_pair(0);
    for (int p = 0; p < np; ++p) {
        asm volatile("cp.async.wait_group 0;");
        __syncthreads();
        if (p + 1 < np) load_pair(p + 1);
        compute_chunk(2 * p);
        compute_chunk(2 * p + 1);
    }

    const int qr = lane >> 2, qc = 2 * (lane & 3);
    #pragma unroll
    for (int f = 0; f < FM; f++) {
        #pragma unroll
        for (int g = 0; g < 4; g++) {
            const int cc = n0 + wn * 32 + g * 8 + qc;
            float bx = 0.f, by = 0.f;
            if (bias) { bx = bias[cc]; by = bias[cc + 1]; }
            #pragma unroll
            for (int h = 0; h < 2; h++) {
                const int row = m0 + wm * 32 + f * 16 + qr + h * 8;
                float v0 = d[f][g][2 * h]     + bx;
                float v1 = d[f][g][2 * h + 1] + by;
                if (act == 1) { v0 = eluf(v0); v1 = eluf(v1); }
                if (!outb) {
                    *reinterpret_cast<float2*>(Cf + (long long)row * ldc + cc) = make_float2(v0, v1);
                } else {
                    *reinterpret_cast<__nv_bfloat162*>(tk_hi + (long long)row * 512 + cc) =
                        __floats2bfloat162_rn(v0, v1);
                }
            }
        }
    }
}

// ---------------- weights: transpose 512x512 fp32 -> bf16 ----------------
struct WPtrs { const float* s[9]; };
__global__ void prep_weights(WPtrs wp, __nv_bfloat16* __restrict__ dhi)
{
    __shared__ float t[32][33];
    const int mtx = blockIdx.z;
    const float* src = wp.s[mtx];
    __nv_bfloat16* oh = dhi + (long long)mtx * 512 * 512;
    const int tx = threadIdx.x, ty = threadIdx.y;
    const int bx = blockIdx.x * 32, by = blockIdx.y * 32;
    #pragma unroll
    for (int i = 0; i < 32; i += 8)
        t[ty + i][tx] = src[(long long)(by + ty + i) * 512 + bx + tx];
    __syncthreads();
    #pragma unroll
    for (int i = 0; i < 32; i += 8)
        oh[(long long)(bx + ty + i) * 512 + by + tx] = __float2bfloat16(t[tx][ty + i]);
}

// ---------------- history small GEMM ----------------
__global__ void hist_small(const float* __restrict__ hist,
                           const __nv_bfloat16* __restrict__ w7h,
                           const __nv_bfloat16* __restrict__ w8h,
                           float* __restrict__ out)
{
    const int wid = threadIdx.x >> 5, lane = threadIdx.x & 31;
    const int c = blockIdx.x * 8 + wid;
    const __nv_bfloat16* rh = (c < 512) ? w7h + (long long)c * 512 : w8h + (long long)(c - 512) * 512;
    float acc[8] = {0.f,0.f,0.f,0.f,0.f,0.f,0.f,0.f};
    #pragma unroll 4
    for (int i = 0; i < 16; i++) {
        const int k = lane + i * 32;
        const float w = __bfloat162float(rh[k]);
        #pragma unroll
        for (int r = 0; r < 8; r++) acc[r] = fmaf(hist[r * 512 + k], w, acc[r]);
    }
    #pragma unroll
    for (int r = 0; r < 8; r++) {
        float v = acc[r];
        #pragma unroll
        for (int o = 16; o; o >>= 1) v += __shfl_xor_sync(0xffffffffu, v, o);
        if (lane == 0) out[r * 1024 + c] = v;
    }
}

// ---------------- tk transpose per batch (bf16) ----------------
__global__ void transpose_tk(const __nv_bfloat16* __restrict__ shi,
                             __nv_bfloat16* __restrict__ dhi)
{
    __shared__ __nv_bfloat16 th[32][33];
    const long long zb = (long long)blockIdx.z * 512 * 512;
    const int tx = threadIdx.x, ty = threadIdx.y;
    const int bx = blockIdx.x * 32, by = blockIdx.y * 32;
    #pragma unroll
    for (int i = 0; i < 32; i += 8)
        th[ty + i][tx] = shi[zb + (long long)(by + ty + i) * 512 + bx + tx];
    __syncthreads();
    #pragma unroll
    for (int i = 0; i < 32; i += 8)
        dhi[zb + (long long)(bx + ty + i) * 512 + by + tx] = th[tx][ty + i];
}

// ---------------- mask dtype detector ----------------
__global__ void detect_mask_kernel(const unsigned int* __restrict__ adj, int nwords)
{
    __shared__ unsigned int s;
    if (threadIdx.x == 0) s = 0u;
    __syncthreads();
    unsigned int local = 0u;
    for (int i = threadIdx.x; i < nwords; i += blockDim.x)
        local |= (adj[i] > 1u) ? 1u : 0u;
    if (local) atomicOr(&s, 1u);
    __syncthreads();
    if (threadIdx.x == 0) g_mask_byte_mode = s;
}

// ---------------- tq = elu(decp + histp + headq + b_tq) -> bf16 ----------------
__global__ void build_tq(const float4* __restrict__ dh, const float4* __restrict__ hh,
                         const float4* __restrict__ headq, const float4* __restrict__ btq,
                         __nv_bfloat162* __restrict__ thi)
{
    const int i = blockIdx.x * 256 + threadIdx.x;
    const int d  = i & 127;
    const int h  = (i >> 7) & 63;
    const int bs = i >> 13;
    const int b  = bs >> 5;
    float4 a = dh[bs * 256 + d];
    float4 c = hh[b * 256 + d];
    float4 e = headq[(b * 64 + h) * 128 + d];
    float4 g = btq[d];
    float4 r;
    r.x = eluf(a.x + c.x + e.x + g.x);
    r.y = eluf(a.y + c.y + e.y + g.y);
    r.z = eluf(a.z + c.z + e.z + g.z);
    r.w = eluf(a.w + c.w + e.w + g.w);
    thi[2 * i]     = __floats2bfloat162_rn(r.x, r.y);
    thi[2 * i + 1] = __floats2bfloat162_rn(r.z, r.w);
}

// ---------------- hq = elu(hqd + hqh + b_hq) (cols 512:1024) ----------------
__global__ void build_hq(const float4* __restrict__ dh, const float4* __restrict__ hh,
                         const float4* __restrict__ bhq, float4* __restrict__ hq)
{
    const int i = blockIdx.x * 256 + threadIdx.x;
    const int d  = i & 127;
    const int bs = i >> 7;
    const int b  = bs >> 5;
    float4 a = dh[bs * 256 + 128 + d];
    float4 c = hh[b * 256 + 128 + d];
    float4 g = bhq[d];
    float4 r;
    r.x = eluf(a.x + c.x + g.x);
    r.y = eluf(a.y + c.y + g.y);
    r.z = eluf(a.z + c.z + g.z);
    r.w = eluf(a.w + c.w + g.w);
    hq[i] = r;
}

// ---------------- masked softmax (scores from bf16 hi/lo; out bf16 hi/lo) ----------------
__global__ void masked_softmax(const __nv_bfloat16* __restrict__ schi,
                               const __nv_bfloat16* __restrict__ sclo,
                               __nv_bfloat16* __restrict__ ahi, __nv_bfloat16* __restrict__ alo,
                               const void* __restrict__ adj, const void* __restrict__ dup)
{
    const int q = blockIdx.x;
    const int b = blockIdx.y;
    const int s = q >> 6, h = q & 63;
    const long long ro = ((long long)(b * 2048 + q)) * 512;
    const long long aoff = ((long long)(b * 64 + h)) * 512;
    const long long doff = ((long long)(b * 32 + s)) * 512;

    const unsigned int byte_mode = g_mask_byte_mode;
    const unsigned char* am8 = (const unsigned char*)adj + aoff;
    const unsigned char* dm8 = (const unsigned char*)dup + doff;
    const int* am32 = (const int*)adj + aoff;
    const int* dm32 = (const int*)dup + doff;

    const int tid = threadIdx.x;
    float v[2]; int mk[2];
    float lmax = -FLT_MAX;
    #pragma unroll
    for (int j = 0; j < 2; j++) {
        const int t = tid + j * 256;
        if (byte_mode) mk[j] = am8[t]  && !dm8[t];
        else           mk[j] = am32[t] && !dm32[t];
        v[j] = __bfloat162float(schi[ro + t]) + __bfloat162float(sclo[ro + t]);
        if (mk[j]) lmax = fmaxf(lmax, v[j]);
    }
    __shared__ float smax[8], ssum[8];
    #pragma unroll
    for (int o = 16; o; o >>= 1) lmax = fmaxf(lmax, __shfl_xor_sync(0xffffffffu, lmax, o));
    if ((tid & 31) == 0) smax[tid >> 5] = lmax;
    __syncthreads();
    float bmax = -FLT_MAX;
    #pragma unroll
    for (int w = 0; w < 8; w++) bmax = fmaxf(bmax, smax[w]);

    float e[2], lsum = 0.f;
    #pragma unroll
    for (int j = 0; j < 2; j++) { e[j] = mk[j] ? expf(v[j] - bmax) : 0.f; lsum += e[j]; }
    #pragma unroll
    for (int o = 16; o; o >>= 1) lsum += __shfl_xor_sync(0xffffffffu, lsum, o);
    if ((tid & 31) == 0) ssum[tid >> 5] = lsum;
    __syncthreads();
    float bsum = 0.f;
    #pragma unroll
    for (int w = 0; w < 8; w++) bsum += ssum[w];

    const float inv = 1.f / bsum;
    #pragma unroll
    for (int j = 0; j < 2; j++) {
        const int t = tid + j * 256;
        const float p = e[j] * inv;
        const __nv_bfloat16 hb = __float2bfloat16(p);
        ahi[ro + t] = hb;
        alo[ro + t] = __float2bfloat16(p - __bfloat162float(hb));
    }
}

// ---------------- final: head attention + prob + log ----------------
__global__ void final_kernel(const float* __restrict__ hq,
                             const __nv_bfloat16* __restrict__ hk,
                             const __nv_bfloat16* __restrict__ athi,
                             const __nv_bfloat16* __restrict__ atlo,
                             const int* __restrict__ head, float* __restrict__ out)
{
    const int n = blockIdx.x;
    const int b = n >> 5;
    const int tid = threadIdx.x;

    __shared__ float shq[512];
    __shared__ float sc[64];
    __shared__ float sw[64];
    __shared__ int   s_len;

    if (tid == 0) s_len = 0;
    shq[tid]       = hq[(long long)n * 512 + tid];
    shq[tid + 256] = hq[(long long)n * 512 + 256 + tid];
    __syncthreads();
    if (tid < 64) { if (head[b * 64 + tid] != 0) atomicAdd(&s_len, 1); }
    __syncthreads();

    const int w = tid >> 5, lane = tid & 31;
    for (int k = w; k < 64; k += 8) {
        const __nv_bfloat16* hkr = hk + ((long long)n * 64 + k) * 512;
        float sacc = 0.f;
        for (int dd = lane; dd < 512; dd += 32)
            sacc = fmaf(shq[dd], __bfloat162float(hkr[dd]), sacc);
        #pragma unroll
        for (int o = 16; o; o >>= 1) sacc += __shfl_xor_sync(0xffffffffu, sacc, o);
        if (lane == 0) sc[k] = sacc;
    }
    __syncthreads();

    if (tid == 0) {
        const int len = s_len;
        float mx = -FLT_MAX;
        for (int k = 0; k < len; k++) mx = fmaxf(mx, sc[k]);
        float sum = 0.f;
        for (int k = 0; k < 64; k++) {
            float e = (k < len) ? expf(sc[k] - mx) : 0.f;
            sw[k] = e; sum += e;
        }
        float inv = 1.f / sum;
        for (int k = 0; k < 64; k++) sw[k] *= inv;
    }
    __syncthreads();

    const long long base = (long long)n * 64 * 512;
    for (int t = tid; t < 512; t += 256) {
        float p = 0.f;
        #pragma unroll 8
        for (int k = 0; k < 64; k++) {
            const long long o = base + k * 512 + t;
            const float a = __bfloat162float(athi[o]) + __bfloat162float(atlo[o]);
            p = fmaf(sw[k], a, p);
        }
        out[(long long)n * 512 + t] = logf(p + 1e-20f);
    }
}

// ---------------- launch ----------------
extern "C" void kernel_launch(void* const* d_in, const int* in_sizes, int n_in,
                              void* d_out, int out_size)
{
    const float* dec_out = (const float*)d_in[0];
    const float* history = (const float*)d_in[1];
    const int*   head    = (const int*)  d_in[2];
    const int*   tail    = (const int*)  d_in[3];
    const void*  adj     = d_in[4];
    const void*  dup     = d_in[5];
    const float* emb     = (const float*)d_in[6];
    const float* W_tq    = (const float*)d_in[7];
    const float* b_tq    = (const float*)d_in[8];
    const float* W_tk    = (const float*)d_in[9];
    const float* b_tk    = (const float*)d_in[10];
    const float* W_tout  = (const float*)d_in[11];
    const float* W_hq    = (const float*)d_in[12];
    const float* b_hq    = (const float*)d_in[13];
    const float* W_hk    = (const float*)d_in[14];
    const float* b_hk    = (const float*)d_in[15];

    float *dh, *hh, *headq, *hkbuf, *hq;
    __nv_bfloat16 *tq_hi, *tk_hi, *tkT_hi, *at_hi, *at_lo, *ctx_hi, *gh_hi, *wT_hi;
    cudaGetSymbolAddress((void**)&dh,     g_dh);
    cudaGetSymbolAddress((void**)&hh,     g_hh);
    cudaGetSymbolAddress((void**)&headq,  g_headq);
    cudaGetSymbolAddress((void**)&hkbuf,  g_hk);
    cudaGetSymbolAddress((void**)&hq,     g_hq);
    cudaGetSymbolAddress((void**)&tq_hi,  g_tq_hi);
    cudaGetSymbolAddress((void**)&tk_hi,  g_tk_hi);
    cudaGetSymbolAddress((void**)&tkT_hi, g_tkT_hi);
    cudaGetSymbolAddress((void**)&at_hi,  g_at_hi);
    cudaGetSymbolAddress((void**)&at_lo,  g_at_lo);
    cudaGetSymbolAddress((void**)&ctx_hi, g_ctx_hi);
    cudaGetSymbolAddress((void**)&gh_hi,  g_gh_hi);
    cudaGetSymbolAddress((void**)&wT_hi,  g_wT_hi);

    // buffer aliasing: scores hi -> g_gh_hi (ghid written later);
    //                  scores lo -> g_hk as bf16 (hk written later);
    //                  hk (bf16)  -> g_hk after softmax consumed scores lo.
    __nv_bfloat16* sc_hi = gh_hi;
    __nv_bfloat16* sc_lo = (__nv_bfloat16*)hkbuf;
    __nv_bfloat16* hkb   = (__nv_bfloat16*)hkbuf;

    cudaFuncSetAttribute(gemm_pro,            cudaFuncAttributeMaxDynamicSharedMemorySize, SMEM_BYTES);
    cudaFuncSetAttribute(gemm_mma<0,false,2>, cudaFuncAttributeMaxDynamicSharedMemorySize, SMEM_BYTES);
    cudaFuncSetAttribute(gemm_mma<0,false,1>, cudaFuncAttributeMaxDynamicSharedMemorySize, SMEM_BYTES);
    cudaFuncSetAttribute(gemm_mma<2,true ,1>, cudaFuncAttributeMaxDynamicSharedMemorySize, SMEM_BYTES);
    cudaFuncSetAttribute(gemm_mma<1,false,1>, cudaFuncAttributeMaxDynamicSharedMemorySize, SMEM_BYTES);

    // weight slots: 0 Wd, 1 Whq0 (merged N=1024), 2 We, 3 Wtk, 4 Wtout0, 5 Wtout1,
    //               6 Whk, 7 Wh, 8 Whq1
    WPtrs wp;
    wp.s[0] = W_tq;               wp.s[1] = W_hq;               wp.s[2] = W_tq + 1024LL*512;
    wp.s[3] = W_tk;               wp.s[4] = W_tout;             wp.s[5] = W_tout + 512LL*512;
    wp.s[6] = W_hk;               wp.s[7] = W_tq + 512LL*512;   wp.s[8] = W_hq + 512LL*512;
    #define WTH(i) (wT_hi + (long long)(i)*512*512)

    detect_mask_kernel<<<1, 256>>>((const unsigned int*)adj, 65536);
    prep_weights<<<dim3(16,16,9), dim3(32,8)>>>(wp, wT_hi);

    hist_small<<<128, 256>>>(history, WTH(7), WTH(8), hh);
    gemm_pro<<<320, 256, SMEM_BYTES>>>(dec_out, emb, head, tail, wT_hi,
                                       dh, headq, tk_hi, b_tk);
    transpose_tk<<<dim3(16,16,8), dim3(32,8)>>>(tk_hi, tkT_hi);
    build_tq<<<8192, 256>>>((const float4*)dh, (const float4*)hh,
                            (const float4*)headq, (const float4*)b_tq,
                            (__nv_bfloat162*)tq_hi);
    // scores[b] = tq[b] @ tk[b]^T -> bf16 hi/lo
    gemm_mma<0,false,2><<<dim3(4,16,8), 256, SMEM_BYTES>>>(
        tq_hi, tk_hi, nullptr, nullptr,
        nullptr, sc_hi, sc_lo, nullptr, 2048, 512,
        2048LL*512, 512LL*512, 2048LL*512, 512);
    masked_softmax<<<dim3(2048,8), 256>>>(sc_hi, sc_lo, at_hi, at_lo, adj, dup);
    // ctx[b] = attn[b] @ tk[b] -> bf16
    gemm_mma<0,false,1><<<dim3(4,16,8), 256, SMEM_BYTES>>>(
        at_hi, tkT_hi, nullptr, nullptr,
        nullptr, ctx_hi, nullptr, nullptr, 2048, 512,
        2048LL*512, 512LL*512, 2048LL*512, 512);
    // ghid = tanh(ctx @ Wtout0 + tq @ Wtout1) -> bf16 (overwrites sc_hi)
    gemm_mma<2,true,1><<<dim3(4,128,1), 256, SMEM_BYTES>>>(
        ctx_hi, WTH(4), tq_hi, WTH(5),
        nullptr, gh_hi, nullptr, nullptr, 16384, 512, 0, 0, 0, 512);
    // hk = elu(ghid @ Whk + b_hk) -> bf16 (overwrites sc_lo space)
    gemm_mma<1,false,1><<<dim3(4,128,1), 256, SMEM_BYTES>>>(
        gh_hi, WTH(6), nullptr, nullptr,
        nullptr, hkb, nullptr, b_hk, 16384, 512, 0, 0, 0, 512);
    build_hq<<<128, 256>>>((const float4*)dh, (const float4*)hh,
                           (const float4*)b_hq, (float4*)hq);
    final_kernel<<<256, 256>>>(hq, hkb, at_hi, at_lo, head, (float*)d_out);
}

// round 15
// speedup vs baseline: 1.7819x; 1.0092x over previous
#include <cuda_runtime.h>
#include <cuda_bf16.h>
#include <math.h>
#include <float.h>
#include <stdint.h>

// Problem dims: B=8, S=32, HN=64, TN=512, HID=EMB=512
// ---------------- scratch (device globals; no allocation) ----------------
__device__ float g_dh  [256 * 1024];            // [.,0:512)=decp  [.,512:1024)=hqd
__device__ float g_hh  [8   * 1024];            // [.,0:512)=histp [.,512:1024)=hqh
__device__ float g_headq[512  * 512];
__device__ float g_hk   [16384LL*512];          // scores_lo (bf16) early, hk (bf16) late
__device__ float g_hq   [256 * 512];
__device__ __nv_bfloat16 g_tq_hi [8LL*2048*512];
__device__ __nv_bfloat16 g_tk_hi [4096LL*512];
__device__ __nv_bfloat16 g_tkT_hi[4096LL*512];
__device__ __nv_bfloat16 g_at_hi [8LL*2048*512], g_at_lo [8LL*2048*512];
__device__ __nv_bfloat16 g_ctx_hi[8LL*2048*512];
__device__ __nv_bfloat16 g_gh_hi [8LL*2048*512];   // scores_hi early, ghid late
__device__ __nv_bfloat16 g_wT_hi [9LL*512*512];
__device__ unsigned int g_mask_byte_mode;

__device__ __forceinline__ uint32_t smem_u32(const void* p) {
    uint32_t a;
    asm("{ .reg .u64 t; cvta.to.shared.u64 t, %1; cvt.u32.u64 %0, t; }" : "=r"(a) : "l"(p));
    return a;
}
__device__ __forceinline__ void cp16(uint32_t dst, const void* src) {
    asm volatile("cp.async.cg.shared.global [%0], [%1], 16;" :: "r"(dst), "l"(src));
}
__device__ __forceinline__ void mma_bf16(float* d, const uint32_t* a, const uint32_t* b) {
    asm volatile("mma.sync.aligned.m16n8k16.row.col.f32.bf16.bf16.f32 "
        "{%0,%1,%2,%3}, {%4,%5,%6,%7}, {%8,%9}, {%0,%1,%2,%3};"
        : "+f"(d[0]), "+f"(d[1]), "+f"(d[2]), "+f"(d[3])
        : "r"(a[0]), "r"(a[1]), "r"(a[2]), "r"(a[3]), "r"(b[0]), "r"(b[1]));
}
__device__ __forceinline__ void ldm_x4(uint32_t& r0, uint32_t& r1, uint32_t& r2, uint32_t& r3,
                                       uint32_t addr) {
    asm volatile("ldmatrix.sync.aligned.m8n8.x4.shared.b16 {%0,%1,%2,%3}, [%4];"
        : "=r"(r0), "=r"(r1), "=r"(r2), "=r"(r3) : "r"(addr));
}
__device__ __forceinline__ float eluf(float x) { return x > 0.f ? x : expm1f(x); }

// ---- big-GEMM smem: 3 buffers; each = A(128x144B)+B(128x144B) ----
#define ROWB   144
#define ATILEB (128 * ROWB)          // 18432
#define BTILEB (128 * ROWB)          // 18432
#define BUFB   (ATILEB + BTILEB)     // 36864
#define NSTAGE 3
#define SMEM_BYTES (NSTAGE * BUFB)   // 110592 -> 2 CTAs/SM
// ---- pro smem: 4 buffers; each = A(64x144B)+B(128x144B) ----
#define PATILEB (64 * ROWB)          // 9216
#define PBUFB   (PATILEB + BTILEB)   // 27648  (4 * 27648 = 110592)

#define LDM_SETUP \
    const int lrow = lane & 7, lsel = lane >> 3; \
    const int a_dm = (lsel & 1) << 3, a_dk = (lsel >> 1) << 3; \
    const int b_dn = (lsel >> 1) << 3, b_dk = (lsel & 1) << 3;

// ==================================================================
// Single-bf16 GEMM; MT=128; K-chunk 64; 3-stage loop.
// OUTB: 0 = fp32 out, 1 = bf16 out, 2 = bf16 hi + residual lo out
// ==================================================================
template<int ACT, bool TWO, int OUTB>
__global__ void __launch_bounds__(256, 2) gemm_mma(
    const __nv_bfloat16* __restrict__ Ahi,
    const __nv_bfloat16* __restrict__ Bhi,
    const __nv_bfloat16* __restrict__ A2hi,
    const __nv_bfloat16* __restrict__ B2hi,
    float* __restrict__ Cf, __nv_bfloat16* __restrict__ Chi, __nv_bfloat16* __restrict__ Clo,
    const float* __restrict__ bias,
    int M, int K, long long sA, long long sB, long long sC, int ldc)
{
    constexpr int FM = 4;
    extern __shared__ char sm[];
    const uint32_t smb = smem_u32(sm);
    const int tid = threadIdx.x, wid = tid >> 5, lane = tid & 31;
    const int wm = wid >> 2, wn = wid & 3;
    const int m0 = blockIdx.y * 128, n0 = blockIdx.x * 128, z = blockIdx.z;

    const int kc  = K >> 6;
    const int nch = TWO ? 2 * kc : kc;

    float d[FM][4][4];
    #pragma unroll
    for (int f = 0; f < FM; f++)
        #pragma unroll
        for (int g = 0; g < 4; g++)
            #pragma unroll
            for (int e = 0; e < 4; e++) d[f][g][e] = 0.f;

    auto load_chunk = [&](int c) {
        const bool sec = TWO && (c >= kc);
        const int koff = (sec ? c - kc : c) << 6;
        const int buf = c % NSTAGE;
        const uint32_t smA = smb + buf * BUFB;
        const uint32_t smB = smA + ATILEB;
        {
            const __nv_bfloat16* pH = (sec ? A2hi : Ahi) + (long long)z * sA;
            #pragma unroll
            for (int i = 0; i < 4; i++) {
                const int idx = tid + 256 * i;
                const int r = idx >> 3, s = idx & 7;
                cp16(smA + r * ROWB + s * 16,
                     pH + (long long)(m0 + r) * K + koff + s * 8);
            }
        }
        {
            const __nv_bfloat16* pH = (sec ? B2hi : Bhi) + (long long)z * sB;
            #pragma unroll
            for (int i = 0; i < 4; i++) {
                const int idx = tid + 256 * i;
                const int r = idx >> 3, s = idx & 7;
                cp16(smB + r * ROWB + s * 16,
                     pH + (long long)(n0 + r) * K + koff + s * 8);
            }
        }
        asm volatile("cp.async.commit_group;");
    };

    LDM_SETUP

    auto compute_chunk = [&](int c) {
        const uint32_t a_base = smb + (c % NSTAGE) * BUFB;
        const uint32_t b_base = a_base + ATILEB;
        #pragma unroll
        for (int st = 0; st < 4; ++st) {
            const int k = st * 16;
            uint32_t a[FM][4], b[4][2];
            #pragma unroll
            for (int f = 0; f < FM; f++) {
                const uint32_t addr = a_base
                    + (uint32_t)((wm * 64 + f * 16 + a_dm + lrow) * ROWB + (k + a_dk) * 2);
                ldm_x4(a[f][0], a[f][1], a[f][2], a[f][3], addr);
            }
            #pragma unroll
            for (int gp = 0; gp < 2; gp++) {
                const uint32_t addr = b_base
                    + (uint32_t)((wn * 32 + gp * 16 + b_dn + lrow) * ROWB + (k + b_dk) * 2);
                ldm_x4(b[2*gp][0], b[2*gp][1], b[2*gp+1][0], b[2*gp+1][1], addr);
            }
            #pragma unroll
            for (int f = 0; f < FM; f++)
                #pragma unroll
                for (int g = 0; g < 4; g++)
                    mma_bf16(d[f][g], a[f], b[g]);
        }
    };

    load_chunk(0);
    if (nch > 1) load_chunk(1);
    for (int c = 0; c < nch; ++c) {
        if (c + 1 < nch) asm volatile("cp.async.wait_group 1;");
        else             asm volatile("cp.async.wait_group 0;");
        __syncthreads();
        if (c + 2 < nch) load_chunk(c + 2);
        compute_chunk(c);
    }

    const int qr = lane >> 2, qc = 2 * (lane & 3);
    #pragma unroll
    for (int f = 0; f < FM; f++) {
        #pragma unroll
        for (int g = 0; g < 4; g++) {
            const int cc = n0 + wn * 32 + g * 8 + qc;
            float bx = 0.f, by = 0.f;
            if (bias) { bx = bias[cc]; by = bias[cc + 1]; }
            #pragma unroll
            for (int h = 0; h < 2; h++) {
                const int row = m0 + wm * 64 + f * 16 + qr + h * 8;
                if (row >= M) continue;
                float v0 = d[f][g][2 * h]     + bx;
                float v1 = d[f][g][2 * h + 1] + by;
                if (ACT == 1) { v0 = eluf(v0); v1 = eluf(v1); }
                else if (ACT == 2) { v0 = tanhf(v0); v1 = tanhf(v1); }
                const long long o = (long long)z * sC + (long long)row * ldc + cc;
                if constexpr (OUTB == 0) {
                    *reinterpret_cast<float2*>(Cf + o) = make_float2(v0, v1);
                } else if constexpr (OUTB == 1) {
                    *reinterpret_cast<__nv_bfloat162*>(Chi + o) = __floats2bfloat162_rn(v0, v1);
                } else {
                    __nv_bfloat162 hb = __floats2bfloat162_rn(v0, v1);
                    float2 hf = __bfloat1622float2(hb);
                    __nv_bfloat162 lb = __floats2bfloat162_rn(v0 - hf.x, v1 - hf.y);
                    *reinterpret_cast<__nv_bfloat162*>(Chi + o) = hb;
                    *reinterpret_cast<__nv_bfloat162*>(Clo + o) = lb;
                }
            }
        }
    }
}

// ==================================================================
// Prologue uber-GEMM (fp32 A with gather -> bf16), MT=64, pair-loop.
// tk CTAs also emit the transposed tile via smem staging (replaces
// the standalone transpose_tk kernel).
// Grid 320 CTAs: [0,32) dh, [32,64) headq, [64,320) tk
// ==================================================================
#define STG_LD 136   // staging row stride (bf16 elems)
__global__ void __launch_bounds__(256, 2) gemm_pro(
    const float* __restrict__ dec_out, const float* __restrict__ emb,
    const int* __restrict__ head, const int* __restrict__ tail,
    const __nv_bfloat16* __restrict__ wT_hi,
    float* __restrict__ dh, float* __restrict__ headq,
    __nv_bfloat16* __restrict__ tk_hi, __nv_bfloat16* __restrict__ tkT_hi,
    const float* __restrict__ b_tk)
{
    constexpr int FM = 2;
    extern __shared__ char sm[];
    const uint32_t smb = smem_u32(sm);
    const int tid = threadIdx.x, wid = tid >> 5, lane = tid & 31;
    const int wm = wid >> 2, wn = wid & 3;

    const int bid = blockIdx.x;
    const float* Af; const int* gidx; long long boff; float* Cf; int ldc;
    int m0, n0; int outb, act; const float* bias;
    if (bid < 32) {
        Af = dec_out; gidx = nullptr; boff = 0;
        Cf = dh; ldc = 1024; outb = 0; act = 0; bias = nullptr;
        n0 = (bid & 7) * 128; m0 = (bid >> 3) * 64;
    } else if (bid < 64) {
        const int t = bid - 32;
        Af = emb; gidx = head; boff = 2LL * 512 * 512;
        Cf = headq; ldc = 512; outb = 0; act = 0; bias = nullptr;
        n0 = (t & 3) * 128; m0 = (t >> 2) * 64;
    } else {
        const int t = bid - 64;
        Af = emb; gidx = tail; boff = 3LL * 512 * 512;
        Cf = nullptr; ldc = 512; outb = 1; act = 1; bias = b_tk;
        n0 = (t & 3) * 128; m0 = (t >> 2) * 64;
    }
    const __nv_bfloat16* Bhi = wT_hi + boff;
    const int K = 512, np = 4;

    float d[FM][4][4];
    #pragma unroll
    for (int f = 0; f < FM; f++)
        #pragma unroll
        for (int g = 0; g < 4; g++)
            #pragma unroll
            for (int e = 0; e < 4; e++) d[f][g][e] = 0.f;

    auto load_chunk = [&](int c) {
        const int koff = c << 6;
        const int buf = c & 3;
        const uint32_t smA = smb + buf * PBUFB;
        const uint32_t smB = smA + PATILEB;
        char* smAp = sm + buf * PBUFB;
        #pragma unroll
        for (int i = 0; i < 4; i++) {
            const int idx = tid + 256 * i;          // 0..1023
            const int r = idx >> 4, s = idx & 15;
            const int gm = m0 + r;
            const long long row = gidx ? (long long)gidx[gm] : (long long)gm;
            float4 v = *reinterpret_cast<const float4*>(Af + row * K + koff + s * 4);
            uint2 uh;
            __nv_bfloat162 h01 = __floats2bfloat162_rn(v.x, v.y);
            __nv_bfloat162 h23 = __floats2bfloat162_rn(v.z, v.w);
            uh.x = *(uint32_t*)&h01; uh.y = *(uint32_t*)&h23;
            *reinterpret_cast<uint2*>(smAp + r * ROWB + s * 8) = uh;
        }
        #pragma unroll
        for (int i = 0; i < 4; i++) {
            const int idx = tid + 256 * i;
            const int r = idx >> 3, s = idx & 7;
            cp16(smB + r * ROWB + s * 16,
                 Bhi + (long long)(n0 + r) * K + koff + s * 8);
        }
    };
    auto load_pair = [&](int p) {
        load_chunk(2 * p);
        load_chunk(2 * p + 1);
        asm volatile("cp.async.commit_group;");
    };

    LDM_SETUP

    auto compute_chunk = [&](int c) {
        const uint32_t a_base = smb + (c & 3) * PBUFB;
        const uint32_t b_base = a_base + PATILEB;
        #pragma unroll
        for (int st = 0; st < 4; ++st) {
            const int k = st * 16;
            uint32_t a[FM][4], b[4][2];
            #pragma unroll
            for (int f = 0; f < FM; f++) {
                const uint32_t addr = a_base
                    + (uint32_t)((wm * 32 + f * 16 + a_dm + lrow) * ROWB + (k + a_dk) * 2);
                ldm_x4(a[f][0], a[f][1], a[f][2], a[f][3], addr);
            }
            #pragma unroll
            for (int gp = 0; gp < 2; gp++) {
                const uint32_t addr = b_base
                    + (uint32_t)((wn * 32 + gp * 16 + b_dn + lrow) * ROWB + (k + b_dk) * 2);
                ldm_x4(b[2*gp][0], b[2*gp][1], b[2*gp+1][0], b[2*gp+1][1], addr);
            }
            #pragma unroll
            for (int f = 0; f < FM; f++)
                #pragma unroll
                for (int g = 0; g < 4; g++)
                    mma_bf16(d[f][g], a[f], b[g]);
        }
    };

    load_pair(0);
    for (int p = 0; p < np; ++p) {
        asm volatile("cp.async.wait_group 0;");
        __syncthreads();
        if (p + 1 < np) load_pair(p + 1);
        compute_chunk(2 * p);
        compute_chunk(2 * p + 1);
    }

    __nv_bfloat16* stg = reinterpret_cast<__nv_bfloat16*>(sm);  // 64 x STG_LD (17408 B)

    const int qr = lane >> 2, qc = 2 * (lane & 3);
    #pragma unroll
    for (int f = 0; f < FM; f++) {
        #pragma unroll
        for (int g = 0; g < 4; g++) {
            const int cc = n0 + wn * 32 + g * 8 + qc;
            float bx = 0.f, by = 0.f;
            if (bias) { bx = bias[cc]; by = bias[cc + 1]; }
            #pragma unroll
            for (int h = 0; h < 2; h++) {
                const int row = m0 + wm * 32 + f * 16 + qr + h * 8;
                float v0 = d[f][g][2 * h]     + bx;
                float v1 = d[f][g][2 * h + 1] + by;
                if (act == 1) { v0 = eluf(v0); v1 = eluf(v1); }
                if (!outb) {
                    *reinterpret_cast<float2*>(Cf + (long long)row * ldc + cc) = make_float2(v0, v1);
                } else {
                    const __nv_bfloat162 hb = __floats2bfloat162_rn(v0, v1);
                    *reinterpret_cast<__nv_bfloat162*>(tk_hi + (long long)row * 512 + cc) = hb;
                    const int lr = row - m0, lc = cc - n0;
                    stg[lr * STG_LD + lc]     = __low2bfloat16(hb);
                    stg[lr * STG_LD + lc + 1] = __high2bfloat16(hb);
                }
            }
        }
    }

    if (outb) {
        __syncthreads();
        // write transposed tile: tkT[(n0+n)][m0 + m], 128 B per n-row
        for (int n = wid; n < 128; n += 8) {
            __nv_bfloat162 pr;
            pr.x = stg[(2 * lane)     * STG_LD + n];
            pr.y = stg[(2 * lane + 1) * STG_LD + n];
            *reinterpret_cast<__nv_bfloat162*>(
                tkT_hi + (long long)(n0 + n) * 512 + m0 + 2 * lane) = pr;
        }
    }
}

// ---------------- weights: transpose 512x512 fp32 -> bf16 ----------------
struct WPtrs { const float* s[9]; };
__global__ void prep_weights(WPtrs wp, __nv_bfloat16* __restrict__ dhi)
{
    __shared__ float t[32][33];
    const int mtx = blockIdx.z;
    const float* src = wp.s[mtx];
    __nv_bfloat16* oh = dhi + (long long)mtx * 512 * 512;
    const int tx = threadIdx.x, ty = threadIdx.y;
    const int bx = blockIdx.x * 32, by = blockIdx.y * 32;
    #pragma unroll
    for (int i = 0; i < 32; i += 8)
        t[ty + i][tx] = src[(long long)(by + ty + i) * 512 + bx + tx];
    __syncthreads();
    #pragma unroll
    for (int i = 0; i < 32; i += 8)
        oh[(long long)(bx + ty + i) * 512 + by + tx] = __float2bfloat16(t[tx][ty + i]);
}

// ---------------- history small GEMM ----------------
__global__ void hist_small(const float* __restrict__ hist,
                           const __nv_bfloat16* __restrict__ w7h,
                           const __nv_bfloat16* __restrict__ w8h,
                           float* __restrict__ out)
{
    const int wid = threadIdx.x >> 5, lane = threadIdx.x & 31;
    const int c = blockIdx.x * 8 + wid;
    const __nv_bfloat16* rh = (c < 512) ? w7h + (long long)c * 512 : w8h + (long long)(c - 512) * 512;
    float acc[8] = {0.f,0.f,0.f,0.f,0.f,0.f,0.f,0.f};
    #pragma unroll 4
    for (int i = 0; i < 16; i++) {
        const int k = lane + i * 32;
        const float w = __bfloat162float(rh[k]);
        #pragma unroll
        for (int r = 0; r < 8; r++) acc[r] = fmaf(hist[r * 512 + k], w, acc[r]);
    }
    #pragma unroll
    for (int r = 0; r < 8; r++) {
        float v = acc[r];
        #pragma unroll
        for (int o = 16; o; o >>= 1) v += __shfl_xor_sync(0xffffffffu, v, o);
        if (lane == 0) out[r * 1024 + c] = v;
    }
}

// ---------------- mask dtype detector ----------------
__global__ void detect_mask_kernel(const unsigned int* __restrict__ adj, int nwords)
{
    __shared__ unsigned int s;
    if (threadIdx.x == 0) s = 0u;
    __syncthreads();
    unsigned int local = 0u;
    for (int i = threadIdx.x; i < nwords; i += blockDim.x)
        local |= (adj[i] > 1u) ? 1u : 0u;
    if (local) atomicOr(&s, 1u);
    __syncthreads();
    if (threadIdx.x == 0) g_mask_byte_mode = s;
}

// ---------------- tq = elu(decp + histp + headq + b_tq) -> bf16 ----------------
__global__ void build_tq(const float4* __restrict__ dh, const float4* __restrict__ hh,
                         const float4* __restrict__ headq, const float4* __restrict__ btq,
                         __nv_bfloat162* __restrict__ thi)
{
    const int i = blockIdx.x * 256 + threadIdx.x;
    const int d  = i & 127;
    const int h  = (i >> 7) & 63;
    const int bs = i >> 13;
    const int b  = bs >> 5;
    float4 a = dh[bs * 256 + d];
    float4 c = hh[b * 256 + d];
    float4 e = headq[(b * 64 + h) * 128 + d];
    float4 g = btq[d];
    float4 r;
    r.x = eluf(a.x + c.x + e.x + g.x);
    r.y = eluf(a.y + c.y + e.y + g.y);
    r.z = eluf(a.z + c.z + e.z + g.z);
    r.w = eluf(a.w + c.w + e.w + g.w);
    thi[2 * i]     = __floats2bfloat162_rn(r.x, r.y);
    thi[2 * i + 1] = __floats2bfloat162_rn(r.z, r.w);
}

// ---------------- hq = elu(hqd + hqh + b_hq) (cols 512:1024) ----------------
__global__ void build_hq(const float4* __restrict__ dh, const float4* __restrict__ hh,
                         const float4* __restrict__ bhq, float4* __restrict__ hq)
{
    const int i = blockIdx.x * 256 + threadIdx.x;
    const int d  = i & 127;
    const int bs = i >> 7;
    const int b  = bs >> 5;
    float4 a = dh[bs * 256 + 128 + d];
    float4 c = hh[b * 256 + 128 + d];
    float4 g = bhq[d];
    float4 r;
    r.x = eluf(a.x + c.x + g.x);
    r.y = eluf(a.y + c.y + g.y);
    r.z = eluf(a.z + c.z + g.z);
    r.w = eluf(a.w + c.w + g.w);
    hq[i] = r;
}

// ---------------- masked softmax (scores from bf16 hi/lo; out bf16 hi/lo) ----------------
__global__ void masked_softmax(const __nv_bfloat16* __restrict__ schi,
                               const __nv_bfloat16* __restrict__ sclo,
                               __nv_bfloat16* __restrict__ ahi, __nv_bfloat16* __restrict__ alo,
                               const void* __restrict__ adj, const void* __restrict__ dup)
{
    const int q = blockIdx.x;
    const int b = blockIdx.y;
    const int s = q >> 6, h = q & 63;
    const long long ro = ((long long)(b * 2048 + q)) * 512;
    const long long aoff = ((long long)(b * 64 + h)) * 512;
    const long long doff = ((long long)(b * 32 + s)) * 512;

    const unsigned int byte_mode = g_mask_byte_mode;
    const unsigned char* am8 = (const unsigned char*)adj + aoff;
    const unsigned char* dm8 = (const unsigned char*)dup + doff;
    const int* am32 = (const int*)adj + aoff;
    const int* dm32 = (const int*)dup + doff;

    const int tid = threadIdx.x;
    float v[2]; int mk[2];
    float lmax = -FLT_MAX;
    #pragma unroll
    for (int j = 0; j < 2; j++) {
        const int t = tid + j * 256;
        if (byte_mode) mk[j] = am8[t]  && !dm8[t];
        else           mk[j] = am32[t] && !dm32[t];
        v[j] = __bfloat162float(schi[ro + t]) + __bfloat162float(sclo[ro + t]);
        if (mk[j]) lmax = fmaxf(lmax, v[j]);
    }
    __shared__ float smax[8], ssum[8];
    #pragma unroll
    for (int o = 16; o; o >>= 1) lmax = fmaxf(lmax, __shfl_xor_sync(0xffffffffu, lmax, o));
    if ((tid & 31) == 0) smax[tid >> 5] = lmax;
    __syncthreads();
    float bmax = -FLT_MAX;
    #pragma unroll
    for (int w = 0; w < 8; w++) bmax = fmaxf(bmax, smax[w]);

    float e[2], lsum = 0.f;
    #pragma unroll
    for (int j = 0; j < 2; j++) { e[j] = mk[j] ? expf(v[j] - bmax) : 0.f; lsum += e[j]; }
    #pragma unroll
    for (int o = 16; o; o >>= 1) lsum += __shfl_xor_sync(0xffffffffu, lsum, o);
    if ((tid & 31) == 0) ssum[tid >> 5] = lsum;
    __syncthreads();
    float bsum = 0.f;
    #pragma unroll
    for (int w = 0; w < 8; w++) bsum += ssum[w];

    const float inv = 1.f / bsum;
    #pragma unroll
    for (int j = 0; j < 2; j++) {
        const int t = tid + j * 256;
        const float p = e[j] * inv;
        const __nv_bfloat16 hb = __float2bfloat16(p);
        ahi[ro + t] = hb;
        alo[ro + t] = __float2bfloat16(p - __bfloat162float(hb));
    }
}

// ---------------- final: head attention + prob + log (vectorized bf16x2) ----------------
__global__ void final_kernel(const float* __restrict__ hq,
                             const __nv_bfloat16* __restrict__ hk,
                             const __nv_bfloat16* __restrict__ athi,
                             const __nv_bfloat16* __restrict__ atlo,
                             const int* __restrict__ head, float* __restrict__ out)
{
    const int n = blockIdx.x;
    const int b = n >> 5;
    const int tid = threadIdx.x;

    __shared__ float shq[512];
    __shared__ float sc[64];
    __shared__ float sw[64];
    __shared__ int   s_len;

    if (tid == 0) s_len = 0;
    shq[tid]       = hq[(long long)n * 512 + tid];
    shq[tid + 256] = hq[(long long)n * 512 + 256 + tid];
    __syncthreads();
    if (tid < 64) { if (head[b * 64 + tid] != 0) atomicAdd(&s_len, 1); }
    __syncthreads();

    const int w = tid >> 5, lane = tid & 31;
    for (int k = w; k < 64; k += 8) {
        const __nv_bfloat162* hkr = reinterpret_cast<const __nv_bfloat162*>(
            hk + ((long long)n * 64 + k) * 512);
        float sacc = 0.f;
        #pragma unroll 4
        for (int dd = lane; dd < 256; dd += 32) {
            const float2 hv = __bfloat1622float2(hkr[dd]);
            sacc = fmaf(shq[2 * dd], hv.x, sacc);
            sacc = fmaf(shq[2 * dd + 1], hv.y, sacc);
        }
        #pragma unroll
        for (int o = 16; o; o >>= 1) sacc += __shfl_xor_sync(0xffffffffu, sacc, o);
        if (lane == 0) sc[k] = sacc;
    }
    __syncthreads();

    if (tid == 0) {
        const int len = s_len;
        float mx = -FLT_MAX;
        for (int k = 0; k < len; k++) mx = fmaxf(mx, sc[k]);
        float sum = 0.f;
        for (int k = 0; k < 64; k++) {
            float e = (k < len) ? expf(sc[k] - mx) : 0.f;
            sw[k] = e; sum += e;
        }
        float inv = 1.f / sum;
        for (int k = 0; k < 64; k++) sw[k] *= inv;
    }
    __syncthreads();

    // 2 outputs per thread via bf16x2 loads
    const long long base2 = (long long)n * 64 * 256;  // in bf16x2 units
    const int t2 = tid;                                // 0..255 -> cols 2t, 2t+1
    const __nv_bfloat162* ph = reinterpret_cast<const __nv_bfloat162*>(athi) + base2 + t2;
    const __nv_bfloat162* pl = reinterpret_cast<const __nv_bfloat162*>(atlo) + base2 + t2;
    float p0 = 0.f, p1 = 0.f;
    #pragma unroll 8
    for (int k = 0; k < 64; k++) {
        const float2 ah = __bfloat1622float2(ph[k * 256]);
        const float2 al = __bfloat1622float2(pl[k * 256]);
        p0 = fmaf(sw[k], ah.x + al.x, p0);
        p1 = fmaf(sw[k], ah.y + al.y, p1);
    }
    float2 res;
    res.x = logf(p0 + 1e-20f);
    res.y = logf(p1 + 1e-20f);
    *reinterpret_cast<float2*>(out + (long long)n * 512 + 2 * t2) = res;
}

// ---------------- launch ----------------
extern "C" void kernel_launch(void* const* d_in, const int* in_sizes, int n_in,
                              void* d_out, int out_size)
{
    const float* dec_out = (const float*)d_in[0];
    const float* history = (const float*)d_in[1];
    const int*   head    = (const int*)  d_in[2];
    const int*   tail    = (const int*)  d_in[3];
    const void*  adj     = d_in[4];
    const void*  dup     = d_in[5];
    const float* emb     = (const float*)d_in[6];
    const float* W_tq    = (const float*)d_in[7];
    const float* b_tq    = (const float*)d_in[8];
    const float* W_tk    = (const float*)d_in[9];
    const float* b_tk    = (const float*)d_in[10];
    const float* W_tout  = (const float*)d_in[11];
    const float* W_hq    = (const float*)d_in[12];
    const float* b_hq    = (const float*)d_in[13];
    const float* W_hk    = (const float*)d_in[14];
    const float* b_hk    = (const float*)d_in[15];

    float *dh, *hh, *headq, *hkbuf, *hq;
    __nv_bfloat16 *tq_hi, *tk_hi, *tkT_hi, *at_hi, *at_lo, *ctx_hi, *gh_hi, *wT_hi;
    cudaGetSymbolAddress((void**)&dh,     g_dh);
    cudaGetSymbolAddress((void**)&hh,     g_hh);
    cudaGetSymbolAddress((void**)&headq,  g_headq);
    cudaGetSymbolAddress((void**)&hkbuf,  g_hk);
    cudaGetSymbolAddress((void**)&hq,     g_hq);
    cudaGetSymbolAddress((void**)&tq_hi,  g_tq_hi);
    cudaGetSymbolAddress((void**)&tk_hi,  g_tk_hi);
    cudaGetSymbolAddress((void**)&tkT_hi, g_tkT_hi);
    cudaGetSymbolAddress((void**)&at_hi,  g_at_hi);
    cudaGetSymbolAddress((void**)&at_lo,  g_at_lo);
    cudaGetSymbolAddress((void**)&ctx_hi, g_ctx_hi);
    cudaGetSymbolAddress((void**)&gh_hi,  g_gh_hi);
    cudaGetSymbolAddress((void**)&wT_hi,  g_wT_hi);

    __nv_bfloat16* sc_hi = gh_hi;
    __nv_bfloat16* sc_lo = (__nv_bfloat16*)hkbuf;
    __nv_bfloat16* hkb   = (__nv_bfloat16*)hkbuf;

    cudaFuncSetAttribute(gemm_pro,            cudaFuncAttributeMaxDynamicSharedMemorySize, SMEM_BYTES);
    cudaFuncSetAttribute(gemm_mma<0,false,2>, cudaFuncAttributeMaxDynamicSharedMemorySize, SMEM_BYTES);
    cudaFuncSetAttribute(gemm_mma<0,false,1>, cudaFuncAttributeMaxDynamicSharedMemorySize, SMEM_BYTES);
    cudaFuncSetAttribute(gemm_mma<2,true ,1>, cudaFuncAttributeMaxDynamicSharedMemorySize, SMEM_BYTES);
    cudaFuncSetAttribute(gemm_mma<1,false,1>, cudaFuncAttributeMaxDynamicSharedMemorySize, SMEM_BYTES);

    // weight slots: 0 Wd, 1 Whq0 (merged N=1024), 2 We, 3 Wtk, 4 Wtout0, 5 Wtout1,
    //               6 Whk, 7 Wh, 8 Whq1
    WPtrs wp;
    wp.s[0] = W_tq;               wp.s[1] = W_hq;               wp.s[2] = W_tq + 1024LL*512;
    wp.s[3] = W_tk;               wp.s[4] = W_tout;             wp.s[5] = W_tout + 512LL*512;
    wp.s[6] = W_hk;               wp.s[7] = W_tq + 512LL*512;   wp.s[8] = W_hq + 512LL*512;
    #define WTH(i) (wT_hi + (long long)(i)*512*512)

    detect_mask_kernel<<<1, 256>>>((const unsigned int*)adj, 65536);
    prep_weights<<<dim3(16,16,9), dim3(32,8)>>>(wp, wT_hi);

    hist_small<<<128, 256>>>(history, WTH(7), WTH(8), hh);
    gemm_pro<<<320, 256, SMEM_BYTES>>>(dec_out, emb, head, tail, wT_hi,
                                       dh, headq, tk_hi, tkT_hi, b_tk);
    build_tq<<<8192, 256>>>((const float4*)dh, (const float4*)hh,
                            (const float4*)headq, (const float4*)b_tq,
                            (__nv_bfloat162*)tq_hi);
    // scores[b] = tq[b] @ tk[b]^T -> bf16 hi/lo
    gemm_mma<0,false,2><<<dim3(4,16,8), 256, SMEM_BYTES>>>(
        tq_hi, tk_hi, nullptr, nullptr,
        nullptr, sc_hi, sc_lo, nullptr, 2048, 512,
        2048LL*512, 512LL*512, 2048LL*512, 512);
    masked_softmax<<<dim3(2048,8), 256>>>(sc_hi, sc_lo, at_hi, at_lo, adj, dup);
    // ctx[b] = attn[b] @ tk[b] -> bf16
    gemm_mma<0,false,1><<<dim3(4,16,8), 256, SMEM_BYTES>>>(
        at_hi, tkT_hi, nullptr, nullptr,
        nullptr, ctx_hi, nullptr, nullptr, 2048, 512,
        2048LL*512, 512LL*512, 2048LL*512, 512);
    // ghid = tanh(ctx @ Wtout0 + tq @ Wtout1) -> bf16 (overwrites sc_hi)
    gemm_mma<2,true,1><<<dim3(4,128,1), 256, SMEM_BYTES>>>(
        ctx_hi, WTH(4), tq_hi, WTH(5),
        nullptr, gh_hi, nullptr, nullptr, 16384, 512, 0, 0, 0, 512);
    // hk = elu(ghid @ Whk + b_hk) -> bf16 (overwrites sc_lo space)
    gemm_mma<1,false,1><<<dim3(4,128,1), 256, SMEM_BYTES>>>(
        gh_hi, WTH(6), nullptr, nullptr,
        nullptr, hkb, nullptr, b_hk, 16384, 512, 0, 0, 0, 512);
    build_hq<<<128, 256>>>((const float4*)dh, (const float4*)hh,
                           (const float4*)b_hq, (float4*)hq);
    final_kernel<<<256, 256>>>(hq, hkb, at_hi, at_lo, head, (float*)d_out);
}

// round 16
// speedup vs baseline: 1.7991x; 1.0096x over previous
#include <cuda_runtime.h>
#include <cuda_bf16.h>
#include <math.h>
#include <float.h>
#include <stdint.h>

// Problem dims: B=8, S=32, HN=64, TN=512, HID=EMB=512
// ---------------- scratch (device globals; no allocation) ----------------
__device__ float g_dh  [256 * 1024];            // [.,0:512)=decp  [.,512:1024)=hqd
__device__ float g_hh  [8   * 1024];            // [.,0:512)=histp [.,512:1024)=hqh
__device__ float g_headq[512  * 512];
__device__ float g_hk   [16384LL*512];          // scores_lo (bf16) early, hk (bf16) late
__device__ float g_hq   [256 * 512];
__device__ __nv_bfloat16 g_tq_hi [8LL*2048*512];
__device__ __nv_bfloat16 g_tk_hi [4096LL*512];
__device__ __nv_bfloat16 g_tkT_hi[4096LL*512];
__device__ __nv_bfloat16 g_at_hi [8LL*2048*512], g_at_lo [8LL*2048*512];
__device__ __nv_bfloat16 g_ctx_hi[8LL*2048*512];
__device__ __nv_bfloat16 g_gh_hi [8LL*2048*512];   // scores_hi early, ghid late
__device__ __nv_bfloat16 g_wT_hi [9LL*512*512];
__device__ uint32_t g_adj_bits[8 * 64 * 16];
__device__ uint32_t g_dup_bits[8 * 32 * 16];
__device__ unsigned int g_mask_byte_mode;

__device__ __forceinline__ uint32_t smem_u32(const void* p) {
    uint32_t a;
    asm("{ .reg .u64 t; cvta.to.shared.u64 t, %1; cvt.u32.u64 %0, t; }" : "=r"(a) : "l"(p));
    return a;
}
__device__ __forceinline__ void cp16(uint32_t dst, const void* src) {
    asm volatile("cp.async.cg.shared.global [%0], [%1], 16;" :: "r"(dst), "l"(src));
}
__device__ __forceinline__ void mma_bf16(float* d, const uint32_t* a, const uint32_t* b) {
    asm volatile("mma.sync.aligned.m16n8k16.row.col.f32.bf16.bf16.f32 "
        "{%0,%1,%2,%3}, {%4,%5,%6,%7}, {%8,%9}, {%0,%1,%2,%3};"
        : "+f"(d[0]), "+f"(d[1]), "+f"(d[2]), "+f"(d[3])
        : "r"(a[0]), "r"(a[1]), "r"(a[2]), "r"(a[3]), "r"(b[0]), "r"(b[1]));
}
__device__ __forceinline__ void ldm_x4(uint32_t& r0, uint32_t& r1, uint32_t& r2, uint32_t& r3,
                                       uint32_t addr) {
    asm volatile("ldmatrix.sync.aligned.m8n8.x4.shared.b16 {%0,%1,%2,%3}, [%4];"
        : "=r"(r0), "=r"(r1), "=r"(r2), "=r"(r3) : "r"(addr));
}
__device__ __forceinline__ float eluf(float x) { return x > 0.f ? x : expm1f(x); }

// ---- big-GEMM smem: 3 buffers; each = A(128x144B)+B(128x144B) ----
#define ROWB   144
#define ATILEB (128 * ROWB)          // 18432
#define BTILEB (128 * ROWB)          // 18432
#define BUFB   (ATILEB + BTILEB)     // 36864
#define NSTAGE 3
#define SMEM_BYTES (NSTAGE * BUFB)   // 110592 -> 2 CTAs/SM
// ---- pro smem: 4 buffers; each = A(64x144B)+B(128x144B) ----
#define PATILEB (64 * ROWB)          // 9216
#define PBUFB   (PATILEB + BTILEB)   // 27648

#define LDM_SETUP \
    const int lrow = lane & 7, lsel = lane >> 3; \
    const int a_dm = (lsel & 1) << 3, a_dk = (lsel >> 1) << 3; \
    const int b_dn = (lsel >> 1) << 3, b_dk = (lsel & 1) << 3;

// ==================================================================
// Single-bf16 GEMM; MT=128; K-chunk 64; 3-stage loop.
// OUTB: 0 = fp32 out, 1 = bf16 out, 2 = bf16 hi + residual lo out
// ==================================================================
template<int ACT, bool TWO, int OUTB>
__global__ void __launch_bounds__(256, 2) gemm_mma(
    const __nv_bfloat16* __restrict__ Ahi,
    const __nv_bfloat16* __restrict__ Bhi,
    const __nv_bfloat16* __restrict__ A2hi,
    const __nv_bfloat16* __restrict__ B2hi,
    float* __restrict__ Cf, __nv_bfloat16* __restrict__ Chi, __nv_bfloat16* __restrict__ Clo,
    const float* __restrict__ bias,
    int M, int K, long long sA, long long sB, long long sC, int ldc)
{
    constexpr int FM = 4;
    extern __shared__ char sm[];
    const uint32_t smb = smem_u32(sm);
    const int tid = threadIdx.x, wid = tid >> 5, lane = tid & 31;
    const int wm = wid >> 2, wn = wid & 3;
    const int m0 = blockIdx.y * 128, n0 = blockIdx.x * 128, z = blockIdx.z;

    const int kc  = K >> 6;
    const int nch = TWO ? 2 * kc : kc;

    float d[FM][4][4];
    #pragma unroll
    for (int f = 0; f < FM; f++)
        #pragma unroll
        for (int g = 0; g < 4; g++)
            #pragma unroll
            for (int e = 0; e < 4; e++) d[f][g][e] = 0.f;

    auto load_chunk = [&](int c) {
        const bool sec = TWO && (c >= kc);
        const int koff = (sec ? c - kc : c) << 6;
        const int buf = c % NSTAGE;
        const uint32_t smA = smb + buf * BUFB;
        const uint32_t smB = smA + ATILEB;
        {
            const __nv_bfloat16* pH = (sec ? A2hi : Ahi) + (long long)z * sA;
            #pragma unroll
            for (int i = 0; i < 4; i++) {
                const int idx = tid + 256 * i;
                const int r = idx >> 3, s = idx & 7;
                cp16(smA + r * ROWB + s * 16,
                     pH + (long long)(m0 + r) * K + koff + s * 8);
            }
        }
        {
            const __nv_bfloat16* pH = (sec ? B2hi : Bhi) + (long long)z * sB;
            #pragma unroll
            for (int i = 0; i < 4; i++) {
                const int idx = tid + 256 * i;
                const int r = idx >> 3, s = idx & 7;
                cp16(smB + r * ROWB + s * 16,
                     pH + (long long)(n0 + r) * K + koff + s * 8);
            }
        }
        asm volatile("cp.async.commit_group;");
    };

    LDM_SETUP

    auto compute_chunk = [&](int c) {
        const uint32_t a_base = smb + (c % NSTAGE) * BUFB;
        const uint32_t b_base = a_base + ATILEB;
        #pragma unroll
        for (int st = 0; st < 4; ++st) {
            const int k = st * 16;
            uint32_t a[FM][4], b[4][2];
            #pragma unroll
            for (int f = 0; f < FM; f++) {
                const uint32_t addr = a_base
                    + (uint32_t)((wm * 64 + f * 16 + a_dm + lrow) * ROWB + (k + a_dk) * 2);
                ldm_x4(a[f][0], a[f][1], a[f][2], a[f][3], addr);
            }
            #pragma unroll
            for (int gp = 0; gp < 2; gp++) {
                const uint32_t addr = b_base
                    + (uint32_t)((wn * 32 + gp * 16 + b_dn + lrow) * ROWB + (k + b_dk) * 2);
                ldm_x4(b[2*gp][0], b[2*gp][1], b[2*gp+1][0], b[2*gp+1][1], addr);
            }
            #pragma unroll
            for (int f = 0; f < FM; f++)
                #pragma unroll
                for (int g = 0; g < 4; g++)
                    mma_bf16(d[f][g], a[f], b[g]);
        }
    };

    load_chunk(0);
    if (nch > 1) load_chunk(1);
    for (int c = 0; c < nch; ++c) {
        if (c + 1 < nch) asm volatile("cp.async.wait_group 1;");
        else             asm volatile("cp.async.wait_group 0;");
        __syncthreads();
        if (c + 2 < nch) load_chunk(c + 2);
        compute_chunk(c);
    }

    const int qr = lane >> 2, qc = 2 * (lane & 3);
    #pragma unroll
    for (int f = 0; f < FM; f++) {
        #pragma unroll
        for (int g = 0; g < 4; g++) {
            const int cc = n0 + wn * 32 + g * 8 + qc;
            float bx = 0.f, by = 0.f;
            if (bias) { bx = bias[cc]; by = bias[cc + 1]; }
            #pragma unroll
            for (int h = 0; h < 2; h++) {
                const int row = m0 + wm * 64 + f * 16 + qr + h * 8;
                if (row >= M) continue;
                float v0 = d[f][g][2 * h]     + bx;
                float v1 = d[f][g][2 * h + 1] + by;
                if (ACT == 1) { v0 = eluf(v0); v1 = eluf(v1); }
                else if (ACT == 2) { v0 = tanhf(v0); v1 = tanhf(v1); }
                const long long o = (long long)z * sC + (long long)row * ldc + cc;
                if constexpr (OUTB == 0) {
                    *reinterpret_cast<float2*>(Cf + o) = make_float2(v0, v1);
                } else if constexpr (OUTB == 1) {
                    *reinterpret_cast<__nv_bfloat162*>(Chi + o) = __floats2bfloat162_rn(v0, v1);
                } else {
                    __nv_bfloat162 hb = __floats2bfloat162_rn(v0, v1);
                    float2 hf = __bfloat1622float2(hb);
                    __nv_bfloat162 lb = __floats2bfloat162_rn(v0 - hf.x, v1 - hf.y);
                    *reinterpret_cast<__nv_bfloat162*>(Chi + o) = hb;
                    *reinterpret_cast<__nv_bfloat162*>(Clo + o) = lb;
                }
            }
        }
    }
}

// ==================================================================
// Prologue uber-GEMM (fp32 A with gather -> bf16), MT=64, pair-loop.
// tk CTAs also emit the transposed tile via smem staging.
// Grid 320 CTAs: [0,32) dh, [32,64) headq, [64,320) tk
// ==================================================================
#define STG_LD 136
__global__ void __launch_bounds__(256, 2) gemm_pro(
    const float* __restrict__ dec_out, const float* __restrict__ emb,
    const int* __restrict__ head, const int* __restrict__ tail,
    const __nv_bfloat16* __restrict__ wT_hi,
    float* __restrict__ dh, float* __restrict__ headq,
    __nv_bfloat16* __restrict__ tk_hi, __nv_bfloat16* __restrict__ tkT_hi,
    const float* __restrict__ b_tk)
{
    constexpr int FM = 2;
    extern __shared__ char sm[];
    const uint32_t smb = smem_u32(sm);
    const int tid = threadIdx.x, wid = tid >> 5, lane = tid & 31;
    const int wm = wid >> 2, wn = wid & 3;

    const int bid = blockIdx.x;
    const float* Af; const int* gidx; long long boff; float* Cf; int ldc;
    int m0, n0; int outb, act; const float* bias;
    if (bid < 32) {
        Af = dec_out; gidx = nullptr; boff = 0;
        Cf = dh; ldc = 1024; outb = 0; act = 0; bias = nullptr;
        n0 = (bid & 7) * 128; m0 = (bid >> 3) * 64;
    } else if (bid < 64) {
        const int t = bid - 32;
        Af = emb; gidx = head; boff = 2LL * 512 * 512;
        Cf = headq; ldc = 512; outb = 0; act = 0; bias = nullptr;
        n0 = (t & 3) * 128; m0 = (t >> 2) * 64;
    } else {
        const int t = bid - 64;
        Af = emb; gidx = tail; boff = 3LL * 512 * 512;
        Cf = nullptr; ldc = 512; outb = 1; act = 1; bias = b_tk;
        n0 = (t & 3) * 128; m0 = (t >> 2) * 64;
    }
    const __nv_bfloat16* Bhi = wT_hi + boff;
    const int K = 512, np = 4;

    float d[FM][4][4];
    #pragma unroll
    for (int f = 0; f < FM; f++)
        #pragma unroll
        for (int g = 0; g < 4; g++)
            #pragma unroll
            for (int e = 0; e < 4; e++) d[f][g][e] = 0.f;

    auto load_chunk = [&](int c) {
        const int koff = c << 6;
        const int buf = c & 3;
        const uint32_t smA = smb + buf * PBUFB;
        const uint32_t smB = smA + PATILEB;
        char* smAp = sm + buf * PBUFB;
        #pragma unroll
        for (int i = 0; i < 4; i++) {
            const int idx = tid + 256 * i;
            const int r = idx >> 4, s = idx & 15;
            const int gm = m0 + r;
            const long long row = gidx ? (long long)gidx[gm] : (long long)gm;
            float4 v = *reinterpret_cast<const float4*>(Af + row * K + koff + s * 4);
            uint2 uh;
            __nv_bfloat162 h01 = __floats2bfloat162_rn(v.x, v.y);
            __nv_bfloat162 h23 = __floats2bfloat162_rn(v.z, v.w);
            uh.x = *(uint32_t*)&h01; uh.y = *(uint32_t*)&h23;
            *reinterpret_cast<uint2*>(smAp + r * ROWB + s * 8) = uh;
        }
        #pragma unroll
        for (int i = 0; i < 4; i++) {
            const int idx = tid + 256 * i;
            const int r = idx >> 3, s = idx & 7;
            cp16(smB + r * ROWB + s * 16,
                 Bhi + (long long)(n0 + r) * K + koff + s * 8);
        }
    };
    auto load_pair = [&](int p) {
        load_chunk(2 * p);
        load_chunk(2 * p + 1);
        asm volatile("cp.async.commit_group;");
    };

    LDM_SETUP

    auto compute_chunk = [&](int c) {
        const uint32_t a_base = smb + (c & 3) * PBUFB;
        const uint32_t b_base = a_base + PATILEB;
        #pragma unroll
        for (int st = 0; st < 4; ++st) {
            const int k = st * 16;
            uint32_t a[FM][4], b[4][2];
            #pragma unroll
            for (int f = 0; f < FM; f++) {
                const uint32_t addr = a_base
                    + (uint32_t)((wm * 32 + f * 16 + a_dm + lrow) * ROWB + (k + a_dk) * 2);
                ldm_x4(a[f][0], a[f][1], a[f][2], a[f][3], addr);
            }
            #pragma unroll
            for (int gp = 0; gp < 2; gp++) {
                const uint32_t addr = b_base
                    + (uint32_t)((wn * 32 + gp * 16 + b_dn + lrow) * ROWB + (k + b_dk) * 2);
                ldm_x4(b[2*gp][0], b[2*gp][1], b[2*gp+1][0], b[2*gp+1][1], addr);
            }
            #pragma unroll
            for (int f = 0; f < FM; f++)
                #pragma unroll
                for (int g = 0; g < 4; g++)
                    mma_bf16(d[f][g], a[f], b[g]);
        }
    };

    load_pair(0);
    for (int p = 0; p < np; ++p) {
        asm volatile("cp.async.wait_group 0;");
        __syncthreads();
        if (p + 1 < np) load_pair(p + 1);
        compute_chunk(2 * p);
        compute_chunk(2 * p + 1);
    }

    __nv_bfloat16* stg = reinterpret_cast<__nv_bfloat16*>(sm);

    const int qr = lane >> 2, qc = 2 * (lane & 3);
    #pragma unroll
    for (int f = 0; f < FM; f++) {
        #pragma unroll
        for (int g = 0; g < 4; g++) {
            const int cc = n0 + wn * 32 + g * 8 + qc;
            float bx = 0.f, by = 0.f;
            if (bias) { bx = bias[cc]; by = bias[cc + 1]; }
            #pragma unroll
            for (int h = 0; h < 2; h++) {
                const int row = m0 + wm * 32 + f * 16 + qr + h * 8;
                float v0 = d[f][g][2 * h]     + bx;
                float v1 = d[f][g][2 * h + 1] + by;
                if (act == 1) { v0 = eluf(v0); v1 = eluf(v1); }
                if (!outb) {
                    *reinterpret_cast<float2*>(Cf + (long long)row * ldc + cc) = make_float2(v0, v1);
                } else {
                    const __nv_bfloat162 hb = __floats2bfloat162_rn(v0, v1);
                    *reinterpret_cast<__nv_bfloat162*>(tk_hi + (long long)row * 512 + cc) = hb;
                    const int lr = row - m0, lc = cc - n0;
                    stg[lr * STG_LD + lc]     = __low2bfloat16(hb);
                    stg[lr * STG_LD + lc + 1] = __high2bfloat16(hb);
                }
            }
        }
    }

    if (outb) {
        __syncthreads();
        for (int n = wid; n < 128; n += 8) {
            __nv_bfloat162 pr;
            pr.x = stg[(2 * lane)     * STG_LD + n];
            pr.y = stg[(2 * lane + 1) * STG_LD + n];
            *reinterpret_cast<__nv_bfloat162*>(
                tkT_hi + (long long)(n0 + n) * 512 + m0 + 2 * lane) = pr;
        }
    }
}

// ---------------- weights: transpose 512x512 fp32 -> bf16 ----------------
struct WPtrs { const float* s[9]; };
__global__ void prep_weights(WPtrs wp, __nv_bfloat16* __restrict__ dhi)
{
    __shared__ float t[32][33];
    const int mtx = blockIdx.z;
    const float* src = wp.s[mtx];
    __nv_bfloat16* oh = dhi + (long long)mtx * 512 * 512;
    const int tx = threadIdx.x, ty = threadIdx.y;
    const int bx = blockIdx.x * 32, by = blockIdx.y * 32;
    #pragma unroll
    for (int i = 0; i < 32; i += 8)
        t[ty + i][tx] = src[(long long)(by + ty + i) * 512 + bx + tx];
    __syncthreads();
    #pragma unroll
    for (int i = 0; i < 32; i += 8)
        oh[(long long)(bx + ty + i) * 512 + by + tx] = __float2bfloat16(t[tx][ty + i]);
}

// ---------------- history small GEMM ----------------
__global__ void hist_small(const float* __restrict__ hist,
                           const __nv_bfloat16* __restrict__ w7h,
                           const __nv_bfloat16* __restrict__ w8h,
                           float* __restrict__ out)
{
    const int wid = threadIdx.x >> 5, lane = threadIdx.x & 31;
    const int c = blockIdx.x * 8 + wid;
    const __nv_bfloat16* rh = (c < 512) ? w7h + (long long)c * 512 : w8h + (long long)(c - 512) * 512;
    float acc[8] = {0.f,0.f,0.f,0.f,0.f,0.f,0.f,0.f};
    #pragma unroll 4
    for (int i = 0; i < 16; i++) {
        const int k = lane + i * 32;
        const float w = __bfloat162float(rh[k]);
        #pragma unroll
        for (int r = 0; r < 8; r++) acc[r] = fmaf(hist[r * 512 + k], w, acc[r]);
    }
    #pragma unroll
    for (int r = 0; r < 8; r++) {
        float v = acc[r];
        #pragma unroll
        for (int o = 16; o; o >>= 1) v += __shfl_xor_sync(0xffffffffu, v, o);
        if (lane == 0) out[r * 1024 + c] = v;
    }
}

// ---------------- mask dtype detector ----------------
__global__ void detect_mask_kernel(const unsigned int* __restrict__ adj, int nwords)
{
    __shared__ unsigned int s;
    if (threadIdx.x == 0) s = 0u;
    __syncthreads();
    unsigned int local = 0u;
    for (int i = threadIdx.x; i < nwords; i += blockDim.x)
        local |= (adj[i] > 1u) ? 1u : 0u;
    if (local) atomicOr(&s, 1u);
    __syncthreads();
    if (threadIdx.x == 0) g_mask_byte_mode = s;
}

// ---------------- masks -> bitmasks (both dtype modes) ----------------
// grid 768 blocks x 512 thr: rows [0,512) = adj (b*64+h), [512,768) = dup (b*32+s)
__global__ void mask_bits(const void* __restrict__ adj, const void* __restrict__ dup,
                          uint32_t* __restrict__ abits, uint32_t* __restrict__ dbits)
{
    const int row = blockIdx.x;
    const int tid = threadIdx.x;
    const unsigned byte_mode = g_mask_byte_mode;
    int v;
    if (row < 512) {
        const long long off = (long long)row * 512 + tid;
        v = byte_mode ? (((const unsigned char*)adj)[off] != 0)
                      : (((const int*)adj)[off] != 0);
    } else {
        const long long off = (long long)(row - 512) * 512 + tid;
        v = byte_mode ? (((const unsigned char*)dup)[off] != 0)
                      : (((const int*)dup)[off] != 0);
    }
    const unsigned m = __ballot_sync(0xffffffffu, v);
    if ((tid & 31) == 0) {
        if (row < 512) abits[row * 16 + (tid >> 5)] = m;
        else           dbits[(row - 512) * 16 + (tid >> 5)] = m;
    }
}

// ---------------- tq = elu(decp + histp + headq + b_tq) -> bf16 ----------------
__global__ void build_tq(const float4* __restrict__ dh, const float4* __restrict__ hh,
                         const float4* __restrict__ headq, const float4* __restrict__ btq,
                         __nv_bfloat162* __restrict__ thi)
{
    const int i = blockIdx.x * 256 + threadIdx.x;
    const int d  = i & 127;
    const int h  = (i >> 7) & 63;
    const int bs = i >> 13;
    const int b  = bs >> 5;
    float4 a = dh[bs * 256 + d];
    float4 c = hh[b * 256 + d];
    float4 e = headq[(b * 64 + h) * 128 + d];
    float4 g = btq[d];
    float4 r;
    r.x = eluf(a.x + c.x + e.x + g.x);
    r.y = eluf(a.y + c.y + e.y + g.y);
    r.z = eluf(a.z + c.z + e.z + g.z);
    r.w = eluf(a.w + c.w + e.w + g.w);
    thi[2 * i]     = __floats2bfloat162_rn(r.x, r.y);
    thi[2 * i + 1] = __floats2bfloat162_rn(r.z, r.w);
}

// ---------------- hq = elu(hqd + hqh + b_hq) (cols 512:1024) ----------------
__global__ void build_hq(const float4* __restrict__ dh, const float4* __restrict__ hh,
                         const float4* __restrict__ bhq, float4* __restrict__ hq)
{
    const int i = blockIdx.x * 256 + threadIdx.x;
    const int d  = i & 127;
    const int bs = i >> 7;
    const int b  = bs >> 5;
    float4 a = dh[bs * 256 + 128 + d];
    float4 c = hh[b * 256 + 128 + d];
    float4 g = bhq[d];
    float4 r;
    r.x = eluf(a.x + c.x + g.x);
    r.y = eluf(a.y + c.y + g.y);
    r.z = eluf(a.z + c.z + g.z);
    r.w = eluf(a.w + c.w + g.w);
    hq[i] = r;
}

// ---------------- masked softmax (bitmasks, fully vectorized bf16x2) ----------------
__global__ void masked_softmax(const __nv_bfloat16* __restrict__ schi,
                               const __nv_bfloat16* __restrict__ sclo,
                               __nv_bfloat16* __restrict__ ahi, __nv_bfloat16* __restrict__ alo,
                               const uint32_t* __restrict__ abits,
                               const uint32_t* __restrict__ dbits)
{
    const int q = blockIdx.x;
    const int b = blockIdx.y;
    const int s = q >> 6, h = q & 63;
    const long long ro2 = ((long long)(b * 2048 + q)) * 256;   // bf16x2 units
    const uint32_t* aw = abits + (b * 64 + h) * 16;
    const uint32_t* dw = dbits + (b * 32 + s) * 16;

    const int tid = threadIdx.x;                 // cols 2*tid, 2*tid+1
    const uint32_t w = aw[tid >> 4] & ~dw[tid >> 4];
    const int bp = 2 * (tid & 15);
    const int mk0 = (w >> bp) & 1, mk1 = (w >> (bp + 1)) & 1;

    const float2 sh = __bfloat1622float2(
        reinterpret_cast<const __nv_bfloat162*>(schi)[ro2 + tid]);
    const float2 sl = __bfloat1622float2(
        reinterpret_cast<const __nv_bfloat162*>(sclo)[ro2 + tid]);
    const float v0 = sh.x + sl.x, v1 = sh.y + sl.y;

    float lmax = -FLT_MAX;
    if (mk0) lmax = v0;
    if (mk1) lmax = fmaxf(lmax, v1);

    __shared__ float smax[8], ssum[8];
    #pragma unroll
    for (int o = 16; o; o >>= 1) lmax = fmaxf(lmax, __shfl_xor_sync(0xffffffffu, lmax, o));
    if ((tid & 31) == 0) smax[tid >> 5] = lmax;
    __syncthreads();
    float bmax = -FLT_MAX;
    #pragma unroll
    for (int ww = 0; ww < 8; ww++) bmax = fmaxf(bmax, smax[ww]);

    const float e0 = mk0 ? expf(v0 - bmax) : 0.f;
    const float e1 = mk1 ? expf(v1 - bmax) : 0.f;
    float lsum = e0 + e1;
    #pragma unroll
    for (int o = 16; o; o >>= 1) lsum += __shfl_xor_sync(0xffffffffu, lsum, o);
    if ((tid & 31) == 0) ssum[tid >> 5] = lsum;
    __syncthreads();
    float bsum = 0.f;
    #pragma unroll
    for (int ww = 0; ww < 8; ww++) bsum += ssum[ww];

    const float inv = 1.f / bsum;
    const float p0 = e0 * inv, p1 = e1 * inv;
    const __nv_bfloat162 hb = __floats2bfloat162_rn(p0, p1);
    const float2 hf = __bfloat1622float2(hb);
    const __nv_bfloat162 lb = __floats2bfloat162_rn(p0 - hf.x, p1 - hf.y);
    reinterpret_cast<__nv_bfloat162*>(ahi)[ro2 + tid] = hb;
    reinterpret_cast<__nv_bfloat162*>(alo)[ro2 + tid] = lb;
}

// ---------------- final: head attention + prob + log (vectorized bf16x2) ----------------
__global__ void final_kernel(const float* __restrict__ hq,
                             const __nv_bfloat16* __restrict__ hk,
                             const __nv_bfloat16* __restrict__ athi,
                             const __nv_bfloat16* __restrict__ atlo,
                             const int* __restrict__ head, float* __restrict__ out)
{
    const int n = blockIdx.x;
    const int b = n >> 5;
    const int tid = threadIdx.x;

    __shared__ float shq[512];
    __shared__ float sc[64];
    __shared__ float sw[64];
    __shared__ int   s_len;

    if (tid == 0) s_len = 0;
    shq[tid]       = hq[(long long)n * 512 + tid];
    shq[tid + 256] = hq[(long long)n * 512 + 256 + tid];
    __syncthreads();
    if (tid < 64) { if (head[b * 64 + tid] != 0) atomicAdd(&s_len, 1); }
    __syncthreads();

    const int w = tid >> 5, lane = tid & 31;
    for (int k = w; k < 64; k += 8) {
        const __nv_bfloat162* hkr = reinterpret_cast<const __nv_bfloat162*>(
            hk + ((long long)n * 64 + k) * 512);
        float sacc = 0.f;
        #pragma unroll 4
        for (int dd = lane; dd < 256; dd += 32) {
            const float2 hv = __bfloat1622float2(hkr[dd]);
            sacc = fmaf(shq[2 * dd], hv.x, sacc);
            sacc = fmaf(shq[2 * dd + 1], hv.y, sacc);
        }
        #pragma unroll
        for (int o = 16; o; o >>= 1) sacc += __shfl_xor_sync(0xffffffffu, sacc, o);
        if (lane == 0) sc[k] = sacc;
    }
    __syncthreads();

    if (tid == 0) {
        const int len = s_len;
        float mx = -FLT_MAX;
        for (int k = 0; k < len; k++) mx = fmaxf(mx, sc[k]);
        float sum = 0.f;
        for (int k = 0; k < 64; k++) {
            float e = (k < len) ? expf(sc[k] - mx) : 0.f;
            sw[k] = e; sum += e;
        }
        float inv = 1.f / sum;
        for (int k = 0; k < 64; k++) sw[k] *= inv;
    }
    __syncthreads();

    const long long base2 = (long long)n * 64 * 256;
    const int t2 = tid;
    const __nv_bfloat162* ph = reinterpret_cast<const __nv_bfloat162*>(athi) + base2 + t2;
    const __nv_bfloat162* pl = reinterpret_cast<const __nv_bfloat162*>(atlo) + base2 + t2;
    float p0 = 0.f, p1 = 0.f;
    #pragma unroll 8
    for (int k = 0; k < 64; k++) {
        const float2 ah = __bfloat1622float2(ph[k * 256]);
        const float2 al = __bfloat1622float2(pl[k * 256]);
        p0 = fmaf(sw[k], ah.x + al.x, p0);
        p1 = fmaf(sw[k], ah.y + al.y, p1);
    }
    float2 res;
    res.x = logf(p0 + 1e-20f);
    res.y = logf(p1 + 1e-20f);
    *reinterpret_cast<float2*>(out + (long long)n * 512 + 2 * t2) = res;
}

// ---------------- launch ----------------
extern "C" void kernel_launch(void* const* d_in, const int* in_sizes, int n_in,
                              void* d_out, int out_size)
{
    const float* dec_out = (const float*)d_in[0];
    const float* history = (const float*)d_in[1];
    const int*   head    = (const int*)  d_in[2];
    const int*   tail    = (const int*)  d_in[3];
    const void*  adj     = d_in[4];
    const void*  dup     = d_in[5];
    const float* emb     = (const float*)d_in[6];
    const float* W_tq    = (const float*)d_in[7];
    const float* b_tq    = (const float*)d_in[8];
    const float* W_tk    = (const float*)d_in[9];
    const float* b_tk    = (const float*)d_in[10];
    const float* W_tout  = (const float*)d_in[11];
    const float* W_hq    = (const float*)d_in[12];
    const float* b_hq    = (const float*)d_in[13];
    const float* W_hk    = (const float*)d_in[14];
    const float* b_hk    = (const float*)d_in[15];

    float *dh, *hh, *headq, *hkbuf, *hq;
    __nv_bfloat16 *tq_hi, *tk_hi, *tkT_hi, *at_hi, *at_lo, *ctx_hi, *gh_hi, *wT_hi;
    uint32_t *abits, *dbits;
    cudaGetSymbolAddress((void**)&dh,     g_dh);
    cudaGetSymbolAddress((void**)&hh,     g_hh);
    cudaGetSymbolAddress((void**)&headq,  g_headq);
    cudaGetSymbolAddress((void**)&hkbuf,  g_hk);
    cudaGetSymbolAddress((void**)&hq,     g_hq);
    cudaGetSymbolAddress((void**)&tq_hi,  g_tq_hi);
    cudaGetSymbolAddress((void**)&tk_hi,  g_tk_hi);
    cudaGetSymbolAddress((void**)&tkT_hi, g_tkT_hi);
    cudaGetSymbolAddress((void**)&at_hi,  g_at_hi);
    cudaGetSymbolAddress((void**)&at_lo,  g_at_lo);
    cudaGetSymbolAddress((void**)&ctx_hi, g_ctx_hi);
    cudaGetSymbolAddress((void**)&gh_hi,  g_gh_hi);
    cudaGetSymbolAddress((void**)&wT_hi,  g_wT_hi);
    cudaGetSymbolAddress((void**)&abits,  g_adj_bits);
    cudaGetSymbolAddress((void**)&dbits,  g_dup_bits);

    __nv_bfloat16* sc_hi = gh_hi;
    __nv_bfloat16* sc_lo = (__nv_bfloat16*)hkbuf;
    __nv_bfloat16* hkb   = (__nv_bfloat16*)hkbuf;

    cudaFuncSetAttribute(gemm_pro,            cudaFuncAttributeMaxDynamicSharedMemorySize, SMEM_BYTES);
    cudaFuncSetAttribute(gemm_mma<0,false,2>, cudaFuncAttributeMaxDynamicSharedMemorySize, SMEM_BYTES);
    cudaFuncSetAttribute(gemm_mma<0,false,1>, cudaFuncAttributeMaxDynamicSharedMemorySize, SMEM_BYTES);
    cudaFuncSetAttribute(gemm_mma<2,true ,1>, cudaFuncAttributeMaxDynamicSharedMemorySize, SMEM_BYTES);
    cudaFuncSetAttribute(gemm_mma<1,false,1>, cudaFuncAttributeMaxDynamicSharedMemorySize, SMEM_BYTES);

    // weight slots: 0 Wd, 1 Whq0 (merged N=1024), 2 We, 3 Wtk, 4 Wtout0, 5 Wtout1,
    //               6 Whk, 7 Wh, 8 Whq1
    WPtrs wp;
    wp.s[0] = W_tq;               wp.s[1] = W_hq;               wp.s[2] = W_tq + 1024LL*512;
    wp.s[3] = W_tk;               wp.s[4] = W_tout;             wp.s[5] = W_tout + 512LL*512;
    wp.s[6] = W_hk;               wp.s[7] = W_tq + 512LL*512;   wp.s[8] = W_hq + 512LL*512;
    #define WTH(i) (wT_hi + (long long)(i)*512*512)

    detect_mask_kernel<<<1, 256>>>((const unsigned int*)adj, 65536);
    mask_bits<<<768, 512>>>(adj, dup, abits, dbits);
    prep_weights<<<dim3(16,16,9), dim3(32,8)>>>(wp, wT_hi);

    hist_small<<<128, 256>>>(history, WTH(7), WTH(8), hh);
    gemm_pro<<<320, 256, SMEM_BYTES>>>(dec_out, emb, head, tail, wT_hi,
                                       dh, headq, tk_hi, tkT_hi, b_tk);
    build_tq<<<8192, 256>>>((const float4*)dh, (const float4*)hh,
                            (const float4*)headq, (const float4*)b_tq,
                            (__nv_bfloat162*)tq_hi);
    // scores[b] = tq[b] @ tk[b]^T -> bf16 hi/lo
    gemm_mma<0,false,2><<<dim3(4,16,8), 256, SMEM_BYTES>>>(
        tq_hi, tk_hi, nullptr, nullptr,
        nullptr, sc_hi, sc_lo, nullptr, 2048, 512,
        2048LL*512, 512LL*512, 2048LL*512, 512);
    masked_softmax<<<dim3(2048,8), 256>>>(sc_hi, sc_lo, at_hi, at_lo, abits, dbits);
    // ctx[b] = attn[b] @ tk[b] -> bf16
    gemm_mma<0,false,1><<<dim3(4,16,8), 256, SMEM_BYTES>>>(
        at_hi, tkT_hi, nullptr, nullptr,
        nullptr, ctx_hi, nullptr, nullptr, 2048, 512,
        2048LL*512, 512LL*512, 2048LL*512, 512);
    // ghid = tanh(ctx @ Wtout0 + tq @ Wtout1) -> bf16 (overwrites sc_hi)
    gemm_mma<2,true,1><<<dim3(4,128,1), 256, SMEM_BYTES>>>(
        ctx_hi, WTH(4), tq_hi, WTH(5),
        nullptr, gh_hi, nullptr, nullptr, 16384, 512, 0, 0, 0, 512);
    // hk = elu(ghid @ Whk + b_hk) -> bf16 (overwrites sc_lo space)
    gemm_mma<1,false,1><<<dim3(4,128,1), 256, SMEM_BYTES>>>(
        gh_hi, WTH(6), nullptr, nullptr,
        nullptr, hkb, nullptr, b_hk, 16384, 512, 0, 0, 0, 512);
    build_hq<<<128, 256>>>((const float4*)dh, (const float4*)hh,
                           (const float4*)b_hq, (float4*)hq);
    final_kernel<<<256, 256>>>(hq, hkb, at_hi, at_lo, head, (float*)d_out);
}

// round 17
// speedup vs baseline: 2.5399x; 1.4118x over previous
#include <cuda_runtime.h>
#include <cuda_bf16.h>
#include <math.h>
#include <float.h>
#include <stdint.h>

// Problem dims: B=8, S=32, HN=64, TN=512, HID=EMB=512
// ---------------- scratch (device globals; no allocation) ----------------
__device__ float g_dh  [256 * 1024];            // [.,0:512)=decp  [.,512:1024)=hqd
__device__ float g_hh  [8   * 1024];            // [.,0:512)=histp [.,512:1024)=hqh
__device__ float g_headq[512  * 512];
__device__ float g_hk   [16384LL*512];          // scores_lo (bf16) early, hk (bf16) late
__device__ float g_hq   [256 * 512];
__device__ __nv_bfloat16 g_tq_hi [8LL*2048*512];
__device__ __nv_bfloat16 g_tk_hi [4096LL*512];
__device__ __nv_bfloat16 g_tkT_hi[4096LL*512];
__device__ __nv_bfloat16 g_at_hi [8LL*2048*512], g_at_lo [8LL*2048*512];
__device__ __nv_bfloat16 g_ctx_hi[8LL*2048*512];
__device__ __nv_bfloat16 g_gh_hi [8LL*2048*512];   // scores_hi early, ghid late
__device__ __nv_bfloat16 g_wT_hi [9LL*512*512];
__device__ uint32_t g_adj_bits[8 * 64 * 16];
__device__ uint32_t g_dup_bits[8 * 32 * 16];
__device__ unsigned int g_mask_byte_mode;

__device__ __forceinline__ uint32_t smem_u32(const void* p) {
    uint32_t a;
    asm("{ .reg .u64 t; cvta.to.shared.u64 t, %1; cvt.u32.u64 %0, t; }" : "=r"(a) : "l"(p));
    return a;
}
__device__ __forceinline__ void cp16(uint32_t dst, const void* src) {
    asm volatile("cp.async.cg.shared.global [%0], [%1], 16;" :: "r"(dst), "l"(src));
}
__device__ __forceinline__ void mma_bf16(float* d, const uint32_t* a, const uint32_t* b) {
    asm volatile("mma.sync.aligned.m16n8k16.row.col.f32.bf16.bf16.f32 "
        "{%0,%1,%2,%3}, {%4,%5,%6,%7}, {%8,%9}, {%0,%1,%2,%3};"
        : "+f"(d[0]), "+f"(d[1]), "+f"(d[2]), "+f"(d[3])
        : "r"(a[0]), "r"(a[1]), "r"(a[2]), "r"(a[3]), "r"(b[0]), "r"(b[1]));
}
__device__ __forceinline__ void ldm_x4(uint32_t& r0, uint32_t& r1, uint32_t& r2, uint32_t& r3,
                                       uint32_t addr) {
    asm volatile("ldmatrix.sync.aligned.m8n8.x4.shared.b16 {%0,%1,%2,%3}, [%4];"
        : "=r"(r0), "=r"(r1), "=r"(r2), "=r"(r3) : "r"(addr));
}
__device__ __forceinline__ float eluf(float x) { return x > 0.f ? x : expm1f(x); }

// ---- big-GEMM smem: 3 buffers; each = A(128x144B)+B(128x144B) ----
#define ROWB   144
#define ATILEB (128 * ROWB)          // 18432
#define BTILEB (128 * ROWB)          // 18432
#define BUFB   (ATILEB + BTILEB)     // 36864
#define NSTAGE 3
#define SMEM_BYTES (NSTAGE * BUFB)   // 110592 -> 2 CTAs/SM
// ---- pro smem: 4 buffers; each = A(64x144B)+B(128x144B) ----
#define PATILEB (64 * ROWB)          // 9216
#define PBUFB   (PATILEB + BTILEB)   // 27648

#define LDM_SETUP \
    const int lrow = lane & 7, lsel = lane >> 3; \
    const int a_dm = (lsel & 1) << 3, a_dk = (lsel >> 1) << 3; \
    const int b_dn = (lsel >> 1) << 3, b_dk = (lsel & 1) << 3;

// ==================================================================
// Single-bf16 GEMM; MT=128; K-chunk 64; 3-stage loop.
// OUTB: 0 = fp32 out, 1 = bf16 out, 2 = bf16 hi + residual lo out
// ==================================================================
template<int ACT, bool TWO, int OUTB>
__global__ void __launch_bounds__(256, 2) gemm_mma(
    const __nv_bfloat16* __restrict__ Ahi,
    const __nv_bfloat16* __restrict__ Bhi,
    const __nv_bfloat16* __restrict__ A2hi,
    const __nv_bfloat16* __restrict__ B2hi,
    float* __restrict__ Cf, __nv_bfloat16* __restrict__ Chi, __nv_bfloat16* __restrict__ Clo,
    const float* __restrict__ bias,
    int M, int K, long long sA, long long sB, long long sC, int ldc)
{
    constexpr int FM = 4;
    extern __shared__ char sm[];
    const uint32_t smb = smem_u32(sm);
    const int tid = threadIdx.x, wid = tid >> 5, lane = tid & 31;
    const int wm = wid >> 2, wn = wid & 3;
    const int m0 = blockIdx.y * 128, n0 = blockIdx.x * 128, z = blockIdx.z;

    const int kc  = K >> 6;
    const int nch = TWO ? 2 * kc : kc;

    float d[FM][4][4];
    #pragma unroll
    for (int f = 0; f < FM; f++)
        #pragma unroll
        for (int g = 0; g < 4; g++)
            #pragma unroll
            for (int e = 0; e < 4; e++) d[f][g][e] = 0.f;

    auto load_chunk = [&](int c) {
        const bool sec = TWO && (c >= kc);
        const int koff = (sec ? c - kc : c) << 6;
        const int buf = c % NSTAGE;
        const uint32_t smA = smb + buf * BUFB;
        const uint32_t smB = smA + ATILEB;
        {
            const __nv_bfloat16* pH = (sec ? A2hi : Ahi) + (long long)z * sA;
            #pragma unroll
            for (int i = 0; i < 4; i++) {
                const int idx = tid + 256 * i;
                const int r = idx >> 3, s = idx & 7;
                cp16(smA + r * ROWB + s * 16,
                     pH + (long long)(m0 + r) * K + koff + s * 8);
            }
        }
        {
            const __nv_bfloat16* pH = (sec ? B2hi : Bhi) + (long long)z * sB;
            #pragma unroll
            for (int i = 0; i < 4; i++) {
                const int idx = tid + 256 * i;
                const int r = idx >> 3, s = idx & 7;
                cp16(smB + r * ROWB + s * 16,
                     pH + (long long)(n0 + r) * K + koff + s * 8);
            }
        }
        asm volatile("cp.async.commit_group;");
    };

    LDM_SETUP

    auto compute_chunk = [&](int c) {
        const uint32_t a_base = smb + (c % NSTAGE) * BUFB;
        const uint32_t b_base = a_base + ATILEB;
        #pragma unroll
        for (int st = 0; st < 4; ++st) {
            const int k = st * 16;
            uint32_t a[FM][4], b[4][2];
            #pragma unroll
            for (int f = 0; f < FM; f++) {
                const uint32_t addr = a_base
                    + (uint32_t)((wm * 64 + f * 16 + a_dm + lrow) * ROWB + (k + a_dk) * 2);
                ldm_x4(a[f][0], a[f][1], a[f][2], a[f][3], addr);
            }
            #pragma unroll
            for (int gp = 0; gp < 2; gp++) {
                const uint32_t addr = b_base
                    + (uint32_t)((wn * 32 + gp * 16 + b_dn + lrow) * ROWB + (k + b_dk) * 2);
                ldm_x4(b[2*gp][0], b[2*gp][1], b[2*gp+1][0], b[2*gp+1][1], addr);
            }
            #pragma unroll
            for (int f = 0; f < FM; f++)
                #pragma unroll
                for (int g = 0; g < 4; g++)
                    mma_bf16(d[f][g], a[f], b[g]);
        }
    };

    load_chunk(0);
    if (nch > 1) load_chunk(1);
    for (int c = 0; c < nch; ++c) {
        if (c + 1 < nch) asm volatile("cp.async.wait_group 1;");
        else             asm volatile("cp.async.wait_group 0;");
        __syncthreads();
        if (c + 2 < nch) load_chunk(c + 2);
        compute_chunk(c);
    }

    const int qr = lane >> 2, qc = 2 * (lane & 3);
    #pragma unroll
    for (int f = 0; f < FM; f++) {
        #pragma unroll
        for (int g = 0; g < 4; g++) {
            const int cc = n0 + wn * 32 + g * 8 + qc;
            float bx = 0.f, by = 0.f;
            if (bias) { bx = bias[cc]; by = bias[cc + 1]; }
            #pragma unroll
            for (int h = 0; h < 2; h++) {
                const int row = m0 + wm * 64 + f * 16 + qr + h * 8;
                if (row >= M) continue;
                float v0 = d[f][g][2 * h]     + bx;
                float v1 = d[f][g][2 * h + 1] + by;
                if (ACT == 1) { v0 = eluf(v0); v1 = eluf(v1); }
                else if (ACT == 2) { v0 = tanhf(v0); v1 = tanhf(v1); }
                const long long o = (long long)z * sC + (long long)row * ldc + cc;
                if constexpr (OUTB == 0) {
                    *reinterpret_cast<float2*>(Cf + o) = make_float2(v0, v1);
                } else if constexpr (OUTB == 1) {
                    *reinterpret_cast<__nv_bfloat162*>(Chi + o) = __floats2bfloat162_rn(v0, v1);
                } else {
                    __nv_bfloat162 hb = __floats2bfloat162_rn(v0, v1);
                    float2 hf = __bfloat1622float2(hb);
                    __nv_bfloat162 lb = __floats2bfloat162_rn(v0 - hf.x, v1 - hf.y);
                    *reinterpret_cast<__nv_bfloat162*>(Chi + o) = hb;
                    *reinterpret_cast<__nv_bfloat162*>(Clo + o) = lb;
                }
            }
        }
    }
}

// ==================================================================
// Prologue uber-GEMM (fp32 A with gather -> bf16), MT=64, pair-loop.
// tk CTAs also emit the transposed tile via smem staging.
// Grid 448 CTAs: [0,32) dh, [32,64) headq, [64,320) tk, [320,448) hist
// ==================================================================
#define STG_LD 136
__global__ void __launch_bounds__(256, 2) gemm_pro(
    const float* __restrict__ dec_out, const float* __restrict__ emb,
    const int* __restrict__ head, const int* __restrict__ tail,
    const __nv_bfloat16* __restrict__ wT_hi,
    float* __restrict__ dh, float* __restrict__ headq,
    __nv_bfloat16* __restrict__ tk_hi, __nv_bfloat16* __restrict__ tkT_hi,
    const float* __restrict__ b_tk,
    const float* __restrict__ hist, float* __restrict__ hh)
{
    constexpr int FM = 2;
    extern __shared__ char sm[];
    const uint32_t smb = smem_u32(sm);
    const int tid = threadIdx.x, wid = tid >> 5, lane = tid & 31;
    const int wm = wid >> 2, wn = wid & 3;

    const int bid = blockIdx.x;

    if (bid >= 320) {
        // ---- hist path: hh[8][1024] = hist @ [Wh | Whq1], hist staged in smem ----
        float* shist = reinterpret_cast<float*>(sm);         // 8 x 512 fp32 = 16 KB
        #pragma unroll
        for (int i = tid; i < 1024; i += 256)
            reinterpret_cast<float4*>(shist)[i] = reinterpret_cast<const float4*>(hist)[i];
        __syncthreads();
        const int c = (bid - 320) * 8 + wid;                 // 0..1023
        const __nv_bfloat16* rh = (c < 512)
            ? wT_hi + 7LL * 512 * 512 + (long long)c * 512
            : wT_hi + 8LL * 512 * 512 + (long long)(c - 512) * 512;
        float acc[8] = {0.f,0.f,0.f,0.f,0.f,0.f,0.f,0.f};
        #pragma unroll 4
        for (int i = 0; i < 16; i++) {
            const int k = lane + i * 32;
            const float w = __bfloat162float(rh[k]);
            #pragma unroll
            for (int r = 0; r < 8; r++) acc[r] = fmaf(shist[r * 512 + k], w, acc[r]);
        }
        #pragma unroll
        for (int r = 0; r < 8; r++) {
            float v = acc[r];
            #pragma unroll
            for (int o = 16; o; o >>= 1) v += __shfl_xor_sync(0xffffffffu, v, o);
            if (lane == 0) hh[r * 1024 + c] = v;
        }
        return;
    }

    const float* Af; const int* gidx; long long boff; float* Cf; int ldc;
    int m0, n0; int outb, act; const float* bias;
    if (bid < 32) {
        Af = dec_out; gidx = nullptr; boff = 0;
        Cf = dh; ldc = 1024; outb = 0; act = 0; bias = nullptr;
        n0 = (bid & 7) * 128; m0 = (bid >> 3) * 64;
    } else if (bid < 64) {
        const int t = bid - 32;
        Af = emb; gidx = head; boff = 2LL * 512 * 512;
        Cf = headq; ldc = 512; outb = 0; act = 0; bias = nullptr;
        n0 = (t & 3) * 128; m0 = (t >> 2) * 64;
    } else {
        const int t = bid - 64;
        Af = emb; gidx = tail; boff = 3LL * 512 * 512;
        Cf = nullptr; ldc = 512; outb = 1; act = 1; bias = b_tk;
        n0 = (t & 3) * 128; m0 = (t >> 2) * 64;
    }
    const __nv_bfloat16* Bhi = wT_hi + boff;
    const int K = 512, np = 4;

    float d[FM][4][4];
    #pragma unroll
    for (int f = 0; f < FM; f++)
        #pragma unroll
        for (int g = 0; g < 4; g++)
            #pragma unroll
            for (int e = 0; e < 4; e++) d[f][g][e] = 0.f;

    auto load_chunk = [&](int c) {
        const int koff = c << 6;
        const int buf = c & 3;
        const uint32_t smA = smb + buf * PBUFB;
        const uint32_t smB = smA + PATILEB;
        char* smAp = sm + buf * PBUFB;
        #pragma unroll
        for (int i = 0; i < 4; i++) {
            const int idx = tid + 256 * i;
            const int r = idx >> 4, s = idx & 15;
            const int gm = m0 + r;
            const long long row = gidx ? (long long)gidx[gm] : (long long)gm;
            float4 v = *reinterpret_cast<const float4*>(Af + row * K + koff + s * 4);
            uint2 uh;
            __nv_bfloat162 h01 = __floats2bfloat162_rn(v.x, v.y);
            __nv_bfloat162 h23 = __floats2bfloat162_rn(v.z, v.w);
            uh.x = *(uint32_t*)&h01; uh.y = *(uint32_t*)&h23;
            *reinterpret_cast<uint2*>(smAp + r * ROWB + s * 8) = uh;
        }
        #pragma unroll
        for (int i = 0; i < 4; i++) {
            const int idx = tid + 256 * i;
            const int r = idx >> 3, s = idx & 7;
            cp16(smB + r * ROWB + s * 16,
                 Bhi + (long long)(n0 + r) * K + koff + s * 8);
        }
    };
    auto load_pair = [&](int p) {
        load_chunk(2 * p);
        load_chunk(2 * p + 1);
        asm volatile("cp.async.commit_group;");
    };

    LDM_SETUP

    auto compute_chunk = [&](int c) {
        const uint32_t a_base = smb + (c & 3) * PBUFB;
        const uint32_t b_base = a_base + PATILEB;
        #pragma unroll
        for (int st = 0; st < 4; ++st) {
            const int k = st * 16;
            uint32_t a[FM][4], b[4][2];
            #pragma unroll
            for (int f = 0; f < FM; f++) {
                const uint32_t addr = a_base
                    + (uint32_t)((wm * 32 + f * 16 + a_dm + lrow) * ROWB + (k + a_dk) * 2);
                ldm_x4(a[f][0], a[f][1], a[f][2], a[f][3], addr);
            }
            #pragma unroll
            for (int gp = 0; gp < 2; gp++) {
                const uint32_t addr = b_base
                    + (uint32_t)((wn * 32 + gp * 16 + b_dn + lrow) * ROWB + (k + b_dk) * 2);
                ldm_x4(b[2*gp][0], b[2*gp][1], b[2*gp+1][0], b[2*gp+1][1], addr);
            }
            #pragma unroll
            for (int f = 0; f < FM; f++)
                #pragma unroll
                for (int g = 0; g < 4; g++)
                    mma_bf16(d[f][g], a[f], b[g]);
        }
    };

    load_pair(0);
    for (int p = 0; p < np; ++p) {
        asm volatile("cp.async.wait_group 0;");
        __syncthreads();
        if (p + 1 < np) load_pair(p + 1);
        compute_chunk(2 * p);
        compute_chunk(2 * p + 1);
    }

    __nv_bfloat16* stg = reinterpret_cast<__nv_bfloat16*>(sm);

    const int qr = lane >> 2, qc = 2 * (lane & 3);
    #pragma unroll
    for (int f = 0; f < FM; f++) {
        #pragma unroll
        for (int g = 0; g < 4; g++) {
            const int cc = n0 + wn * 32 + g * 8 + qc;
            float bx = 0.f, by = 0.f;
            if (bias) { bx = bias[cc]; by = bias[cc + 1]; }
            #pragma unroll
            for (int h = 0; h < 2; h++) {
                const int row = m0 + wm * 32 + f * 16 + qr + h * 8;
                float v0 = d[f][g][2 * h]     + bx;
                float v1 = d[f][g][2 * h + 1] + by;
                if (act == 1) { v0 = eluf(v0); v1 = eluf(v1); }
                if (!outb) {
                    *reinterpret_cast<float2*>(Cf + (long long)row * ldc + cc) = make_float2(v0, v1);
                } else {
                    const __nv_bfloat162 hb = __floats2bfloat162_rn(v0, v1);
                    *reinterpret_cast<__nv_bfloat162*>(tk_hi + (long long)row * 512 + cc) = hb;
                    const int lr = row - m0, lc = cc - n0;
                    stg[lr * STG_LD + lc]     = __low2bfloat16(hb);
                    stg[lr * STG_LD + lc + 1] = __high2bfloat16(hb);
                }
            }
        }
    }

    if (outb) {
        __syncthreads();
        for (int n = wid; n < 128; n += 8) {
            __nv_bfloat162 pr;
            pr.x = stg[(2 * lane)     * STG_LD + n];
            pr.y = stg[(2 * lane + 1) * STG_LD + n];
            *reinterpret_cast<__nv_bfloat162*>(
                tkT_hi + (long long)(n0 + n) * 512 + m0 + 2 * lane) = pr;
        }
    }
}

// ---------------- weights: transpose 512x512 fp32 -> bf16 ----------------
struct WPtrs { const float* s[9]; };
__global__ void prep_weights(WPtrs wp, __nv_bfloat16* __restrict__ dhi)
{
    __shared__ float t[32][33];
    const int mtx = blockIdx.z;
    const float* src = wp.s[mtx];
    __nv_bfloat16* oh = dhi + (long long)mtx * 512 * 512;
    const int tx = threadIdx.x, ty = threadIdx.y;
    const int bx = blockIdx.x * 32, by = blockIdx.y * 32;
    #pragma unroll
    for (int i = 0; i < 32; i += 8)
        t[ty + i][tx] = src[(long long)(by + ty + i) * 512 + bx + tx];
    __syncthreads();
    #pragma unroll
    for (int i = 0; i < 32; i += 8)
        oh[(long long)(bx + ty + i) * 512 + by + tx] = __float2bfloat16(t[tx][ty + i]);
}

// ---------------- mask dtype detector (parallel) ----------------
__global__ void detect_mask_kernel(const unsigned int* __restrict__ adj, int nwords)
{
    unsigned int local = 0u;
    for (int i = blockIdx.x * blockDim.x + threadIdx.x; i < nwords;
         i += gridDim.x * blockDim.x)
        local |= (adj[i] > 1u) ? 1u : 0u;
    #pragma unroll
    for (int o = 16; o; o >>= 1) local |= __shfl_xor_sync(0xffffffffu, local, o);
    if ((threadIdx.x & 31) == 0 && local) atomicOr(&g_mask_byte_mode, 1u);
}

// ---------------- masks -> bitmasks (both dtype modes) ----------------
__global__ void mask_bits(const void* __restrict__ adj, const void* __restrict__ dup,
                          uint32_t* __restrict__ abits, uint32_t* __restrict__ dbits)
{
    const int row = blockIdx.x;
    const int tid = threadIdx.x;
    const unsigned byte_mode = g_mask_byte_mode;
    int v;
    if (row < 512) {
        const long long off = (long long)row * 512 + tid;
        v = byte_mode ? (((const unsigned char*)adj)[off] != 0)
                      : (((const int*)adj)[off] != 0);
    } else {
        const long long off = (long long)(row - 512) * 512 + tid;
        v = byte_mode ? (((const unsigned char*)dup)[off] != 0)
                      : (((const int*)dup)[off] != 0);
    }
    const unsigned m = __ballot_sync(0xffffffffu, v);
    if ((tid & 31) == 0) {
        if (row < 512) abits[row * 16 + (tid >> 5)] = m;
        else           dbits[(row - 512) * 16 + (tid >> 5)] = m;
    }
}

// ---------------- tq = elu(decp + histp + headq + b_tq) -> bf16 ----------------
__global__ void build_tq(const float4* __restrict__ dh, const float4* __restrict__ hh,
                         const float4* __restrict__ headq, const float4* __restrict__ btq,
                         __nv_bfloat162* __restrict__ thi)
{
    const int i = blockIdx.x * 256 + threadIdx.x;
    const int d  = i & 127;
    const int h  = (i >> 7) & 63;
    const int bs = i >> 13;
    const int b  = bs >> 5;
    float4 a = dh[bs * 256 + d];
    float4 c = hh[b * 256 + d];
    float4 e = headq[(b * 64 + h) * 128 + d];
    float4 g = btq[d];
    float4 r;
    r.x = eluf(a.x + c.x + e.x + g.x);
    r.y = eluf(a.y + c.y + e.y + g.y);
    r.z = eluf(a.z + c.z + e.z + g.z);
    r.w = eluf(a.w + c.w + e.w + g.w);
    thi[2 * i]     = __floats2bfloat162_rn(r.x, r.y);
    thi[2 * i + 1] = __floats2bfloat162_rn(r.z, r.w);
}

// ---------------- hq = elu(hqd + hqh + b_hq) (cols 512:1024) ----------------
__global__ void build_hq(const float4* __restrict__ dh, const float4* __restrict__ hh,
                         const float4* __restrict__ bhq, float4* __restrict__ hq)
{
    const int i = blockIdx.x * 256 + threadIdx.x;
    const int d  = i & 127;
    const int bs = i >> 7;
    const int b  = bs >> 5;
    float4 a = dh[bs * 256 + 128 + d];
    float4 c = hh[b * 256 + 128 + d];
    float4 g = bhq[d];
    float4 r;
    r.x = eluf(a.x + c.x + g.x);
    r.y = eluf(a.y + c.y + g.y);
    r.z = eluf(a.z + c.z + g.z);
    r.w = eluf(a.w + c.w + g.w);
    hq[i] = r;
}

// ---------------- masked softmax (bitmasks, fully vectorized bf16x2) ----------------
__global__ void masked_softmax(const __nv_bfloat16* __restrict__ schi,
                               const __nv_bfloat16* __restrict__ sclo,
                               __nv_bfloat16* __restrict__ ahi, __nv_bfloat16* __restrict__ alo,
                               const uint32_t* __restrict__ abits,
                               const uint32_t* __restrict__ dbits)
{
    const int q = blockIdx.x;
    const int b = blockIdx.y;
    const int s = q >> 6, h = q & 63;
    const long long ro2 = ((long long)(b * 2048 + q)) * 256;
    const uint32_t* aw = abits + (b * 64 + h) * 16;
    const uint32_t* dw = dbits + (b * 32 + s) * 16;

    const int tid = threadIdx.x;
    const uint32_t w = aw[tid >> 4] & ~dw[tid >> 4];
    const int bp = 2 * (tid & 15);
    const int mk0 = (w >> bp) & 1, mk1 = (w >> (bp + 1)) & 1;

    const float2 sh = __bfloat1622float2(
        reinterpret_cast<const __nv_bfloat162*>(schi)[ro2 + tid]);
    const float2 sl = __bfloat1622float2(
        reinterpret_cast<const __nv_bfloat162*>(sclo)[ro2 + tid]);
    const float v0 = sh.x + sl.x, v1 = sh.y + sl.y;

    float lmax = -FLT_MAX;
    if (mk0) lmax = v0;
    if (mk1) lmax = fmaxf(lmax, v1);

    __shared__ float smax[8], ssum[8];
    #pragma unroll
    for (int o = 16; o; o >>= 1) lmax = fmaxf(lmax, __shfl_xor_sync(0xffffffffu, lmax, o));
    if ((tid & 31) == 0) smax[tid >> 5] = lmax;
    __syncthreads();
    float bmax = -FLT_MAX;
    #pragma unroll
    for (int ww = 0; ww < 8; ww++) bmax = fmaxf(bmax, smax[ww]);

    const float e0 = mk0 ? expf(v0 - bmax) : 0.f;
    const float e1 = mk1 ? expf(v1 - bmax) : 0.f;
    float lsum = e0 + e1;
    #pragma unroll
    for (int o = 16; o; o >>= 1) lsum += __shfl_xor_sync(0xffffffffu, lsum, o);
    if ((tid & 31) == 0) ssum[tid >> 5] = lsum;
    __syncthreads();
    float bsum = 0.f;
    #pragma unroll
    for (int ww = 0; ww < 8; ww++) bsum += ssum[ww];

    const float inv = 1.f / bsum;
    const float p0 = e0 * inv, p1 = e1 * inv;
    const __nv_bfloat162 hb = __floats2bfloat162_rn(p0, p1);
    const float2 hf = __bfloat1622float2(hb);
    const __nv_bfloat162 lb = __floats2bfloat162_rn(p0 - hf.x, p1 - hf.y);
    reinterpret_cast<__nv_bfloat162*>(ahi)[ro2 + tid] = hb;
    reinterpret_cast<__nv_bfloat162*>(alo)[ro2 + tid] = lb;
}

// ---------------- final: head attention + prob + log (vectorized bf16x2) ----------------
__global__ void final_kernel(const float* __restrict__ hq,
                             const __nv_bfloat16* __restrict__ hk,
                             const __nv_bfloat16* __restrict__ athi,
                             const __nv_bfloat16* __restrict__ atlo,
                             const int* __restrict__ head, float* __restrict__ out)
{
    const int n = blockIdx.x;
    const int b = n >> 5;
    const int tid = threadIdx.x;

    __shared__ float shq[512];
    __shared__ float sc[64];
    __shared__ float sw[64];
    __shared__ int   s_len;

    if (tid == 0) s_len = 0;
    shq[tid]       = hq[(long long)n * 512 + tid];
    shq[tid + 256] = hq[(long long)n * 512 + 256 + tid];
    __syncthreads();
    if (tid < 64) { if (head[b * 64 + tid] != 0) atomicAdd(&s_len, 1); }
    __syncthreads();

    const int w = tid >> 5, lane = tid & 31;
    for (int k = w; k < 64; k += 8) {
        const __nv_bfloat162* hkr = reinterpret_cast<const __nv_bfloat162*>(
            hk + ((long long)n * 64 + k) * 512);
        float sacc = 0.f;
        #pragma unroll 4
        for (int dd = lane; dd < 256; dd += 32) {
            const float2 hv = __bfloat1622float2(hkr[dd]);
            sacc = fmaf(shq[2 * dd], hv.x, sacc);
            sacc = fmaf(shq[2 * dd + 1], hv.y, sacc);
        }
        #pragma unroll
        for (int o = 16; o; o >>= 1) sacc += __shfl_xor_sync(0xffffffffu, sacc, o);
        if (lane == 0) sc[k] = sacc;
    }
    __syncthreads();

    if (tid == 0) {
        const int len = s_len;
        float mx = -FLT_MAX;
        for (int k = 0; k < len; k++) mx = fmaxf(mx, sc[k]);
        float sum = 0.f;
        for (int k = 0; k < 64; k++) {
            float e = (k < len) ? expf(sc[k] - mx) : 0.f;
            sw[k] = e; sum += e;
        }
        float inv = 1.f / sum;
        for (int k = 0; k < 64; k++) sw[k] *= inv;
    }
    __syncthreads();

    const long long base2 = (long long)n * 64 * 256;
    const int t2 = tid;
    const __nv_bfloat162* ph = reinterpret_cast<const __nv_bfloat162*>(athi) + base2 + t2;
    const __nv_bfloat162* pl = reinterpret_cast<const __nv_bfloat162*>(atlo) + base2 + t2;
    float p0 = 0.f, p1 = 0.f;
    #pragma unroll 8
    for (int k = 0; k < 64; k++) {
        const float2 ah = __bfloat1622float2(ph[k * 256]);
        const float2 al = __bfloat1622float2(pl[k * 256]);
        p0 = fmaf(sw[k], ah.x + al.x, p0);
        p1 = fmaf(sw[k], ah.y + al.y, p1);
    }
    float2 res;
    res.x = logf(p0 + 1e-20f);
    res.y = logf(p1 + 1e-20f);
    *reinterpret_cast<float2*>(out + (long long)n * 512 + 2 * t2) = res;
}

// ---------------- launch ----------------
extern "C" void kernel_launch(void* const* d_in, const int* in_sizes, int n_in,
                              void* d_out, int out_size)
{
    const float* dec_out = (const float*)d_in[0];
    const float* history = (const float*)d_in[1];
    const int*   head    = (const int*)  d_in[2];
    const int*   tail    = (const int*)  d_in[3];
    const void*  adj     = d_in[4];
    const void*  dup     = d_in[5];
    const float* emb     = (const float*)d_in[6];
    const float* W_tq    = (const float*)d_in[7];
    const float* b_tq    = (const float*)d_in[8];
    const float* W_tk    = (const float*)d_in[9];
    const float* b_tk    = (const float*)d_in[10];
    const float* W_tout  = (const float*)d_in[11];
    const float* W_hq    = (const float*)d_in[12];
    const float* b_hq    = (const float*)d_in[13];
    const float* W_hk    = (const float*)d_in[14];
    const float* b_hk    = (const float*)d_in[15];

    float *dh, *hh, *headq, *hkbuf, *hq;
    __nv_bfloat16 *tq_hi, *tk_hi, *tkT_hi, *at_hi, *at_lo, *ctx_hi, *gh_hi, *wT_hi;
    uint32_t *abits, *dbits;
    unsigned int* modep;
    cudaGetSymbolAddress((void**)&dh,     g_dh);
    cudaGetSymbolAddress((void**)&hh,     g_hh);
    cudaGetSymbolAddress((void**)&headq,  g_headq);
    cudaGetSymbolAddress((void**)&hkbuf,  g_hk);
    cudaGetSymbolAddress((void**)&hq,     g_hq);
    cudaGetSymbolAddress((void**)&tq_hi,  g_tq_hi);
    cudaGetSymbolAddress((void**)&tk_hi,  g_tk_hi);
    cudaGetSymbolAddress((void**)&tkT_hi, g_tkT_hi);
    cudaGetSymbolAddress((void**)&at_hi,  g_at_hi);
    cudaGetSymbolAddress((void**)&at_lo,  g_at_lo);
    cudaGetSymbolAddress((void**)&ctx_hi, g_ctx_hi);
    cudaGetSymbolAddress((void**)&gh_hi,  g_gh_hi);
    cudaGetSymbolAddress((void**)&wT_hi,  g_wT_hi);
    cudaGetSymbolAddress((void**)&abits,  g_adj_bits);
    cudaGetSymbolAddress((void**)&dbits,  g_dup_bits);
    cudaGetSymbolAddress((void**)&modep,  g_mask_byte_mode);

    __nv_bfloat16* sc_hi = gh_hi;
    __nv_bfloat16* sc_lo = (__nv_bfloat16*)hkbuf;
    __nv_bfloat16* hkb   = (__nv_bfloat16*)hkbuf;

    cudaFuncSetAttribute(gemm_pro,            cudaFuncAttributeMaxDynamicSharedMemorySize, SMEM_BYTES);
    cudaFuncSetAttribute(gemm_mma<0,false,2>, cudaFuncAttributeMaxDynamicSharedMemorySize, SMEM_BYTES);
    cudaFuncSetAttribute(gemm_mma<0,false,1>, cudaFuncAttributeMaxDynamicSharedMemorySize, SMEM_BYTES);
    cudaFuncSetAttribute(gemm_mma<2,true ,1>, cudaFuncAttributeMaxDynamicSharedMemorySize, SMEM_BYTES);
    cudaFuncSetAttribute(gemm_mma<1,false,1>, cudaFuncAttributeMaxDynamicSharedMemorySize, SMEM_BYTES);

    // weight slots: 0 Wd, 1 Whq0 (merged N=1024), 2 We, 3 Wtk, 4 Wtout0, 5 Wtout1,
    //               6 Whk, 7 Wh, 8 Whq1
    WPtrs wp;
    wp.s[0] = W_tq;               wp.s[1] = W_hq;               wp.s[2] = W_tq + 1024LL*512;
    wp.s[3] = W_tk;               wp.s[4] = W_tout;             wp.s[5] = W_tout + 512LL*512;
    wp.s[6] = W_hk;               wp.s[7] = W_tq + 512LL*512;   wp.s[8] = W_hq + 512LL*512;
    #define WTH(i) (wT_hi + (long long)(i)*512*512)

    cudaMemsetAsync(modep, 0, sizeof(unsigned int));
    detect_mask_kernel<<<128, 256>>>((const unsigned int*)adj, 65536);
    mask_bits<<<768, 512>>>(adj, dup, abits, dbits);
    prep_weights<<<dim3(16,16,9), dim3(32,8)>>>(wp, wT_hi);

    gemm_pro<<<448, 256, SMEM_BYTES>>>(dec_out, emb, head, tail, wT_hi,
                                       dh, headq, tk_hi, tkT_hi, b_tk,
                                       history, hh);
    build_tq<<<8192, 256>>>((const float4*)dh, (const float4*)hh,
                            (const float4*)headq, (const float4*)b_tq,
                            (__nv_bfloat162*)tq_hi);
    // scores[b] = tq[b] @ tk[b]^T -> bf16 hi/lo
    gemm_mma<0,false,2><<<dim3(4,16,8), 256, SMEM_BYTES>>>(
        tq_hi, tk_hi, nullptr, nullptr,
        nullptr, sc_hi, sc_lo, nullptr, 2048, 512,
        2048LL*512, 512LL*512, 2048LL*512, 512);
    masked_softmax<<<dim3(2048,8), 256>>>(sc_hi, sc_lo, at_hi, at_lo, abits, dbits);
    // ctx[b] = attn[b] @ tk[b] -> bf16
    gemm_mma<0,false,1><<<dim3(4,16,8), 256, SMEM_BYTES>>>(
        at_hi, tkT_hi, nullptr, nullptr,
        nullptr, ctx_hi, nullptr, nullptr, 2048, 512,
        2048LL*512, 512LL*512, 2048LL*512, 512);
    // ghid = tanh(ctx @ Wtout0 + tq @ Wtout1) -> bf16 (overwrites sc_hi)
    gemm_mma<2,true,1><<<dim3(4,128,1), 256, SMEM_BYTES>>>(
        ctx_hi, WTH(4), tq_hi, WTH(5),
        nullptr, gh_hi, nullptr, nullptr, 16384, 512, 0, 0, 0, 512);
    // hk = elu(ghid @ Whk + b_hk) -> bf16 (overwrites sc_lo space)
    gemm_mma<1,false,1><<<dim3(4,128,1), 256, SMEM_BYTES>>>(
        gh_hi, WTH(6), nullptr, nullptr,
        nullptr, hkb, nullptr, b_hk, 16384, 512, 0, 0, 0, 512);
    build_hq<<<128, 256>>>((const float4*)dh, (const float4*)hh,
                           (const float4*)b_hq, (float4*)hq);
    final_kernel<<<256, 256>>>(hq, hkb, at_hi, at_lo, head, (float*)d_out);
}